// round 1
// baseline (speedup 1.0000x reference)
#include <cuda_runtime.h>
#include <math.h>

#define D_MODEL 256
#define BATCH   4
#define SEQ     2048
#define HEADS   8
#define DEPTH   32
#define DFF     1024
#define TOK     (BATCH*SEQ)   // 8192
#define EPS     1e-6f

// ---------------- scratch (static device allocations only) ----------------
__device__ float g_q   [TOK*D_MODEL];
__device__ float g_k   [TOK*D_MODEL];
__device__ float g_v   [TOK*D_MODEL];
__device__ float g_att [TOK*D_MODEL];
__device__ float g_tmp [TOK*D_MODEL];
__device__ float g_out1[TOK*D_MODEL];
__device__ float g_ffh [TOK*DFF];

// ---------------- tiled SGEMM: C = A[M,K] @ B[K,N] + bias (+relu) ----------
// BM=BN=64, BK=16, 256 threads, 4x4 microtile per thread. All dims divide.
__global__ __launch_bounds__(256) void sgemm_bias(
    const float* __restrict__ A, const float* __restrict__ B,
    const float* __restrict__ bias, float* __restrict__ C,
    int M, int N, int K, int relu)
{
    __shared__ __align__(16) float As[16][64];
    __shared__ __align__(16) float Bs[16][64];
    int tid  = threadIdx.x;
    int row0 = blockIdx.y * 64;
    int col0 = blockIdx.x * 64;
    int tr = tid >> 4;          // 0..15 -> rows tr*4..+3
    int tc = tid & 15;          // 0..15 -> cols tc*4..+3
    int ar = tid >> 2;          // A-load row 0..63
    int av = (tid & 3) << 2;    // A-load col 0,4,8,12
    int br = tid >> 4;          // B-load row 0..15
    int bc = (tid & 15) << 2;   // B-load col 0..60

    float acc[4][4] = {};

    for (int k0 = 0; k0 < K; k0 += 16) {
        float4 a = *(const float4*)&A[(size_t)(row0 + ar) * K + k0 + av];
        As[av+0][ar] = a.x; As[av+1][ar] = a.y;
        As[av+2][ar] = a.z; As[av+3][ar] = a.w;
        *(float4*)&Bs[br][bc] = *(const float4*)&B[(size_t)(k0 + br) * N + col0 + bc];
        __syncthreads();
        #pragma unroll
        for (int kk = 0; kk < 16; kk++) {
            float4 af = *(float4*)&As[kk][tr << 2];
            float4 bf = *(float4*)&Bs[kk][tc << 2];
            float a4[4] = {af.x, af.y, af.z, af.w};
            float b4[4] = {bf.x, bf.y, bf.z, bf.w};
            #pragma unroll
            for (int m = 0; m < 4; m++)
                #pragma unroll
                for (int n = 0; n < 4; n++)
                    acc[m][n] = fmaf(a4[m], b4[n], acc[m][n]);
        }
        __syncthreads();
    }

    float4 bb = *(const float4*)&bias[col0 + (tc << 2)];
    #pragma unroll
    for (int m = 0; m < 4; m++) {
        int r = row0 + (tr << 2) + m;
        float4 c;
        c.x = acc[m][0] + bb.x;
        c.y = acc[m][1] + bb.y;
        c.z = acc[m][2] + bb.z;
        c.w = acc[m][3] + bb.w;
        if (relu) {
            c.x = fmaxf(c.x, 0.f); c.y = fmaxf(c.y, 0.f);
            c.z = fmaxf(c.z, 0.f); c.w = fmaxf(c.w, 0.f);
        }
        *(float4*)&C[(size_t)r * N + col0 + (tc << 2)] = c;
    }
}

// ---------------- RBF attention, streaming (no SxS materialization) --------
// attn = softmax_j( exp(-0.5*||q_i - k_j||^2) ), out_i = attn @ V.
// Arguments of the outer softmax are in (0,1] -> no max subtraction needed;
// single pass with running denom is exactly equivalent to the reference.
// 1 thread = 1 query (depth=32 in registers), K/V tiles in smem (broadcast reads).
#define QB 128
#define KB 128
__global__ __launch_bounds__(QB) void attn_kernel(
    const float* __restrict__ Q, const float* __restrict__ K,
    const float* __restrict__ V, float* __restrict__ O)
{
    // pad rows to 36 floats: keeps float4 alignment (36*4=144B, mult of 16)
    // and spreads the row-wise stores across banks.
    __shared__ __align__(16) float ks[KB][36];
    __shared__ __align__(16) float vs[KB][36];
    __shared__ float k2s[KB];

    int t  = threadIdx.x;
    int bh = blockIdx.y;
    int b  = bh >> 3;
    int h  = bh & 7;
    int qi = blockIdx.x * QB + t;

    const float* qp = Q + ((size_t)(b * SEQ + qi)) * D_MODEL + h * DEPTH;
    float4 qr[8];
    float  q2 = 0.f;
    #pragma unroll
    for (int i = 0; i < 8; i++) {
        qr[i] = ((const float4*)qp)[i];
        q2 += qr[i].x*qr[i].x + qr[i].y*qr[i].y + qr[i].z*qr[i].z + qr[i].w*qr[i].w;
    }

    float4 acc[8];
    #pragma unroll
    for (int i = 0; i < 8; i++) acc[i] = make_float4(0.f, 0.f, 0.f, 0.f);
    float denom = 0.f;

    for (int kt = 0; kt < SEQ; kt += KB) {
        const float* kp = K + ((size_t)(b * SEQ + kt + t)) * D_MODEL + h * DEPTH;
        const float* vp = V + ((size_t)(b * SEQ + kt + t)) * D_MODEL + h * DEPTH;
        float k2 = 0.f;
        #pragma unroll
        for (int i = 0; i < 8; i++) {
            float4 kv = ((const float4*)kp)[i];
            *(float4*)&ks[t][i << 2] = kv;
            k2 += kv.x*kv.x + kv.y*kv.y + kv.z*kv.z + kv.w*kv.w;
            float4 vv = ((const float4*)vp)[i];
            *(float4*)&vs[t][i << 2] = vv;
        }
        k2s[t] = k2;
        __syncthreads();

        #pragma unroll 2
        for (int j = 0; j < KB; j++) {
            const float4* kr = (const float4*)&ks[j][0];
            float dot = 0.f;
            #pragma unroll
            for (int i = 0; i < 8; i++) {
                float4 kf = kr[i];
                dot = fmaf(qr[i].x, kf.x, dot);
                dot = fmaf(qr[i].y, kf.y, dot);
                dot = fmaf(qr[i].z, kf.z, dot);
                dot = fmaf(qr[i].w, kf.w, dot);
            }
            float dist = q2 + k2s[j] - 2.f * dot;
            float w = __expf(-0.5f * dist);   // in (0,1]
            float p = __expf(w);              // softmax numerator, no max needed
            denom += p;
            const float4* vr = (const float4*)&vs[j][0];
            #pragma unroll
            for (int i = 0; i < 8; i++) {
                float4 vf = vr[i];
                acc[i].x = fmaf(p, vf.x, acc[i].x);
                acc[i].y = fmaf(p, vf.y, acc[i].y);
                acc[i].z = fmaf(p, vf.z, acc[i].z);
                acc[i].w = fmaf(p, vf.w, acc[i].w);
            }
        }
        __syncthreads();
    }

    float inv = 1.f / denom;
    float* op = O + ((size_t)(b * SEQ + qi)) * D_MODEL + h * DEPTH;
    #pragma unroll
    for (int i = 0; i < 8; i++) {
        float4 c = make_float4(acc[i].x*inv, acc[i].y*inv, acc[i].z*inv, acc[i].w*inv);
        ((float4*)op)[i] = c;
    }
}

// ---------------- fused residual + LayerNorm (1 block = 1 row, D=256) ------
__global__ __launch_bounds__(256) void residual_ln(
    const float* __restrict__ X, const float* __restrict__ Y,
    const float* __restrict__ g, const float* __restrict__ b,
    float* __restrict__ out)
{
    int row = blockIdx.x;
    int t   = threadIdx.x;
    float v = X[(size_t)row * D_MODEL + t] + Y[(size_t)row * D_MODEL + t];

    __shared__ float red[8];
    float s = v;
    #pragma unroll
    for (int o = 16; o > 0; o >>= 1) s += __shfl_xor_sync(0xffffffffu, s, o);
    if ((t & 31) == 0) red[t >> 5] = s;
    __syncthreads();
    float mean = (red[0]+red[1]+red[2]+red[3]+red[4]+red[5]+red[6]+red[7]) * (1.f/D_MODEL);

    float d  = v - mean;
    float s2 = d * d;
    #pragma unroll
    for (int o = 16; o > 0; o >>= 1) s2 += __shfl_xor_sync(0xffffffffu, s2, o);
    __syncthreads();
    if ((t & 31) == 0) red[t >> 5] = s2;
    __syncthreads();
    float var = (red[0]+red[1]+red[2]+red[3]+red[4]+red[5]+red[6]+red[7]) * (1.f/D_MODEL);

    out[(size_t)row * D_MODEL + t] = d * rsqrtf(var + EPS) * g[t] + b[t];
}

// ---------------- launch -----------------------------------------------------
extern "C" void kernel_launch(void* const* d_in, const int* in_sizes, int n_in,
                              void* d_out, int out_size)
{
    const float* x      = (const float*)d_in[0];
    const float* wq_w   = (const float*)d_in[1];
    const float* wq_b   = (const float*)d_in[2];
    const float* wk_w   = (const float*)d_in[3];
    const float* wk_b   = (const float*)d_in[4];
    const float* wv_w   = (const float*)d_in[5];
    const float* wv_b   = (const float*)d_in[6];
    const float* wo_w   = (const float*)d_in[7];
    const float* wo_b   = (const float*)d_in[8];
    const float* ffn1_w = (const float*)d_in[9];
    const float* ffn1_b = (const float*)d_in[10];
    const float* ffn2_w = (const float*)d_in[11];
    const float* ffn2_b = (const float*)d_in[12];
    const float* ln1_g  = (const float*)d_in[13];
    const float* ln1_b  = (const float*)d_in[14];
    const float* ln2_g  = (const float*)d_in[15];
    const float* ln2_b  = (const float*)d_in[16];

    float *q, *k, *v, *att, *tmp, *out1, *ffh;
    cudaGetSymbolAddress((void**)&q,    g_q);
    cudaGetSymbolAddress((void**)&k,    g_k);
    cudaGetSymbolAddress((void**)&v,    g_v);
    cudaGetSymbolAddress((void**)&att,  g_att);
    cudaGetSymbolAddress((void**)&tmp,  g_tmp);
    cudaGetSymbolAddress((void**)&out1, g_out1);
    cudaGetSymbolAddress((void**)&ffh,  g_ffh);

    dim3 gProj(D_MODEL / 64, TOK / 64);   // (4, 128)
    dim3 gFfn1(DFF / 64,     TOK / 64);   // (16, 128)

    // Q/K/V projections
    sgemm_bias<<<gProj, 256>>>(x, wq_w, wq_b, q, TOK, D_MODEL, D_MODEL, 0);
    sgemm_bias<<<gProj, 256>>>(x, wk_w, wk_b, k, TOK, D_MODEL, D_MODEL, 0);
    sgemm_bias<<<gProj, 256>>>(x, wv_w, wv_b, v, TOK, D_MODEL, D_MODEL, 0);

    // RBF attention (writes concat-head layout directly)
    attn_kernel<<<dim3(SEQ / QB, BATCH * HEADS), QB>>>(q, k, v, att);

    // output projection + residual LN1
    sgemm_bias<<<gProj, 256>>>(att, wo_w, wo_b, tmp, TOK, D_MODEL, D_MODEL, 0);
    residual_ln<<<TOK, 256>>>(x, tmp, ln1_g, ln1_b, out1);

    // FFN (relu fused into first GEMM) + residual LN2
    sgemm_bias<<<gFfn1, 256>>>(out1, ffn1_w, ffn1_b, ffh, TOK, DFF, D_MODEL, 1);
    sgemm_bias<<<gProj, 256>>>(ffh, ffn2_w, ffn2_b, tmp, TOK, D_MODEL, DFF, 0);
    residual_ln<<<TOK, 256>>>(out1, tmp, ln2_g, ln2_b, (float*)d_out);
}

// round 2
// speedup vs baseline: 1.1029x; 1.1029x over previous
#include <cuda_runtime.h>
#include <math.h>

#define D_MODEL 256
#define BATCH   4
#define SEQ     2048
#define HEADS   8
#define DEPTH   32
#define DFF     1024
#define TOK     (BATCH*SEQ)   // 8192
#define EPS     1e-6f

typedef unsigned long long ull;

// ---------------- packed f32x2 helpers (sm_100+ FFMA2 path) ----------------
__device__ __forceinline__ ull fma2(ull a, ull b, ull c) {
    ull d; asm("fma.rn.f32x2 %0, %1, %2, %3;" : "=l"(d) : "l"(a), "l"(b), "l"(c));
    return d;
}
__device__ __forceinline__ ull mul2(ull a, ull b) {
    ull d; asm("mul.rn.f32x2 %0, %1, %2;" : "=l"(d) : "l"(a), "l"(b));
    return d;
}
__device__ __forceinline__ ull pack2(float lo, float hi) {
    ull d; asm("mov.b64 %0, {%1, %2};" : "=l"(d) : "f"(lo), "f"(hi));
    return d;
}
__device__ __forceinline__ float2 unpack2(ull v) {
    float lo, hi; asm("mov.b64 {%0, %1}, %2;" : "=f"(lo), "=f"(hi) : "l"(v));
    return make_float2(lo, hi);
}

// ---------------- scratch (static device allocations only) ----------------
__device__ float g_q   [TOK*D_MODEL];
__device__ float g_k   [TOK*D_MODEL];
__device__ float g_v   [TOK*D_MODEL];
__device__ float g_att [TOK*D_MODEL];
__device__ float g_tmp [TOK*D_MODEL];
__device__ float g_out1[TOK*D_MODEL];
__device__ float g_ffh [TOK*DFF];

// ---------------- tiled SGEMM with packed f32x2 accumulation ---------------
// BM=BN=64, BK=16, 256 threads, 4x4 microtile -> 4x2 f32x2 accumulators.
__global__ __launch_bounds__(256) void sgemm_bias(
    const float* __restrict__ A, const float* __restrict__ B,
    const float* __restrict__ bias, float* __restrict__ C,
    int M, int N, int K, int relu)
{
    __shared__ __align__(16) float As[16][64];
    __shared__ __align__(16) float Bs[16][64];
    int tid  = threadIdx.x;
    int row0 = blockIdx.y * 64;
    int col0 = blockIdx.x * 64;
    int tr = tid >> 4;          // 0..15 -> rows tr*4..+3
    int tc = tid & 15;          // 0..15 -> cols tc*4..+3
    int ar = tid >> 2;          // A-load row 0..63
    int av = (tid & 3) << 2;    // A-load col 0,4,8,12
    int br = tid >> 4;          // B-load row 0..15
    int bc = (tid & 15) << 2;   // B-load col 0..60

    ull acc2[4][2];
    #pragma unroll
    for (int m = 0; m < 4; m++) { acc2[m][0] = 0ull; acc2[m][1] = 0ull; }

    for (int k0 = 0; k0 < K; k0 += 16) {
        float4 a = *(const float4*)&A[(size_t)(row0 + ar) * K + k0 + av];
        As[av+0][ar] = a.x; As[av+1][ar] = a.y;
        As[av+2][ar] = a.z; As[av+3][ar] = a.w;
        *(float4*)&Bs[br][bc] = *(const float4*)&B[(size_t)(k0 + br) * N + col0 + bc];
        __syncthreads();
        #pragma unroll
        for (int kk = 0; kk < 16; kk++) {
            float4 af = *(float4*)&As[kk][tr << 2];
            ulonglong2 bp = *(ulonglong2*)&Bs[kk][tc << 2];
            ull a0 = pack2(af.x, af.x);
            ull a1 = pack2(af.y, af.y);
            ull a2 = pack2(af.z, af.z);
            ull a3 = pack2(af.w, af.w);
            acc2[0][0] = fma2(a0, bp.x, acc2[0][0]);
            acc2[0][1] = fma2(a0, bp.y, acc2[0][1]);
            acc2[1][0] = fma2(a1, bp.x, acc2[1][0]);
            acc2[1][1] = fma2(a1, bp.y, acc2[1][1]);
            acc2[2][0] = fma2(a2, bp.x, acc2[2][0]);
            acc2[2][1] = fma2(a2, bp.y, acc2[2][1]);
            acc2[3][0] = fma2(a3, bp.x, acc2[3][0]);
            acc2[3][1] = fma2(a3, bp.y, acc2[3][1]);
        }
        __syncthreads();
    }

    float4 bb = *(const float4*)&bias[col0 + (tc << 2)];
    #pragma unroll
    for (int m = 0; m < 4; m++) {
        int r = row0 + (tr << 2) + m;
        float2 lo = unpack2(acc2[m][0]);
        float2 hi = unpack2(acc2[m][1]);
        float4 c;
        c.x = lo.x + bb.x;
        c.y = lo.y + bb.y;
        c.z = hi.x + bb.z;
        c.w = hi.y + bb.w;
        if (relu) {
            c.x = fmaxf(c.x, 0.f); c.y = fmaxf(c.y, 0.f);
            c.z = fmaxf(c.z, 0.f); c.w = fmaxf(c.w, 0.f);
        }
        *(float4*)&C[(size_t)r * N + col0 + (tc << 2)] = c;
    }
}

// ---------------- RBF attention: 2 queries/thread, packed f32x2 ------------
// attn = softmax_j( exp(-0.5*||q_i - k_j||^2) ), out_i = attn @ V.
// Softmax args are in (0,1] -> single-pass streaming denom, no max needed.
// 64 threads/block, each thread owns queries (t) and (t+64); K/V tiles of 64
// rows staged in smem, every smem read amortized over 2 queries.
#define ATH 64
#define AKB 64
__global__ __launch_bounds__(ATH) void attn_kernel(
    const float* __restrict__ Q, const float* __restrict__ K,
    const float* __restrict__ V, float* __restrict__ O)
{
    __shared__ __align__(16) float ks[AKB][36];
    __shared__ __align__(16) float vs[AKB][36];
    __shared__ float k2s[AKB];   // holds -0.5*||k||^2

    int t  = threadIdx.x;
    int bh = blockIdx.y;
    int b  = bh >> 3;
    int h  = bh & 7;
    int q0 = blockIdx.x * 128 + t;
    int q1 = q0 + 64;

    const float* qptr0 = Q + ((size_t)(b * SEQ + q0)) * D_MODEL + h * DEPTH;
    const float* qptr1 = Q + ((size_t)(b * SEQ + q1)) * D_MODEL + h * DEPTH;

    ull qp0[16], qp1[16];
    float q2_0 = 0.f, q2_1 = 0.f;
    #pragma unroll
    for (int i = 0; i < 8; i++) {
        float4 f0 = ((const float4*)qptr0)[i];
        float4 f1 = ((const float4*)qptr1)[i];
        qp0[2*i]   = pack2(f0.x, f0.y);
        qp0[2*i+1] = pack2(f0.z, f0.w);
        qp1[2*i]   = pack2(f1.x, f1.y);
        qp1[2*i+1] = pack2(f1.z, f1.w);
        q2_0 += f0.x*f0.x + f0.y*f0.y + f0.z*f0.z + f0.w*f0.w;
        q2_1 += f1.x*f1.x + f1.y*f1.y + f1.z*f1.z + f1.w*f1.w;
    }
    float qh0 = -0.5f * q2_0;
    float qh1 = -0.5f * q2_1;

    ull acc0[16], acc1[16];
    #pragma unroll
    for (int i = 0; i < 16; i++) { acc0[i] = 0ull; acc1[i] = 0ull; }
    float den0 = 0.f, den1 = 0.f;

    for (int kt = 0; kt < SEQ; kt += AKB) {
        // stage one K row and one V row per thread
        const float* kp = K + ((size_t)(b * SEQ + kt + t)) * D_MODEL + h * DEPTH;
        const float* vp = V + ((size_t)(b * SEQ + kt + t)) * D_MODEL + h * DEPTH;
        float k2 = 0.f;
        #pragma unroll
        for (int i = 0; i < 8; i++) {
            float4 kv = ((const float4*)kp)[i];
            *(float4*)&ks[t][i << 2] = kv;
            k2 += kv.x*kv.x + kv.y*kv.y + kv.z*kv.z + kv.w*kv.w;
            float4 vv = ((const float4*)vp)[i];
            *(float4*)&vs[t][i << 2] = vv;
        }
        k2s[t] = -0.5f * k2;
        __syncthreads();

        for (int j = 0; j < AKB; j++) {
            const ulonglong2* kr = (const ulonglong2*)&ks[j][0];
            ull d0a = 0ull, d0b = 0ull, d1a = 0ull, d1b = 0ull;
            #pragma unroll
            for (int i = 0; i < 8; i++) {
                ulonglong2 kk2 = kr[i];
                d0a = fma2(qp0[2*i],   kk2.x, d0a);
                d0b = fma2(qp0[2*i+1], kk2.y, d0b);
                d1a = fma2(qp1[2*i],   kk2.x, d1a);
                d1b = fma2(qp1[2*i+1], kk2.y, d1b);
            }
            float2 s0a = unpack2(d0a), s0b = unpack2(d0b);
            float2 s1a = unpack2(d1a), s1b = unpack2(d1b);
            float dot0 = (s0a.x + s0a.y) + (s0b.x + s0b.y);
            float dot1 = (s1a.x + s1a.y) + (s1b.x + s1b.y);
            float k2h = k2s[j];
            // -0.5*dist = dot - 0.5*q2 - 0.5*k2
            float w0 = __expf(dot0 + (qh0 + k2h));   // in (0,1]
            float w1 = __expf(dot1 + (qh1 + k2h));
            float p0 = __expf(w0);                   // softmax numerator
            float p1 = __expf(w1);
            den0 += p0;
            den1 += p1;
            ull p0p = pack2(p0, p0);
            ull p1p = pack2(p1, p1);
            const ulonglong2* vr = (const ulonglong2*)&vs[j][0];
            #pragma unroll
            for (int i = 0; i < 8; i++) {
                ulonglong2 vv = vr[i];
                acc0[2*i]   = fma2(p0p, vv.x, acc0[2*i]);
                acc0[2*i+1] = fma2(p0p, vv.y, acc0[2*i+1]);
                acc1[2*i]   = fma2(p1p, vv.x, acc1[2*i]);
                acc1[2*i+1] = fma2(p1p, vv.y, acc1[2*i+1]);
            }
        }
        __syncthreads();
    }

    ull inv0 = pack2(1.f / den0, 1.f / den0);
    ull inv1 = pack2(1.f / den1, 1.f / den1);
    ull* op0 = (ull*)(O + ((size_t)(b * SEQ + q0)) * D_MODEL + h * DEPTH);
    ull* op1 = (ull*)(O + ((size_t)(b * SEQ + q1)) * D_MODEL + h * DEPTH);
    #pragma unroll
    for (int i = 0; i < 16; i++) {
        op0[i] = mul2(acc0[i], inv0);
        op1[i] = mul2(acc1[i], inv1);
    }
}

// ---------------- fused residual + LayerNorm (1 block = 1 row, D=256) ------
__global__ __launch_bounds__(256) void residual_ln(
    const float* __restrict__ X, const float* __restrict__ Y,
    const float* __restrict__ g, const float* __restrict__ b,
    float* __restrict__ out)
{
    int row = blockIdx.x;
    int t   = threadIdx.x;
    float v = X[(size_t)row * D_MODEL + t] + Y[(size_t)row * D_MODEL + t];

    __shared__ float red[8];
    float s = v;
    #pragma unroll
    for (int o = 16; o > 0; o >>= 1) s += __shfl_xor_sync(0xffffffffu, s, o);
    if ((t & 31) == 0) red[t >> 5] = s;
    __syncthreads();
    float mean = (red[0]+red[1]+red[2]+red[3]+red[4]+red[5]+red[6]+red[7]) * (1.f/D_MODEL);

    float d  = v - mean;
    float s2 = d * d;
    #pragma unroll
    for (int o = 16; o > 0; o >>= 1) s2 += __shfl_xor_sync(0xffffffffu, s2, o);
    __syncthreads();
    if ((t & 31) == 0) red[t >> 5] = s2;
    __syncthreads();
    float var = (red[0]+red[1]+red[2]+red[3]+red[4]+red[5]+red[6]+red[7]) * (1.f/D_MODEL);

    out[(size_t)row * D_MODEL + t] = d * rsqrtf(var + EPS) * g[t] + b[t];
}

// ---------------- launch -----------------------------------------------------
extern "C" void kernel_launch(void* const* d_in, const int* in_sizes, int n_in,
                              void* d_out, int out_size)
{
    const float* x      = (const float*)d_in[0];
    const float* wq_w   = (const float*)d_in[1];
    const float* wq_b   = (const float*)d_in[2];
    const float* wk_w   = (const float*)d_in[3];
    const float* wk_b   = (const float*)d_in[4];
    const float* wv_w   = (const float*)d_in[5];
    const float* wv_b   = (const float*)d_in[6];
    const float* wo_w   = (const float*)d_in[7];
    const float* wo_b   = (const float*)d_in[8];
    const float* ffn1_w = (const float*)d_in[9];
    const float* ffn1_b = (const float*)d_in[10];
    const float* ffn2_w = (const float*)d_in[11];
    const float* ffn2_b = (const float*)d_in[12];
    const float* ln1_g  = (const float*)d_in[13];
    const float* ln1_b  = (const float*)d_in[14];
    const float* ln2_g  = (const float*)d_in[15];
    const float* ln2_b  = (const float*)d_in[16];

    float *q, *k, *v, *att, *tmp, *out1, *ffh;
    cudaGetSymbolAddress((void**)&q,    g_q);
    cudaGetSymbolAddress((void**)&k,    g_k);
    cudaGetSymbolAddress((void**)&v,    g_v);
    cudaGetSymbolAddress((void**)&att,  g_att);
    cudaGetSymbolAddress((void**)&tmp,  g_tmp);
    cudaGetSymbolAddress((void**)&out1, g_out1);
    cudaGetSymbolAddress((void**)&ffh,  g_ffh);

    dim3 gProj(D_MODEL / 64, TOK / 64);   // (4, 128)
    dim3 gFfn1(DFF / 64,     TOK / 64);   // (16, 128)

    // Q/K/V projections
    sgemm_bias<<<gProj, 256>>>(x, wq_w, wq_b, q, TOK, D_MODEL, D_MODEL, 0);
    sgemm_bias<<<gProj, 256>>>(x, wk_w, wk_b, k, TOK, D_MODEL, D_MODEL, 0);
    sgemm_bias<<<gProj, 256>>>(x, wv_w, wv_b, v, TOK, D_MODEL, D_MODEL, 0);

    // RBF attention (writes concat-head layout directly)
    attn_kernel<<<dim3(SEQ / 128, BATCH * HEADS), ATH>>>(q, k, v, att);

    // output projection + residual LN1
    sgemm_bias<<<gProj, 256>>>(att, wo_w, wo_b, tmp, TOK, D_MODEL, D_MODEL, 0);
    residual_ln<<<TOK, 256>>>(x, tmp, ln1_g, ln1_b, out1);

    // FFN (relu fused into first GEMM) + residual LN2
    sgemm_bias<<<gFfn1, 256>>>(out1, ffn1_w, ffn1_b, ffh, TOK, DFF, D_MODEL, 1);
    sgemm_bias<<<gProj, 256>>>(ffh, ffn2_w, ffn2_b, tmp, TOK, D_MODEL, DFF, 0);
    residual_ln<<<TOK, 256>>>(out1, tmp, ln2_g, ln2_b, (float*)d_out);
}

// round 4
// speedup vs baseline: 1.1085x; 1.0052x over previous
#include <cuda_runtime.h>
#include <cuda_bf16.h>
#include <cstdint>
#include <math.h>

#define D_MODEL 256
#define BATCH   4
#define SEQ     2048
#define HEADS   8
#define DEPTH   32
#define DFF     1024
#define TOK     (BATCH*SEQ)   // 8192
#define EPS     1e-6f

typedef unsigned long long ull;

// ---------------- packed f32x2 helpers -------------------------------------
__device__ __forceinline__ ull fma2(ull a, ull b, ull c) {
    ull d; asm("fma.rn.f32x2 %0, %1, %2, %3;" : "=l"(d) : "l"(a), "l"(b), "l"(c));
    return d;
}
__device__ __forceinline__ ull add2(ull a, ull b) {
    ull d; asm("add.rn.f32x2 %0, %1, %2;" : "=l"(d) : "l"(a), "l"(b));
    return d;
}
__device__ __forceinline__ ull mul2(ull a, ull b) {
    ull d; asm("mul.rn.f32x2 %0, %1, %2;" : "=l"(d) : "l"(a), "l"(b));
    return d;
}
__device__ __forceinline__ ull pack2(float lo, float hi) {
    ull d; asm("mov.b64 %0, {%1, %2};" : "=l"(d) : "f"(lo), "f"(hi));
    return d;
}
__device__ __forceinline__ float2 unpack2(ull v) {
    float lo, hi; asm("mov.b64 {%0, %1}, %2;" : "=f"(lo), "=f"(hi) : "l"(v));
    return make_float2(lo, hi);
}

// ---------------- mma.sync helpers (sm_80+ path, works on sm_103) ----------
__device__ __forceinline__ uint32_t smem_u32(const void* p) {
    uint32_t a;
    asm("{ .reg .u64 t; cvta.to.shared.u64 t, %1; cvt.u32.u64 %0, t; }"
        : "=r"(a) : "l"(p));
    return a;
}
__device__ __forceinline__ void ldsm_x4(uint32_t* r, uint32_t addr) {
    asm volatile("ldmatrix.sync.aligned.m8n8.x4.shared.b16 {%0,%1,%2,%3}, [%4];"
        : "=r"(r[0]), "=r"(r[1]), "=r"(r[2]), "=r"(r[3]) : "r"(addr));
}
__device__ __forceinline__ void ldsm_x4t(uint32_t* r, uint32_t addr) {
    asm volatile("ldmatrix.sync.aligned.m8n8.x4.trans.shared.b16 {%0,%1,%2,%3}, [%4];"
        : "=r"(r[0]), "=r"(r[1]), "=r"(r[2]), "=r"(r[3]) : "r"(addr));
}
__device__ __forceinline__ void mma_bf16(float* d, const uint32_t* a, const uint32_t* b) {
    asm volatile("mma.sync.aligned.m16n8k16.row.col.f32.bf16.bf16.f32 "
        "{%0,%1,%2,%3}, {%4,%5,%6,%7}, {%8,%9}, {%0,%1,%2,%3};"
        : "+f"(d[0]), "+f"(d[1]), "+f"(d[2]), "+f"(d[3])
        : "r"(a[0]), "r"(a[1]), "r"(a[2]), "r"(a[3]), "r"(b[0]), "r"(b[1]));
}
__device__ __forceinline__ uint32_t pkbf(__nv_bfloat16 a, __nv_bfloat16 b) {
    return (uint32_t)__bfloat16_as_ushort(a) | ((uint32_t)__bfloat16_as_ushort(b) << 16);
}

// ---------------- scratch ---------------------------------------------------
__device__ float g_q   [TOK*D_MODEL];
__device__ float g_k   [TOK*D_MODEL];
__device__ float g_v   [TOK*D_MODEL];
__device__ float g_att [TOK*D_MODEL];
__device__ float g_tmp [TOK*D_MODEL];
__device__ float g_out1[TOK*D_MODEL];
__device__ float g_ffh [TOK*DFF];
// hi/lo split bf16 weights, [K,N] layout (same as fp32 source)
__device__ __nv_bfloat16 g_wqh[D_MODEL*D_MODEL], g_wql[D_MODEL*D_MODEL];
__device__ __nv_bfloat16 g_wkh[D_MODEL*D_MODEL], g_wkl[D_MODEL*D_MODEL];
__device__ __nv_bfloat16 g_wvh[D_MODEL*D_MODEL], g_wvl[D_MODEL*D_MODEL];
__device__ __nv_bfloat16 g_woh[D_MODEL*D_MODEL], g_wol[D_MODEL*D_MODEL];
__device__ __nv_bfloat16 g_f1h[D_MODEL*DFF],     g_f1l[D_MODEL*DFF];
__device__ __nv_bfloat16 g_f2h[DFF*D_MODEL],     g_f2l[DFF*D_MODEL];

// ---------------- weight hi/lo split (layout preserved) --------------------
__global__ void split_w(const float* __restrict__ W,
                        __nv_bfloat16* __restrict__ Wh,
                        __nv_bfloat16* __restrict__ Wl, int n)
{
    int i = blockIdx.x * 256 + threadIdx.x;
    if (i >= n) return;
    float w = W[i];
    __nv_bfloat16 h = __float2bfloat16(w);
    Wh[i] = h;
    Wl[i] = __float2bfloat16(w - __bfloat162float(h));
}

// ---------------- bf16x3 mma.sync GEMM -------------------------------------
// C[z][M,Ntot] = A[M,K] @ W[z][K,Ntot] + bias[z]  (optional relu)
// Block 128x128, BK=32, 256 threads (8 warps, 4x2 of 32x64 warp tiles).
__global__ __launch_bounds__(256) void gemm_mma(
    const float* __restrict__ A,
    const __nv_bfloat16* __restrict__ Bh0, const __nv_bfloat16* __restrict__ Bl0,
    const __nv_bfloat16* __restrict__ Bh1, const __nv_bfloat16* __restrict__ Bl1,
    const __nv_bfloat16* __restrict__ Bh2, const __nv_bfloat16* __restrict__ Bl2,
    const float* __restrict__ bias0, const float* __restrict__ bias1,
    const float* __restrict__ bias2,
    float* __restrict__ C0, float* __restrict__ C1, float* __restrict__ C2,
    int K, int Ntot, int relu)
{
    // padded rows: A stride 40 bf16 (80B), B stride 136 bf16 (272B) ->
    // conflict-free ldmatrix address phases.
    __shared__ __align__(16) __nv_bfloat16 Ash[128][40];
    __shared__ __align__(16) __nv_bfloat16 Asl[128][40];
    __shared__ __align__(16) __nv_bfloat16 Bsh[32][136];
    __shared__ __align__(16) __nv_bfloat16 Bsl[32][136];

    int tid  = threadIdx.x;
    int lane = tid & 31;
    int wid  = tid >> 5;
    int wm   = wid & 3;      // 0..3 -> m offset wm*32
    int wn   = wid >> 2;     // 0..1 -> n offset wn*64

    int z = blockIdx.z;
    const __nv_bfloat16* Bh = (z == 0) ? Bh0 : (z == 1) ? Bh1 : Bh2;
    const __nv_bfloat16* Bl = (z == 0) ? Bl0 : (z == 1) ? Bl1 : Bl2;
    const float* bias = (z == 0) ? bias0 : (z == 1) ? bias1 : bias2;
    float* C = (z == 0) ? C0 : (z == 1) ? C1 : C2;

    int row0 = blockIdx.y * 128;
    int col0 = blockIdx.x * 128;

    float acc[2][8][4];
    #pragma unroll
    for (int a = 0; a < 2; a++)
        #pragma unroll
        for (int b = 0; b < 8; b++)
            #pragma unroll
            for (int c = 0; c < 4; c++) acc[a][b][c] = 0.f;

    for (int k0 = 0; k0 < K; k0 += 32) {
        // stage A: 128x32 fp32 -> bf16 hi/lo (1024 float4 loads)
        #pragma unroll
        for (int ii = 0; ii < 4; ii++) {
            int i = tid + ii * 256;
            int r = i >> 3, c = (i & 7) << 2;
            float4 av = *(const float4*)&A[(size_t)(row0 + r) * K + k0 + c];
            __nv_bfloat16 h0 = __float2bfloat16(av.x);
            __nv_bfloat16 h1 = __float2bfloat16(av.y);
            __nv_bfloat16 h2 = __float2bfloat16(av.z);
            __nv_bfloat16 h3 = __float2bfloat16(av.w);
            __nv_bfloat16 l0 = __float2bfloat16(av.x - __bfloat162float(h0));
            __nv_bfloat16 l1 = __float2bfloat16(av.y - __bfloat162float(h1));
            __nv_bfloat16 l2 = __float2bfloat16(av.z - __bfloat162float(h2));
            __nv_bfloat16 l3 = __float2bfloat16(av.w - __bfloat162float(h3));
            *(uint2*)&Ash[r][c] = make_uint2(pkbf(h0, h1), pkbf(h2, h3));
            *(uint2*)&Asl[r][c] = make_uint2(pkbf(l0, l1), pkbf(l2, l3));
        }
        // stage B: 32x128 bf16 hi/lo (preconverted, row-major [K,N])
        #pragma unroll
        for (int ii = 0; ii < 2; ii++) {
            int i = tid + ii * 256;
            int r = i >> 4, c = (i & 15) << 3;
            *(uint4*)&Bsh[r][c] = *(const uint4*)&Bh[(size_t)(k0 + r) * Ntot + col0 + c];
            *(uint4*)&Bsl[r][c] = *(const uint4*)&Bl[(size_t)(k0 + r) * Ntot + col0 + c];
        }
        __syncthreads();

        #pragma unroll
        for (int kk = 0; kk < 2; kk++) {
            uint32_t ah[2][4], al[2][4], bh[4][4], bl[4][4];
            int ar = (lane & 15);
            int ac = kk * 16 + (lane >> 4) * 8;
            #pragma unroll
            for (int mt = 0; mt < 2; mt++) {
                ldsm_x4(ah[mt], smem_u32(&Ash[wm * 32 + mt * 16 + ar][ac]));
                ldsm_x4(al[mt], smem_u32(&Asl[wm * 32 + mt * 16 + ar][ac]));
            }
            int br = kk * 16 + (lane & 15);
            int bcb = wn * 64 + (lane >> 4) * 8;
            #pragma unroll
            for (int nt = 0; nt < 4; nt++) {
                ldsm_x4t(bh[nt], smem_u32(&Bsh[br][bcb + nt * 16]));
                ldsm_x4t(bl[nt], smem_u32(&Bsl[br][bcb + nt * 16]));
            }
            #pragma unroll
            for (int mt = 0; mt < 2; mt++)
                #pragma unroll
                for (int nt = 0; nt < 4; nt++) {
                    mma_bf16(acc[mt][2*nt],   ah[mt], &bh[nt][0]);
                    mma_bf16(acc[mt][2*nt+1], ah[mt], &bh[nt][2]);
                    mma_bf16(acc[mt][2*nt],   al[mt], &bh[nt][0]);
                    mma_bf16(acc[mt][2*nt+1], al[mt], &bh[nt][2]);
                    mma_bf16(acc[mt][2*nt],   ah[mt], &bl[nt][0]);
                    mma_bf16(acc[mt][2*nt+1], ah[mt], &bl[nt][2]);
                }
        }
        __syncthreads();
    }

    // epilogue: d0,d1 -> row lane/4, cols (lane%4)*2+{0,1}; d2,d3 -> row+8
    int rb = row0 + wm * 32 + (lane >> 2);
    int cb = col0 + wn * 64 + (lane & 3) * 2;
    #pragma unroll
    for (int mt = 0; mt < 2; mt++) {
        #pragma unroll
        for (int nt8 = 0; nt8 < 8; nt8++) {
            int gc = cb + nt8 * 8;
            float2 bb = *(const float2*)&bias[gc];
            float2 o0, o1;
            o0.x = acc[mt][nt8][0] + bb.x;
            o0.y = acc[mt][nt8][1] + bb.y;
            o1.x = acc[mt][nt8][2] + bb.x;
            o1.y = acc[mt][nt8][3] + bb.y;
            if (relu) {
                o0.x = fmaxf(o0.x, 0.f); o0.y = fmaxf(o0.y, 0.f);
                o1.x = fmaxf(o1.x, 0.f); o1.y = fmaxf(o1.y, 0.f);
            }
            int gr = rb + mt * 16;
            *(float2*)&C[(size_t)gr * Ntot + gc] = o0;
            *(float2*)&C[(size_t)(gr + 8) * Ntot + gc] = o1;
        }
    }
}

// ---------------- RBF attention: 2 queries/thread, split-K x2 --------------
// block = 64 threads: threads 0-31 process keys [0,1024), threads 32-63 keys
// [1024,2048); thread owns queries q0 = blk*64 + (t&31) and q1 = q0+32.
// Softmax args in (0,1] -> single-pass streaming denom, no max needed.
__global__ __launch_bounds__(64) void attn_kernel(
    const float* __restrict__ Q, const float* __restrict__ K,
    const float* __restrict__ V, float* __restrict__ O)
{
    __shared__ __align__(16) float ks[2][64][36];
    __shared__ __align__(16) float vs[2][64][36];
    __shared__ float k2s[2][64];

    int t    = threadIdx.x;
    int half = t >> 5;
    int tq   = t & 31;
    int bh = blockIdx.y;
    int b  = bh >> 3;
    int h  = bh & 7;
    int q0 = blockIdx.x * 64 + tq;
    int q1 = q0 + 32;

    const float* qptr0 = Q + ((size_t)(b * SEQ + q0)) * D_MODEL + h * DEPTH;
    const float* qptr1 = Q + ((size_t)(b * SEQ + q1)) * D_MODEL + h * DEPTH;

    ull qp0[16], qp1[16];
    float q2_0 = 0.f, q2_1 = 0.f;
    #pragma unroll
    for (int i = 0; i < 8; i++) {
        float4 f0 = ((const float4*)qptr0)[i];
        float4 f1 = ((const float4*)qptr1)[i];
        qp0[2*i]   = pack2(f0.x, f0.y);
        qp0[2*i+1] = pack2(f0.z, f0.w);
        qp1[2*i]   = pack2(f1.x, f1.y);
        qp1[2*i+1] = pack2(f1.z, f1.w);
        q2_0 += f0.x*f0.x + f0.y*f0.y + f0.z*f0.z + f0.w*f0.w;
        q2_1 += f1.x*f1.x + f1.y*f1.y + f1.z*f1.z + f1.w*f1.w;
    }
    float qh0 = -0.5f * q2_0;
    float qh1 = -0.5f * q2_1;

    ull acc0[16], acc1[16];
    #pragma unroll
    for (int i = 0; i < 16; i++) { acc0[i] = 0ull; acc1[i] = 0ull; }
    float den0 = 0.f, den1 = 0.f;

    int ktbase = half * (SEQ / 2);
    for (int it = 0; it < (SEQ / 2) / 64; it++) {
        #pragma unroll
        for (int rr = 0; rr < 2; rr++) {
            int row = 2 * tq + rr;
            const float* kp = K + ((size_t)(b * SEQ + ktbase + it * 64 + row)) * D_MODEL + h * DEPTH;
            const float* vp = V + ((size_t)(b * SEQ + ktbase + it * 64 + row)) * D_MODEL + h * DEPTH;
            float k2 = 0.f;
            #pragma unroll
            for (int i = 0; i < 8; i++) {
                float4 kv = ((const float4*)kp)[i];
                *(float4*)&ks[half][row][i << 2] = kv;
                k2 += kv.x*kv.x + kv.y*kv.y + kv.z*kv.z + kv.w*kv.w;
                float4 vv = ((const float4*)vp)[i];
                *(float4*)&vs[half][row][i << 2] = vv;
            }
            k2s[half][row] = -0.5f * k2;
        }
        __syncthreads();

        for (int j = 0; j < 64; j++) {
            const ulonglong2* kr = (const ulonglong2*)&ks[half][j][0];
            ull d0a = 0ull, d0b = 0ull, d1a = 0ull, d1b = 0ull;
            #pragma unroll
            for (int i = 0; i < 8; i++) {
                ulonglong2 kk2 = kr[i];
                d0a = fma2(qp0[2*i],   kk2.x, d0a);
                d0b = fma2(qp0[2*i+1], kk2.y, d0b);
                d1a = fma2(qp1[2*i],   kk2.x, d1a);
                d1b = fma2(qp1[2*i+1], kk2.y, d1b);
            }
            float2 s0 = unpack2(add2(d0a, d0b));
            float2 s1 = unpack2(add2(d1a, d1b));
            float k2h = k2s[half][j];
            float w0 = __expf((s0.x + s0.y) + (qh0 + k2h));   // in (0,1]
            float w1 = __expf((s1.x + s1.y) + (qh1 + k2h));
            float p0 = __expf(w0);
            float p1 = __expf(w1);
            den0 += p0;
            den1 += p1;
            ull p0p = pack2(p0, p0);
            ull p1p = pack2(p1, p1);
            const ulonglong2* vr = (const ulonglong2*)&vs[half][j][0];
            #pragma unroll
            for (int i = 0; i < 8; i++) {
                ulonglong2 vv = vr[i];
                acc0[2*i]   = fma2(p0p, vv.x, acc0[2*i]);
                acc0[2*i+1] = fma2(p0p, vv.y, acc0[2*i+1]);
                acc1[2*i]   = fma2(p1p, vv.x, acc1[2*i]);
                acc1[2*i+1] = fma2(p1p, vv.y, acc1[2*i+1]);
            }
        }
        __syncthreads();
    }

    // combine halves
    ull*   cb = (ull*)&ks[0][0][0];
    float* db = &vs[0][0][0];
    if (half == 1) {
        ull* dst = cb + tq * 32;
        #pragma unroll
        for (int i = 0; i < 16; i++) { dst[i] = acc0[i]; dst[16 + i] = acc1[i]; }
        db[tq] = den0; db[32 + tq] = den1;
    }
    __syncthreads();
    if (half == 0) {
        const ull* src = cb + tq * 32;
        #pragma unroll
        for (int i = 0; i < 16; i++) {
            acc0[i] = add2(acc0[i], src[i]);
            acc1[i] = add2(acc1[i], src[16 + i]);
        }
        den0 += db[tq]; den1 += db[32 + tq];
        ull inv0 = pack2(1.f / den0, 1.f / den0);
        ull inv1 = pack2(1.f / den1, 1.f / den1);
        ull* op0 = (ull*)(O + ((size_t)(b * SEQ + q0)) * D_MODEL + h * DEPTH);
        ull* op1 = (ull*)(O + ((size_t)(b * SEQ + q1)) * D_MODEL + h * DEPTH);
        #pragma unroll
        for (int i = 0; i < 16; i++) {
            op0[i] = mul2(acc0[i], inv0);
            op1[i] = mul2(acc1[i], inv1);
        }
    }
}

// ---------------- fused residual + LayerNorm -------------------------------
__global__ __launch_bounds__(256) void residual_ln(
    const float* __restrict__ X, const float* __restrict__ Y,
    const float* __restrict__ g, const float* __restrict__ b,
    float* __restrict__ out)
{
    int row = blockIdx.x;
    int t   = threadIdx.x;
    float v = X[(size_t)row * D_MODEL + t] + Y[(size_t)row * D_MODEL + t];

    __shared__ float red[8];
    float s = v;
    #pragma unroll
    for (int o = 16; o > 0; o >>= 1) s += __shfl_xor_sync(0xffffffffu, s, o);
    if ((t & 31) == 0) red[t >> 5] = s;
    __syncthreads();
    float mean = (red[0]+red[1]+red[2]+red[3]+red[4]+red[5]+red[6]+red[7]) * (1.f/D_MODEL);

    float d  = v - mean;
    float s2 = d * d;
    #pragma unroll
    for (int o = 16; o > 0; o >>= 1) s2 += __shfl_xor_sync(0xffffffffu, s2, o);
    __syncthreads();
    if ((t & 31) == 0) red[t >> 5] = s2;
    __syncthreads();
    float var = (red[0]+red[1]+red[2]+red[3]+red[4]+red[5]+red[6]+red[7]) * (1.f/D_MODEL);

    out[(size_t)row * D_MODEL + t] = d * rsqrtf(var + EPS) * g[t] + b[t];
}

// ---------------- launch -----------------------------------------------------
extern "C" void kernel_launch(void* const* d_in, const int* in_sizes, int n_in,
                              void* d_out, int out_size)
{
    const float* x      = (const float*)d_in[0];
    const float* wq_w   = (const float*)d_in[1];
    const float* wq_b   = (const float*)d_in[2];
    const float* wk_w   = (const float*)d_in[3];
    const float* wk_b   = (const float*)d_in[4];
    const float* wv_w   = (const float*)d_in[5];
    const float* wv_b   = (const float*)d_in[6];
    const float* wo_w   = (const float*)d_in[7];
    const float* wo_b   = (const float*)d_in[8];
    const float* ffn1_w = (const float*)d_in[9];
    const float* ffn1_b = (const float*)d_in[10];
    const float* ffn2_w = (const float*)d_in[11];
    const float* ffn2_b = (const float*)d_in[12];
    const float* ln1_g  = (const float*)d_in[13];
    const float* ln1_b  = (const float*)d_in[14];
    const float* ln2_g  = (const float*)d_in[15];
    const float* ln2_b  = (const float*)d_in[16];

    float *q, *k, *v, *att, *tmp, *out1, *ffh;
    cudaGetSymbolAddress((void**)&q,    g_q);
    cudaGetSymbolAddress((void**)&k,    g_k);
    cudaGetSymbolAddress((void**)&v,    g_v);
    cudaGetSymbolAddress((void**)&att,  g_att);
    cudaGetSymbolAddress((void**)&tmp,  g_tmp);
    cudaGetSymbolAddress((void**)&out1, g_out1);
    cudaGetSymbolAddress((void**)&ffh,  g_ffh);

    __nv_bfloat16 *wqh, *wql, *wkh, *wkl, *wvh, *wvl, *woh, *wol, *f1h, *f1l, *f2h, *f2l;
    cudaGetSymbolAddress((void**)&wqh, g_wqh); cudaGetSymbolAddress((void**)&wql, g_wql);
    cudaGetSymbolAddress((void**)&wkh, g_wkh); cudaGetSymbolAddress((void**)&wkl, g_wkl);
    cudaGetSymbolAddress((void**)&wvh, g_wvh); cudaGetSymbolAddress((void**)&wvl, g_wvl);
    cudaGetSymbolAddress((void**)&woh, g_woh); cudaGetSymbolAddress((void**)&wol, g_wol);
    cudaGetSymbolAddress((void**)&f1h, g_f1h); cudaGetSymbolAddress((void**)&f1l, g_f1l);
    cudaGetSymbolAddress((void**)&f2h, g_f2h); cudaGetSymbolAddress((void**)&f2l, g_f2l);

    // weight hi/lo splits (layout preserved [K,N])
    int nsm = D_MODEL * D_MODEL;
    split_w<<<(nsm + 255) / 256, 256>>>(wq_w, wqh, wql, nsm);
    split_w<<<(nsm + 255) / 256, 256>>>(wk_w, wkh, wkl, nsm);
    split_w<<<(nsm + 255) / 256, 256>>>(wv_w, wvh, wvl, nsm);
    split_w<<<(nsm + 255) / 256, 256>>>(wo_w, woh, wol, nsm);
    int nf = D_MODEL * DFF;
    split_w<<<(nf + 255) / 256, 256>>>(ffn1_w, f1h, f1l, nf);
    split_w<<<(nf + 255) / 256, 256>>>(ffn2_w, f2h, f2l, nf);

    // fused Q/K/V projections (grid.z selects weight set)
    gemm_mma<<<dim3(D_MODEL / 128, TOK / 128, 3), 256>>>(
        x, wqh, wql, wkh, wkl, wvh, wvl, wq_b, wk_b, wv_b, q, k, v,
        D_MODEL, D_MODEL, 0);

    // RBF attention
    attn_kernel<<<dim3(SEQ / 64, BATCH * HEADS), 64>>>(q, k, v, att);

    // output projection + residual LN1
    gemm_mma<<<dim3(D_MODEL / 128, TOK / 128, 1), 256>>>(
        att, woh, wol, woh, wol, woh, wol, wo_b, wo_b, wo_b, tmp, tmp, tmp,
        D_MODEL, D_MODEL, 0);
    residual_ln<<<TOK, 256>>>(x, tmp, ln1_g, ln1_b, out1);

    // FFN
    gemm_mma<<<dim3(DFF / 128, TOK / 128, 1), 256>>>(
        out1, f1h, f1l, f1h, f1l, f1h, f1l, ffn1_b, ffn1_b, ffn1_b, ffh, ffh, ffh,
        D_MODEL, DFF, 1);
    gemm_mma<<<dim3(D_MODEL / 128, TOK / 128, 1), 256>>>(
        ffh, f2h, f2l, f2h, f2l, f2h, f2l, ffn2_b, ffn2_b, ffn2_b, tmp, tmp, tmp,
        DFF, D_MODEL, 0);
    residual_ln<<<TOK, 256>>>(out1, tmp, ln2_g, ln2_b, (float*)d_out);
}

// round 9
// speedup vs baseline: 2.0927x; 1.8878x over previous
#include <cuda_runtime.h>
#include <cuda_bf16.h>
#include <cstdint>
#include <math.h>

#define D_MODEL 256
#define BATCH   4
#define SEQ     2048
#define HEADS   8
#define DEPTH   32
#define DFF     1024
#define TOK     (BATCH*SEQ)   // 8192
#define EPS     1e-6f

// ---------------- mma.sync helpers (sm_80+ path, works on sm_103) ----------
__device__ __forceinline__ uint32_t smem_u32(const void* p) {
    uint32_t a;
    asm("{ .reg .u64 t; cvta.to.shared.u64 t, %1; cvt.u32.u64 %0, t; }"
        : "=r"(a) : "l"(p));
    return a;
}
__device__ __forceinline__ void ldsm_x4(uint32_t* r, uint32_t addr) {
    asm volatile("ldmatrix.sync.aligned.m8n8.x4.shared.b16 {%0,%1,%2,%3}, [%4];"
        : "=r"(r[0]), "=r"(r[1]), "=r"(r[2]), "=r"(r[3]) : "r"(addr));
}
__device__ __forceinline__ void ldsm_x4t(uint32_t* r, uint32_t addr) {
    asm volatile("ldmatrix.sync.aligned.m8n8.x4.trans.shared.b16 {%0,%1,%2,%3}, [%4];"
        : "=r"(r[0]), "=r"(r[1]), "=r"(r[2]), "=r"(r[3]) : "r"(addr));
}
__device__ __forceinline__ void mma_bf16(float* d, const uint32_t* a,
                                         uint32_t b0, uint32_t b1) {
    asm volatile("mma.sync.aligned.m16n8k16.row.col.f32.bf16.bf16.f32 "
        "{%0,%1,%2,%3}, {%4,%5,%6,%7}, {%8,%9}, {%0,%1,%2,%3};"
        : "+f"(d[0]), "+f"(d[1]), "+f"(d[2]), "+f"(d[3])
        : "r"(a[0]), "r"(a[1]), "r"(a[2]), "r"(a[3]), "r"(b0), "r"(b1));
}
__device__ __forceinline__ uint32_t pkbf(__nv_bfloat16 a, __nv_bfloat16 b) {
    return (uint32_t)__bfloat16_as_ushort(a) | ((uint32_t)__bfloat16_as_ushort(b) << 16);
}

// ---------------- scratch ---------------------------------------------------
__device__ float g_q   [TOK*D_MODEL];
__device__ float g_k   [TOK*D_MODEL];
__device__ float g_v   [TOK*D_MODEL];
__device__ float g_att [TOK*D_MODEL];
__device__ float g_tmp [TOK*D_MODEL];
__device__ float g_out1[TOK*D_MODEL];
__device__ float g_ffh [TOK*DFF];
__device__ __nv_bfloat16 g_wqh[D_MODEL*D_MODEL], g_wql[D_MODEL*D_MODEL];
__device__ __nv_bfloat16 g_wkh[D_MODEL*D_MODEL], g_wkl[D_MODEL*D_MODEL];
__device__ __nv_bfloat16 g_wvh[D_MODEL*D_MODEL], g_wvl[D_MODEL*D_MODEL];
__device__ __nv_bfloat16 g_woh[D_MODEL*D_MODEL], g_wol[D_MODEL*D_MODEL];
__device__ __nv_bfloat16 g_f1h[D_MODEL*DFF],     g_f1l[D_MODEL*DFF];
__device__ __nv_bfloat16 g_f2h[DFF*D_MODEL],     g_f2l[DFF*D_MODEL];

// ---------------- weight hi/lo split ---------------------------------------
__global__ void split_w(const float* __restrict__ W,
                        __nv_bfloat16* __restrict__ Wh,
                        __nv_bfloat16* __restrict__ Wl, int n)
{
    int i = blockIdx.x * 256 + threadIdx.x;
    if (i >= n) return;
    float w = W[i];
    __nv_bfloat16 h = __float2bfloat16(w);
    Wh[i] = h;
    Wl[i] = __float2bfloat16(w - __bfloat162float(h));
}

// ---------------- bf16x3 mma.sync GEMM -------------------------------------
__global__ __launch_bounds__(256) void gemm_mma(
    const float* __restrict__ A,
    const __nv_bfloat16* __restrict__ Bh0, const __nv_bfloat16* __restrict__ Bl0,
    const __nv_bfloat16* __restrict__ Bh1, const __nv_bfloat16* __restrict__ Bl1,
    const __nv_bfloat16* __restrict__ Bh2, const __nv_bfloat16* __restrict__ Bl2,
    const float* __restrict__ bias0, const float* __restrict__ bias1,
    const float* __restrict__ bias2,
    float* __restrict__ C0, float* __restrict__ C1, float* __restrict__ C2,
    int K, int Ntot, int relu)
{
    __shared__ __align__(16) __nv_bfloat16 Ash[128][40];
    __shared__ __align__(16) __nv_bfloat16 Asl[128][40];
    __shared__ __align__(16) __nv_bfloat16 Bsh[32][136];
    __shared__ __align__(16) __nv_bfloat16 Bsl[32][136];

    int tid  = threadIdx.x;
    int lane = tid & 31;
    int wid  = tid >> 5;
    int wm   = wid & 3;
    int wn   = wid >> 2;

    int z = blockIdx.z;
    const __nv_bfloat16* Bh = (z == 0) ? Bh0 : (z == 1) ? Bh1 : Bh2;
    const __nv_bfloat16* Bl = (z == 0) ? Bl0 : (z == 1) ? Bl1 : Bl2;
    const float* bias = (z == 0) ? bias0 : (z == 1) ? bias1 : bias2;
    float* C = (z == 0) ? C0 : (z == 1) ? C1 : C2;

    int row0 = blockIdx.y * 128;
    int col0 = blockIdx.x * 128;

    float acc[2][8][4];
    #pragma unroll
    for (int a = 0; a < 2; a++)
        #pragma unroll
        for (int b = 0; b < 8; b++)
            #pragma unroll
            for (int c = 0; c < 4; c++) acc[a][b][c] = 0.f;

    for (int k0 = 0; k0 < K; k0 += 32) {
        #pragma unroll
        for (int ii = 0; ii < 4; ii++) {
            int i = tid + ii * 256;
            int r = i >> 3, c = (i & 7) << 2;
            float4 av = *(const float4*)&A[(size_t)(row0 + r) * K + k0 + c];
            __nv_bfloat16 h0 = __float2bfloat16(av.x);
            __nv_bfloat16 h1 = __float2bfloat16(av.y);
            __nv_bfloat16 h2 = __float2bfloat16(av.z);
            __nv_bfloat16 h3 = __float2bfloat16(av.w);
            __nv_bfloat16 l0 = __float2bfloat16(av.x - __bfloat162float(h0));
            __nv_bfloat16 l1 = __float2bfloat16(av.y - __bfloat162float(h1));
            __nv_bfloat16 l2 = __float2bfloat16(av.z - __bfloat162float(h2));
            __nv_bfloat16 l3 = __float2bfloat16(av.w - __bfloat162float(h3));
            *(uint2*)&Ash[r][c] = make_uint2(pkbf(h0, h1), pkbf(h2, h3));
            *(uint2*)&Asl[r][c] = make_uint2(pkbf(l0, l1), pkbf(l2, l3));
        }
        #pragma unroll
        for (int ii = 0; ii < 2; ii++) {
            int i = tid + ii * 256;
            int r = i >> 4, c = (i & 15) << 3;
            *(uint4*)&Bsh[r][c] = *(const uint4*)&Bh[(size_t)(k0 + r) * Ntot + col0 + c];
            *(uint4*)&Bsl[r][c] = *(const uint4*)&Bl[(size_t)(k0 + r) * Ntot + col0 + c];
        }
        __syncthreads();

        #pragma unroll
        for (int kk = 0; kk < 2; kk++) {
            uint32_t ah[2][4], al[2][4], bh[4][4], bl[4][4];
            int ar = (lane & 15);
            int ac = kk * 16 + (lane >> 4) * 8;
            #pragma unroll
            for (int mt = 0; mt < 2; mt++) {
                ldsm_x4(ah[mt], smem_u32(&Ash[wm * 32 + mt * 16 + ar][ac]));
                ldsm_x4(al[mt], smem_u32(&Asl[wm * 32 + mt * 16 + ar][ac]));
            }
            int br = kk * 16 + (lane & 15);
            int bcb = wn * 64 + (lane >> 4) * 8;
            #pragma unroll
            for (int nt = 0; nt < 4; nt++) {
                ldsm_x4t(bh[nt], smem_u32(&Bsh[br][bcb + nt * 16]));
                ldsm_x4t(bl[nt], smem_u32(&Bsl[br][bcb + nt * 16]));
            }
            #pragma unroll
            for (int mt = 0; mt < 2; mt++)
                #pragma unroll
                for (int nt = 0; nt < 4; nt++) {
                    mma_bf16(acc[mt][2*nt],   ah[mt], bh[nt][0], bh[nt][1]);
                    mma_bf16(acc[mt][2*nt+1], ah[mt], bh[nt][2], bh[nt][3]);
                    mma_bf16(acc[mt][2*nt],   al[mt], bh[nt][0], bh[nt][1]);
                    mma_bf16(acc[mt][2*nt+1], al[mt], bh[nt][2], bh[nt][3]);
                    mma_bf16(acc[mt][2*nt],   ah[mt], bl[nt][0], bl[nt][1]);
                    mma_bf16(acc[mt][2*nt+1], ah[mt], bl[nt][2], bl[nt][3]);
                }
        }
        __syncthreads();
    }

    int rb = row0 + wm * 32 + (lane >> 2);
    int cb = col0 + wn * 64 + (lane & 3) * 2;
    #pragma unroll
    for (int mt = 0; mt < 2; mt++) {
        #pragma unroll
        for (int nt8 = 0; nt8 < 8; nt8++) {
            int gc = cb + nt8 * 8;
            float2 bb = *(const float2*)&bias[gc];
            float2 o0, o1;
            o0.x = acc[mt][nt8][0] + bb.x;
            o0.y = acc[mt][nt8][1] + bb.y;
            o1.x = acc[mt][nt8][2] + bb.x;
            o1.y = acc[mt][nt8][3] + bb.y;
            if (relu) {
                o0.x = fmaxf(o0.x, 0.f); o0.y = fmaxf(o0.y, 0.f);
                o1.x = fmaxf(o1.x, 0.f); o1.y = fmaxf(o1.y, 0.f);
            }
            int gr = rb + mt * 16;
            *(float2*)&C[(size_t)gr * Ntot + gc] = o0;
            *(float2*)&C[(size_t)(gr + 8) * Ntot + gc] = o1;
        }
    }
}

// ---------------- tensor-core RBF flash attention ---------------------------
// attn = softmax_j(exp(-0.5*||q_i-k_j||^2)); out = attn @ V.
// exp arg = dot(q,k) - 0.5||q||^2 - 0.5||k||^2; softmax args in (0,1] -> no max.
// Scores: bf16x3 (QhKh + QlKh + QhKl). PV: PhVh + PlVh + PhVl.
// Block: 128 queries, 4 warps (32 rows each), key tiles of 64.
#define ASM_QH 0
#define ASM_QL 10240
#define ASM_Q2 20480
#define ASM_KH 20992
#define ASM_KL 26112
#define ASM_K2 31232
#define ASM_VH 31488
#define ASM_VL 36608
#define ASM_PH 41728
#define ASM_PL 60160
#define ASM_TOT 78592

__global__ __launch_bounds__(128) void attn_mma(
    const float* __restrict__ Q, const float* __restrict__ K,
    const float* __restrict__ V, float* __restrict__ O)
{
    extern __shared__ __align__(16) char sm[];
    __nv_bfloat16* Qh = (__nv_bfloat16*)(sm + ASM_QH);
    __nv_bfloat16* Ql = (__nv_bfloat16*)(sm + ASM_QL);
    float*         q2s = (float*)(sm + ASM_Q2);
    __nv_bfloat16* Kh = (__nv_bfloat16*)(sm + ASM_KH);
    __nv_bfloat16* Kl = (__nv_bfloat16*)(sm + ASM_KL);
    float*         k2s = (float*)(sm + ASM_K2);
    __nv_bfloat16* Vh = (__nv_bfloat16*)(sm + ASM_VH);
    __nv_bfloat16* Vl = (__nv_bfloat16*)(sm + ASM_VL);
    __nv_bfloat16* Ph = (__nv_bfloat16*)(sm + ASM_PH);
    __nv_bfloat16* Pl = (__nv_bfloat16*)(sm + ASM_PL);

    int tid = threadIdx.x, lane = tid & 31, wid = tid >> 5;
    int bh = blockIdx.y, b = bh >> 3, h = bh & 7;
    int q0 = blockIdx.x * 128;

    // ---- stage Q: 8 passes, 16 rows each; 8 threads cover one row (coalesced)
    {
        int r = tid >> 3, cg = (tid & 7) * 4;
        #pragma unroll
        for (int p = 0; p < 8; p++) {
            int row = p * 16 + r;
            float4 f = *(const float4*)(Q + (size_t)(b*SEQ + q0 + row)*D_MODEL + h*DEPTH + cg);
            __nv_bfloat16 h0 = __float2bfloat16(f.x), h1 = __float2bfloat16(f.y);
            __nv_bfloat16 h2 = __float2bfloat16(f.z), h3 = __float2bfloat16(f.w);
            __nv_bfloat16 l0 = __float2bfloat16(f.x - __bfloat162float(h0));
            __nv_bfloat16 l1 = __float2bfloat16(f.y - __bfloat162float(h1));
            __nv_bfloat16 l2 = __float2bfloat16(f.z - __bfloat162float(h2));
            __nv_bfloat16 l3 = __float2bfloat16(f.w - __bfloat162float(h3));
            *(uint2*)&Qh[row*40 + cg] = make_uint2(pkbf(h0,h1), pkbf(h2,h3));
            *(uint2*)&Ql[row*40 + cg] = make_uint2(pkbf(l0,l1), pkbf(l2,l3));
            float s2 = f.x*f.x + f.y*f.y + f.z*f.z + f.w*f.w;
            s2 += __shfl_xor_sync(0xffffffffu, s2, 1);
            s2 += __shfl_xor_sync(0xffffffffu, s2, 2);
            s2 += __shfl_xor_sync(0xffffffffu, s2, 4);
            if ((tid & 7) == 0) q2s[row] = -0.5f * s2;
        }
    }
    __syncthreads();

    // ---- Q fragments (once)
    uint32_t qah[2][2][4], qal[2][2][4];
    {
        int ar = lane & 15, ag = (lane >> 4) * 8;
        #pragma unroll
        for (int mt = 0; mt < 2; mt++)
            #pragma unroll
            for (int kc = 0; kc < 2; kc++) {
                int off = (wid*32 + mt*16 + ar)*40 + kc*16 + ag;
                ldsm_x4(qah[mt][kc], smem_u32(&Qh[off]));
                ldsm_x4(qal[mt][kc], smem_u32(&Ql[off]));
            }
    }
    float q2r[2][2];
    #pragma unroll
    for (int mt = 0; mt < 2; mt++)
        #pragma unroll
        for (int rh = 0; rh < 2; rh++)
            q2r[mt][rh] = q2s[wid*32 + mt*16 + rh*8 + (lane >> 2)];

    float oacc[2][4][4];
    #pragma unroll
    for (int a = 0; a < 2; a++)
        #pragma unroll
        for (int c = 0; c < 4; c++)
            #pragma unroll
            for (int d = 0; d < 4; d++) oacc[a][c][d] = 0.f;
    float dpart[2][2] = {{0.f, 0.f}, {0.f, 0.f}};

    for (int kt = 0; kt < SEQ / 64; kt++) {
        // ---- stage K/V tile (64 rows): 4 passes, 8 threads per row
        {
            int r = tid >> 3, cg = (tid & 7) * 4;
            #pragma unroll
            for (int p = 0; p < 4; p++) {
                int row = p * 16 + r;
                size_t gofs = (size_t)(b*SEQ + kt*64 + row)*D_MODEL + h*DEPTH + cg;
                float4 f = *(const float4*)(K + gofs);
                __nv_bfloat16 h0 = __float2bfloat16(f.x), h1 = __float2bfloat16(f.y);
                __nv_bfloat16 h2 = __float2bfloat16(f.z), h3 = __float2bfloat16(f.w);
                __nv_bfloat16 l0 = __float2bfloat16(f.x - __bfloat162float(h0));
                __nv_bfloat16 l1 = __float2bfloat16(f.y - __bfloat162float(h1));
                __nv_bfloat16 l2 = __float2bfloat16(f.z - __bfloat162float(h2));
                __nv_bfloat16 l3 = __float2bfloat16(f.w - __bfloat162float(h3));
                *(uint2*)&Kh[row*40 + cg] = make_uint2(pkbf(h0,h1), pkbf(h2,h3));
                *(uint2*)&Kl[row*40 + cg] = make_uint2(pkbf(l0,l1), pkbf(l2,l3));
                float s2 = f.x*f.x + f.y*f.y + f.z*f.z + f.w*f.w;
                s2 += __shfl_xor_sync(0xffffffffu, s2, 1);
                s2 += __shfl_xor_sync(0xffffffffu, s2, 2);
                s2 += __shfl_xor_sync(0xffffffffu, s2, 4);
                if ((tid & 7) == 0) k2s[row] = -0.5f * s2;

                float4 g = *(const float4*)(V + gofs);
                __nv_bfloat16 vh0 = __float2bfloat16(g.x), vh1 = __float2bfloat16(g.y);
                __nv_bfloat16 vh2 = __float2bfloat16(g.z), vh3 = __float2bfloat16(g.w);
                __nv_bfloat16 vl0 = __float2bfloat16(g.x - __bfloat162float(vh0));
                __nv_bfloat16 vl1 = __float2bfloat16(g.y - __bfloat162float(vh1));
                __nv_bfloat16 vl2 = __float2bfloat16(g.z - __bfloat162float(vh2));
                __nv_bfloat16 vl3 = __float2bfloat16(g.w - __bfloat162float(vh3));
                *(uint2*)&Vh[row*40 + cg] = make_uint2(pkbf(vh0,vh1), pkbf(vh2,vh3));
                *(uint2*)&Vl[row*40 + cg] = make_uint2(pkbf(vl0,vl1), pkbf(vl2,vl3));
            }
        }
        __syncthreads();

        // ---- phase 1: scores -> p (bf16 hi/lo into P smem)
        {
            int ar = lane & 15, ag = (lane >> 4) * 8;
            #pragma unroll
            for (int ntp = 0; ntp < 4; ntp++) {
                uint32_t kbh[2][4], kbl[2][4];
                #pragma unroll
                for (int kc = 0; kc < 2; kc++) {
                    int off = (ntp*16 + ar)*40 + kc*16 + ag;
                    ldsm_x4(kbh[kc], smem_u32(&Kh[off]));
                    ldsm_x4(kbl[kc], smem_u32(&Kl[off]));
                }
                #pragma unroll
                for (int mt = 0; mt < 2; mt++)
                    #pragma unroll
                    for (int nt = 0; nt < 2; nt++) {
                        float s[4] = {0.f, 0.f, 0.f, 0.f};
                        #pragma unroll
                        for (int kc = 0; kc < 2; kc++) {
                            mma_bf16(s, qah[mt][kc], kbh[kc][nt], kbh[kc][nt+2]);
                            mma_bf16(s, qal[mt][kc], kbh[kc][nt], kbh[kc][nt+2]);
                            mma_bf16(s, qah[mt][kc], kbl[kc][nt], kbl[kc][nt+2]);
                        }
                        int cbase = ntp*16 + nt*8 + (lane & 3)*2;
                        float k2c0 = k2s[cbase], k2c1 = k2s[cbase + 1];
                        #pragma unroll
                        for (int rh = 0; rh < 2; rh++) {
                            float w0 = __expf(s[rh*2+0] + q2r[mt][rh] + k2c0);
                            float w1 = __expf(s[rh*2+1] + q2r[mt][rh] + k2c1);
                            float p0 = __expf(w0);
                            float p1 = __expf(w1);
                            dpart[mt][rh] += p0 + p1;
                            __nv_bfloat162 hp = __float22bfloat162_rn(make_float2(p0, p1));
                            float pl0 = p0 - __low2float(hp);
                            float pl1 = p1 - __high2float(hp);
                            __nv_bfloat162 lp = __float22bfloat162_rn(make_float2(pl0, pl1));
                            int prow = wid*32 + mt*16 + rh*8 + (lane >> 2);
                            *(uint32_t*)&Ph[prow*72 + cbase] = *(uint32_t*)&hp;
                            *(uint32_t*)&Pl[prow*72 + cbase] = *(uint32_t*)&lp;
                        }
                    }
            }
        }
        __syncwarp();

        // ---- phase 2: out += P @ V
        {
            int ar = lane & 15, ag = (lane >> 4) * 8;
            #pragma unroll
            for (int kc = 0; kc < 4; kc++) {
                uint32_t pah[2][4], pal[2][4], vbh[2][4], vbl[2][4];
                #pragma unroll
                for (int mt = 0; mt < 2; mt++) {
                    int off = (wid*32 + mt*16 + ar)*72 + kc*16 + ag;
                    ldsm_x4(pah[mt], smem_u32(&Ph[off]));
                    ldsm_x4(pal[mt], smem_u32(&Pl[off]));
                }
                #pragma unroll
                for (int ntp = 0; ntp < 2; ntp++) {
                    int off = (kc*16 + ar)*40 + ntp*16 + ag;
                    ldsm_x4t(vbh[ntp], smem_u32(&Vh[off]));
                    ldsm_x4t(vbl[ntp], smem_u32(&Vl[off]));
                }
                #pragma unroll
                for (int mt = 0; mt < 2; mt++)
                    #pragma unroll
                    for (int ntp = 0; ntp < 2; ntp++)
                        #pragma unroll
                        for (int nt = 0; nt < 2; nt++) {
                            float* o = oacc[mt][ntp*2 + nt];
                            mma_bf16(o, pah[mt], vbh[ntp][2*nt], vbh[ntp][2*nt+1]);
                            mma_bf16(o, pal[mt], vbh[ntp][2*nt], vbh[ntp][2*nt+1]);
                            mma_bf16(o, pah[mt], vbl[ntp][2*nt], vbl[ntp][2*nt+1]);
                        }
            }
        }
        __syncthreads();
    }

    // ---- epilogue: normalize + store
    #pragma unroll
    for (int mt = 0; mt < 2; mt++)
        #pragma unroll
        for (int rh = 0; rh < 2; rh++) {
            float den = dpart[mt][rh];
            den += __shfl_xor_sync(0xffffffffu, den, 1);
            den += __shfl_xor_sync(0xffffffffu, den, 2);
            float inv = 1.f / den;
            int row = q0 + wid*32 + mt*16 + rh*8 + (lane >> 2);
            float* op = O + (size_t)(b*SEQ + row)*D_MODEL + h*DEPTH + (lane & 3)*2;
            #pragma unroll
            for (int nt4 = 0; nt4 < 4; nt4++) {
                float2 o;
                o.x = oacc[mt][nt4][rh*2+0] * inv;
                o.y = oacc[mt][nt4][rh*2+1] * inv;
                *(float2*)(op + nt4*8) = o;
            }
        }
}

// ---------------- fused residual + LayerNorm -------------------------------
__global__ __launch_bounds__(256) void residual_ln(
    const float* __restrict__ X, const float* __restrict__ Y,
    const float* __restrict__ g, const float* __restrict__ b,
    float* __restrict__ out)
{
    int row = blockIdx.x;
    int t   = threadIdx.x;
    float v = X[(size_t)row * D_MODEL + t] + Y[(size_t)row * D_MODEL + t];

    __shared__ float red[8];
    float s = v;
    #pragma unroll
    for (int o = 16; o > 0; o >>= 1) s += __shfl_xor_sync(0xffffffffu, s, o);
    if ((t & 31) == 0) red[t >> 5] = s;
    __syncthreads();
    float mean = (red[0]+red[1]+red[2]+red[3]+red[4]+red[5]+red[6]+red[7]) * (1.f/D_MODEL);

    float d  = v - mean;
    float s2 = d * d;
    #pragma unroll
    for (int o = 16; o > 0; o >>= 1) s2 += __shfl_xor_sync(0xffffffffu, s2, o);
    __syncthreads();
    if ((t & 31) == 0) red[t >> 5] = s2;
    __syncthreads();
    float var = (red[0]+red[1]+red[2]+red[3]+red[4]+red[5]+red[6]+red[7]) * (1.f/D_MODEL);

    out[(size_t)row * D_MODEL + t] = d * rsqrtf(var + EPS) * g[t] + b[t];
}

// ---------------- launch -----------------------------------------------------
extern "C" void kernel_launch(void* const* d_in, const int* in_sizes, int n_in,
                              void* d_out, int out_size)
{
    const float* x      = (const float*)d_in[0];
    const float* wq_w   = (const float*)d_in[1];
    const float* wq_b   = (const float*)d_in[2];
    const float* wk_w   = (const float*)d_in[3];
    const float* wk_b   = (const float*)d_in[4];
    const float* wv_w   = (const float*)d_in[5];
    const float* wv_b   = (const float*)d_in[6];
    const float* wo_w   = (const float*)d_in[7];
    const float* wo_b   = (const float*)d_in[8];
    const float* ffn1_w = (const float*)d_in[9];
    const float* ffn1_b = (const float*)d_in[10];
    const float* ffn2_w = (const float*)d_in[11];
    const float* ffn2_b = (const float*)d_in[12];
    const float* ln1_g  = (const float*)d_in[13];
    const float* ln1_b  = (const float*)d_in[14];
    const float* ln2_g  = (const float*)d_in[15];
    const float* ln2_b  = (const float*)d_in[16];

    float *q, *k, *v, *att, *tmp, *out1, *ffh;
    cudaGetSymbolAddress((void**)&q,    g_q);
    cudaGetSymbolAddress((void**)&k,    g_k);
    cudaGetSymbolAddress((void**)&v,    g_v);
    cudaGetSymbolAddress((void**)&att,  g_att);
    cudaGetSymbolAddress((void**)&tmp,  g_tmp);
    cudaGetSymbolAddress((void**)&out1, g_out1);
    cudaGetSymbolAddress((void**)&ffh,  g_ffh);

    __nv_bfloat16 *wqh, *wql, *wkh, *wkl, *wvh, *wvl, *woh, *wol, *f1h, *f1l, *f2h, *f2l;
    cudaGetSymbolAddress((void**)&wqh, g_wqh); cudaGetSymbolAddress((void**)&wql, g_wql);
    cudaGetSymbolAddress((void**)&wkh, g_wkh); cudaGetSymbolAddress((void**)&wkl, g_wkl);
    cudaGetSymbolAddress((void**)&wvh, g_wvh); cudaGetSymbolAddress((void**)&wvl, g_wvl);
    cudaGetSymbolAddress((void**)&woh, g_woh); cudaGetSymbolAddress((void**)&wol, g_wol);
    cudaGetSymbolAddress((void**)&f1h, g_f1h); cudaGetSymbolAddress((void**)&f1l, g_f1l);
    cudaGetSymbolAddress((void**)&f2h, g_f2h); cudaGetSymbolAddress((void**)&f2l, g_f2l);

    cudaFuncSetAttribute(attn_mma, cudaFuncAttributeMaxDynamicSharedMemorySize, ASM_TOT);

    // weight hi/lo splits (layout preserved [K,N])
    int nsm = D_MODEL * D_MODEL;
    split_w<<<(nsm + 255) / 256, 256>>>(wq_w, wqh, wql, nsm);
    split_w<<<(nsm + 255) / 256, 256>>>(wk_w, wkh, wkl, nsm);
    split_w<<<(nsm + 255) / 256, 256>>>(wv_w, wvh, wvl, nsm);
    split_w<<<(nsm + 255) / 256, 256>>>(wo_w, woh, wol, nsm);
    int nf = D_MODEL * DFF;
    split_w<<<(nf + 255) / 256, 256>>>(ffn1_w, f1h, f1l, nf);
    split_w<<<(nf + 255) / 256, 256>>>(ffn2_w, f2h, f2l, nf);

    // fused Q/K/V projections
    gemm_mma<<<dim3(D_MODEL / 128, TOK / 128, 3), 256>>>(
        x, wqh, wql, wkh, wkl, wvh, wvl, wq_b, wk_b, wv_b, q, k, v,
        D_MODEL, D_MODEL, 0);

    // tensor-core RBF attention
    attn_mma<<<dim3(SEQ / 128, BATCH * HEADS), 128, ASM_TOT>>>(q, k, v, att);

    // output projection + residual LN1
    gemm_mma<<<dim3(D_MODEL / 128, TOK / 128, 1), 256>>>(
        att, woh, wol, woh, wol, woh, wol, wo_b, wo_b, wo_b, tmp, tmp, tmp,
        D_MODEL, D_MODEL, 0);
    residual_ln<<<TOK, 256>>>(x, tmp, ln1_g, ln1_b, out1);

    // FFN
    gemm_mma<<<dim3(DFF / 128, TOK / 128, 1), 256>>>(
        out1, f1h, f1l, f1h, f1l, f1h, f1l, ffn1_b, ffn1_b, ffn1_b, ffh, ffh, ffh,
        D_MODEL, DFF, 1);
    gemm_mma<<<dim3(D_MODEL / 128, TOK / 128, 1), 256>>>(
        ffh, f2h, f2l, f2h, f2l, f2h, f2l, ffn2_b, ffn2_b, ffn2_b, tmp, tmp, tmp,
        DFF, D_MODEL, 0);
    residual_ln<<<TOK, 256>>>(out1, tmp, ln2_g, ln2_b, (float*)d_out);
}

// round 10
// speedup vs baseline: 2.7931x; 1.3347x over previous
#include <cuda_runtime.h>
#include <cuda_bf16.h>
#include <cstdint>
#include <math.h>

#define D_MODEL 256
#define BATCH   4
#define SEQ     2048
#define HEADS   8
#define DEPTH   32
#define DFF     1024
#define TOK     (BATCH*SEQ)   // 8192
#define EPS     1e-6f

// ---------------- mma.sync / cp.async helpers ------------------------------
__device__ __forceinline__ uint32_t smem_u32(const void* p) {
    uint32_t a;
    asm("{ .reg .u64 t; cvta.to.shared.u64 t, %1; cvt.u32.u64 %0, t; }"
        : "=r"(a) : "l"(p));
    return a;
}
__device__ __forceinline__ void ldsm_x4(uint32_t* r, uint32_t addr) {
    asm volatile("ldmatrix.sync.aligned.m8n8.x4.shared.b16 {%0,%1,%2,%3}, [%4];"
        : "=r"(r[0]), "=r"(r[1]), "=r"(r[2]), "=r"(r[3]) : "r"(addr));
}
__device__ __forceinline__ void ldsm_x4t(uint32_t* r, uint32_t addr) {
    asm volatile("ldmatrix.sync.aligned.m8n8.x4.trans.shared.b16 {%0,%1,%2,%3}, [%4];"
        : "=r"(r[0]), "=r"(r[1]), "=r"(r[2]), "=r"(r[3]) : "r"(addr));
}
__device__ __forceinline__ void mma_bf16(float* d, const uint32_t* a,
                                         uint32_t b0, uint32_t b1) {
    asm volatile("mma.sync.aligned.m16n8k16.row.col.f32.bf16.bf16.f32 "
        "{%0,%1,%2,%3}, {%4,%5,%6,%7}, {%8,%9}, {%0,%1,%2,%3};"
        : "+f"(d[0]), "+f"(d[1]), "+f"(d[2]), "+f"(d[3])
        : "r"(a[0]), "r"(a[1]), "r"(a[2]), "r"(a[3]), "r"(b0), "r"(b1));
}
__device__ __forceinline__ uint32_t pkbf(__nv_bfloat16 a, __nv_bfloat16 b) {
    return (uint32_t)__bfloat16_as_ushort(a) | ((uint32_t)__bfloat16_as_ushort(b) << 16);
}
__device__ __forceinline__ void cpa16(uint32_t dst, const void* src) {
    asm volatile("cp.async.cg.shared.global [%0], [%1], 16;" :: "r"(dst), "l"(src));
}
#define CP_COMMIT() asm volatile("cp.async.commit_group;" ::: "memory")

// ---------------- scratch ---------------------------------------------------
__device__ float g_q   [TOK*D_MODEL];
__device__ float g_k   [TOK*D_MODEL];
__device__ float g_v   [TOK*D_MODEL];
__device__ float g_tmp [TOK*D_MODEL];
__device__ float g_out1[TOK*D_MODEL];
__device__ __nv_bfloat16 g_xh  [TOK*D_MODEL], g_xl  [TOK*D_MODEL];
__device__ __nv_bfloat16 g_atth[TOK*D_MODEL], g_attl[TOK*D_MODEL];
__device__ __nv_bfloat16 g_o1h [TOK*D_MODEL], g_o1l [TOK*D_MODEL];
__device__ __nv_bfloat16 g_ffhh[TOK*DFF],     g_ffhl[TOK*DFF];
__device__ __nv_bfloat16 g_wqh[D_MODEL*D_MODEL], g_wql[D_MODEL*D_MODEL];
__device__ __nv_bfloat16 g_wkh[D_MODEL*D_MODEL], g_wkl[D_MODEL*D_MODEL];
__device__ __nv_bfloat16 g_wvh[D_MODEL*D_MODEL], g_wvl[D_MODEL*D_MODEL];
__device__ __nv_bfloat16 g_woh[D_MODEL*D_MODEL], g_wol[D_MODEL*D_MODEL];
__device__ __nv_bfloat16 g_f1h[D_MODEL*DFF],     g_f1l[D_MODEL*DFF];
__device__ __nv_bfloat16 g_f2h[DFF*D_MODEL],     g_f2l[DFF*D_MODEL];

// ---------------- combined hi/lo split (weights + x), one launch ------------
struct SplitJobs {
    const float*   src[7];
    __nv_bfloat16* h[7];
    __nv_bfloat16* l[7];
    long long      start[8];   // start chunk (float4 units); start[7] = total
};
__global__ __launch_bounds__(256) void split_all(SplitJobs J)
{
    long long c = (long long)blockIdx.x * 256 + threadIdx.x;
    if (c >= J.start[7]) return;
    int s = 0;
    #pragma unroll
    for (int i = 1; i < 7; i++) if (c >= J.start[i]) s = i;
    long long i4 = c - J.start[s];
    float4 f = ((const float4*)J.src[s])[i4];
    __nv_bfloat16 h0 = __float2bfloat16(f.x), h1 = __float2bfloat16(f.y);
    __nv_bfloat16 h2 = __float2bfloat16(f.z), h3 = __float2bfloat16(f.w);
    __nv_bfloat16 l0 = __float2bfloat16(f.x - __bfloat162float(h0));
    __nv_bfloat16 l1 = __float2bfloat16(f.y - __bfloat162float(h1));
    __nv_bfloat16 l2 = __float2bfloat16(f.z - __bfloat162float(h2));
    __nv_bfloat16 l3 = __float2bfloat16(f.w - __bfloat162float(h3));
    ((uint2*)J.h[s])[i4] = make_uint2(pkbf(h0, h1), pkbf(h2, h3));
    ((uint2*)J.l[s])[i4] = make_uint2(pkbf(l0, l1), pkbf(l2, l3));
}

// ---------------- bf16x3 GEMM, cp.async double-buffered ---------------------
// A/B both pre-split bf16. Block 128x128, BK=32, 256 threads.
// outbf=0: C fp32 (+bias,+relu). outbf=1: C bf16 hi/lo pair (+bias,+relu).
#define GSTG   37888
#define G_AH   0
#define G_AL   10240
#define G_BH   20480
#define G_BL   29184
#define G_TOT  (2*GSTG)

__global__ __launch_bounds__(256) void gemm_bf3(
    const __nv_bfloat16* __restrict__ Ah, const __nv_bfloat16* __restrict__ Al,
    const __nv_bfloat16* __restrict__ Bh0, const __nv_bfloat16* __restrict__ Bl0,
    const __nv_bfloat16* __restrict__ Bh1, const __nv_bfloat16* __restrict__ Bl1,
    const __nv_bfloat16* __restrict__ Bh2, const __nv_bfloat16* __restrict__ Bl2,
    const float* __restrict__ bias0, const float* __restrict__ bias1,
    const float* __restrict__ bias2,
    float* __restrict__ Cf0, float* __restrict__ Cf1, float* __restrict__ Cf2,
    __nv_bfloat16* __restrict__ Ch, __nv_bfloat16* __restrict__ Cl,
    int K, int Ntot, int relu, int outbf)
{
    extern __shared__ __align__(16) char sm[];
    uint32_t smb = smem_u32(sm);

    int tid  = threadIdx.x;
    int lane = tid & 31;
    int wid  = tid >> 5;
    int wm   = wid & 3;
    int wn   = wid >> 2;

    int z = blockIdx.z;
    const __nv_bfloat16* Bh = (z == 0) ? Bh0 : (z == 1) ? Bh1 : Bh2;
    const __nv_bfloat16* Bl = (z == 0) ? Bl0 : (z == 1) ? Bl1 : Bl2;
    const float* bias = (z == 0) ? bias0 : (z == 1) ? bias1 : bias2;
    float* Cf = (z == 0) ? Cf0 : (z == 1) ? Cf1 : Cf2;

    int row0 = blockIdx.y * 128;
    int col0 = blockIdx.x * 128;

    float acc[2][8][4];
    #pragma unroll
    for (int a = 0; a < 2; a++)
        #pragma unroll
        for (int b = 0; b < 8; b++)
            #pragma unroll
            for (int c = 0; c < 4; c++) acc[a][b][c] = 0.f;

    int T = K >> 5;

    // stage loader (cp.async): A 128x32, B 32x128 (padded strides 40/136)
    #define LOAD_STAGE(sbuf, k0) do {                                          \
        uint32_t _b = smb + (sbuf) * GSTG;                                     \
        _Pragma("unroll")                                                      \
        for (int it = 0; it < 2; it++) {                                       \
            int idx = tid + it * 256;                                          \
            int r = idx >> 2, c8 = (idx & 3) << 3;                             \
            cpa16(_b + G_AH + r * 80 + c8 * 2,                                 \
                  Ah + (size_t)(row0 + r) * K + (k0) + c8);                    \
            cpa16(_b + G_AL + r * 80 + c8 * 2,                                 \
                  Al + (size_t)(row0 + r) * K + (k0) + c8);                    \
        }                                                                      \
        _Pragma("unroll")                                                      \
        for (int it = 0; it < 2; it++) {                                       \
            int idx = tid + it * 256;                                          \
            int r = idx >> 4, c8 = (idx & 15) << 3;                            \
            cpa16(_b + G_BH + r * 272 + c8 * 2,                                \
                  Bh + (size_t)((k0) + r) * Ntot + col0 + c8);                 \
            cpa16(_b + G_BL + r * 272 + c8 * 2,                                \
                  Bl + (size_t)((k0) + r) * Ntot + col0 + c8);                 \
        }                                                                      \
        CP_COMMIT();                                                           \
    } while (0)

    LOAD_STAGE(0, 0);

    for (int t = 0; t < T; t++) {
        if (t + 1 < T) {
            LOAD_STAGE((t + 1) & 1, (t + 1) * 32);
            asm volatile("cp.async.wait_group 1;" ::: "memory");
        } else {
            asm volatile("cp.async.wait_group 0;" ::: "memory");
        }
        __syncthreads();

        uint32_t sb = smb + (t & 1) * GSTG;
        #pragma unroll
        for (int kk = 0; kk < 2; kk++) {
            uint32_t ah[2][4], al[2][4], bh[4][4], bl[4][4];
            int ar = (lane & 15);
            int ac = kk * 16 + (lane >> 4) * 8;
            #pragma unroll
            for (int mt = 0; mt < 2; mt++) {
                uint32_t aoff = sb + (wm * 32 + mt * 16 + ar) * 80 + ac * 2;
                ldsm_x4(ah[mt], aoff + G_AH);
                ldsm_x4(al[mt], aoff + G_AL);
            }
            int br = kk * 16 + (lane & 15);
            int bcb = wn * 64 + (lane >> 4) * 8;
            #pragma unroll
            for (int nt = 0; nt < 4; nt++) {
                uint32_t boff = sb + br * 272 + (bcb + nt * 16) * 2;
                ldsm_x4t(bh[nt], boff + G_BH);
                ldsm_x4t(bl[nt], boff + G_BL);
            }
            #pragma unroll
            for (int mt = 0; mt < 2; mt++)
                #pragma unroll
                for (int nt = 0; nt < 4; nt++) {
                    mma_bf16(acc[mt][2*nt],   ah[mt], bh[nt][0], bh[nt][1]);
                    mma_bf16(acc[mt][2*nt+1], ah[mt], bh[nt][2], bh[nt][3]);
                    mma_bf16(acc[mt][2*nt],   al[mt], bh[nt][0], bh[nt][1]);
                    mma_bf16(acc[mt][2*nt+1], al[mt], bh[nt][2], bh[nt][3]);
                    mma_bf16(acc[mt][2*nt],   ah[mt], bl[nt][0], bl[nt][1]);
                    mma_bf16(acc[mt][2*nt+1], ah[mt], bl[nt][2], bl[nt][3]);
                }
        }
        __syncthreads();
    }

    int rb = row0 + wm * 32 + (lane >> 2);
    int cb = col0 + wn * 64 + (lane & 3) * 2;
    #pragma unroll
    for (int mt = 0; mt < 2; mt++) {
        #pragma unroll
        for (int nt8 = 0; nt8 < 8; nt8++) {
            int gc = cb + nt8 * 8;
            float2 bb = *(const float2*)&bias[gc];
            float2 o0, o1;
            o0.x = acc[mt][nt8][0] + bb.x;
            o0.y = acc[mt][nt8][1] + bb.y;
            o1.x = acc[mt][nt8][2] + bb.x;
            o1.y = acc[mt][nt8][3] + bb.y;
            if (relu) {
                o0.x = fmaxf(o0.x, 0.f); o0.y = fmaxf(o0.y, 0.f);
                o1.x = fmaxf(o1.x, 0.f); o1.y = fmaxf(o1.y, 0.f);
            }
            int gr = rb + mt * 16;
            if (!outbf) {
                *(float2*)&Cf[(size_t)gr * Ntot + gc] = o0;
                *(float2*)&Cf[(size_t)(gr + 8) * Ntot + gc] = o1;
            } else {
                __nv_bfloat16 h0 = __float2bfloat16(o0.x), h1 = __float2bfloat16(o0.y);
                __nv_bfloat16 h2 = __float2bfloat16(o1.x), h3 = __float2bfloat16(o1.y);
                uint32_t hw0 = pkbf(h0, h1), hw1 = pkbf(h2, h3);
                uint32_t lw0 = pkbf(__float2bfloat16(o0.x - __bfloat162float(h0)),
                                    __float2bfloat16(o0.y - __bfloat162float(h1)));
                uint32_t lw1 = pkbf(__float2bfloat16(o1.x - __bfloat162float(h2)),
                                    __float2bfloat16(o1.y - __bfloat162float(h3)));
                *(uint32_t*)&Ch[(size_t)gr * Ntot + gc] = hw0;
                *(uint32_t*)&Cl[(size_t)gr * Ntot + gc] = lw0;
                *(uint32_t*)&Ch[(size_t)(gr + 8) * Ntot + gc] = hw1;
                *(uint32_t*)&Cl[(size_t)(gr + 8) * Ntot + gc] = lw1;
            }
        }
    }
}

// ---------------- tensor-core RBF flash attention ---------------------------
// Scores: bf16x3 (QhKh + QlKh + QhKl). PV: single term PhVh (low-order PV
// terms are unbiased ~2^-9 noise diluted ~1/sqrt(2048) by the softmax mean).
// Output written directly as bf16 hi/lo pair for the O-projection GEMM.
#define ASM_QH 0
#define ASM_QL 10240
#define ASM_Q2 20480
#define ASM_KH 20992
#define ASM_KL 26112
#define ASM_K2 31232
#define ASM_VH 31488
#define ASM_PH 36608
#define ASM_TOT 55040

__global__ __launch_bounds__(128) void attn_mma(
    const float* __restrict__ Q, const float* __restrict__ K,
    const float* __restrict__ V,
    __nv_bfloat16* __restrict__ Oh, __nv_bfloat16* __restrict__ Ol)
{
    extern __shared__ __align__(16) char sm[];
    __nv_bfloat16* Qh = (__nv_bfloat16*)(sm + ASM_QH);
    __nv_bfloat16* Ql = (__nv_bfloat16*)(sm + ASM_QL);
    float*         q2s = (float*)(sm + ASM_Q2);
    __nv_bfloat16* Kh = (__nv_bfloat16*)(sm + ASM_KH);
    __nv_bfloat16* Kl = (__nv_bfloat16*)(sm + ASM_KL);
    float*         k2s = (float*)(sm + ASM_K2);
    __nv_bfloat16* Vh = (__nv_bfloat16*)(sm + ASM_VH);
    __nv_bfloat16* Ph = (__nv_bfloat16*)(sm + ASM_PH);

    int tid = threadIdx.x, lane = tid & 31, wid = tid >> 5;
    int bh = blockIdx.y, b = bh >> 3, h = bh & 7;
    int q0 = blockIdx.x * 128;

    // ---- stage Q (fp32 -> bf16 hi/lo + norms)
    {
        int r = tid >> 3, cg = (tid & 7) * 4;
        #pragma unroll
        for (int p = 0; p < 8; p++) {
            int row = p * 16 + r;
            float4 f = *(const float4*)(Q + (size_t)(b*SEQ + q0 + row)*D_MODEL + h*DEPTH + cg);
            __nv_bfloat16 h0 = __float2bfloat16(f.x), h1 = __float2bfloat16(f.y);
            __nv_bfloat16 h2 = __float2bfloat16(f.z), h3 = __float2bfloat16(f.w);
            __nv_bfloat16 l0 = __float2bfloat16(f.x - __bfloat162float(h0));
            __nv_bfloat16 l1 = __float2bfloat16(f.y - __bfloat162float(h1));
            __nv_bfloat16 l2 = __float2bfloat16(f.z - __bfloat162float(h2));
            __nv_bfloat16 l3 = __float2bfloat16(f.w - __bfloat162float(h3));
            *(uint2*)&Qh[row*40 + cg] = make_uint2(pkbf(h0,h1), pkbf(h2,h3));
            *(uint2*)&Ql[row*40 + cg] = make_uint2(pkbf(l0,l1), pkbf(l2,l3));
            float s2 = f.x*f.x + f.y*f.y + f.z*f.z + f.w*f.w;
            s2 += __shfl_xor_sync(0xffffffffu, s2, 1);
            s2 += __shfl_xor_sync(0xffffffffu, s2, 2);
            s2 += __shfl_xor_sync(0xffffffffu, s2, 4);
            if ((tid & 7) == 0) q2s[row] = -0.5f * s2;
        }
    }
    __syncthreads();

    uint32_t qah[2][2][4], qal[2][2][4];
    {
        int ar = lane & 15, ag = (lane >> 4) * 8;
        #pragma unroll
        for (int mt = 0; mt < 2; mt++)
            #pragma unroll
            for (int kc = 0; kc < 2; kc++) {
                int off = (wid*32 + mt*16 + ar)*40 + kc*16 + ag;
                ldsm_x4(qah[mt][kc], smem_u32(&Qh[off]));
                ldsm_x4(qal[mt][kc], smem_u32(&Ql[off]));
            }
    }
    float q2r[2][2];
    #pragma unroll
    for (int mt = 0; mt < 2; mt++)
        #pragma unroll
        for (int rh = 0; rh < 2; rh++)
            q2r[mt][rh] = q2s[wid*32 + mt*16 + rh*8 + (lane >> 2)];

    float oacc[2][4][4];
    #pragma unroll
    for (int a = 0; a < 2; a++)
        #pragma unroll
        for (int c = 0; c < 4; c++)
            #pragma unroll
            for (int d = 0; d < 4; d++) oacc[a][c][d] = 0.f;
    float dpart[2][2] = {{0.f, 0.f}, {0.f, 0.f}};

    for (int kt = 0; kt < SEQ / 64; kt++) {
        // ---- stage K (hi/lo + norms) and V (hi only)
        {
            int r = tid >> 3, cg = (tid & 7) * 4;
            #pragma unroll
            for (int p = 0; p < 4; p++) {
                int row = p * 16 + r;
                size_t gofs = (size_t)(b*SEQ + kt*64 + row)*D_MODEL + h*DEPTH + cg;
                float4 f = *(const float4*)(K + gofs);
                __nv_bfloat16 h0 = __float2bfloat16(f.x), h1 = __float2bfloat16(f.y);
                __nv_bfloat16 h2 = __float2bfloat16(f.z), h3 = __float2bfloat16(f.w);
                __nv_bfloat16 l0 = __float2bfloat16(f.x - __bfloat162float(h0));
                __nv_bfloat16 l1 = __float2bfloat16(f.y - __bfloat162float(h1));
                __nv_bfloat16 l2 = __float2bfloat16(f.z - __bfloat162float(h2));
                __nv_bfloat16 l3 = __float2bfloat16(f.w - __bfloat162float(h3));
                *(uint2*)&Kh[row*40 + cg] = make_uint2(pkbf(h0,h1), pkbf(h2,h3));
                *(uint2*)&Kl[row*40 + cg] = make_uint2(pkbf(l0,l1), pkbf(l2,l3));
                float s2 = f.x*f.x + f.y*f.y + f.z*f.z + f.w*f.w;
                s2 += __shfl_xor_sync(0xffffffffu, s2, 1);
                s2 += __shfl_xor_sync(0xffffffffu, s2, 2);
                s2 += __shfl_xor_sync(0xffffffffu, s2, 4);
                if ((tid & 7) == 0) k2s[row] = -0.5f * s2;

                float4 g = *(const float4*)(V + gofs);
                __nv_bfloat16 vh0 = __float2bfloat16(g.x), vh1 = __float2bfloat16(g.y);
                __nv_bfloat16 vh2 = __float2bfloat16(g.z), vh3 = __float2bfloat16(g.w);
                *(uint2*)&Vh[row*40 + cg] = make_uint2(pkbf(vh0,vh1), pkbf(vh2,vh3));
            }
        }
        __syncthreads();

        // ---- phase 1: scores -> p (bf16 into P smem)
        {
            int ar = lane & 15, ag = (lane >> 4) * 8;
            #pragma unroll
            for (int ntp = 0; ntp < 4; ntp++) {
                uint32_t kbh[2][4], kbl[2][4];
                #pragma unroll
                for (int kc = 0; kc < 2; kc++) {
                    int off = (ntp*16 + ar)*40 + kc*16 + ag;
                    ldsm_x4(kbh[kc], smem_u32(&Kh[off]));
                    ldsm_x4(kbl[kc], smem_u32(&Kl[off]));
                }
                #pragma unroll
                for (int mt = 0; mt < 2; mt++)
                    #pragma unroll
                    for (int nt = 0; nt < 2; nt++) {
                        float s[4] = {0.f, 0.f, 0.f, 0.f};
                        #pragma unroll
                        for (int kc = 0; kc < 2; kc++) {
                            mma_bf16(s, qah[mt][kc], kbh[kc][nt], kbh[kc][nt+2]);
                            mma_bf16(s, qal[mt][kc], kbh[kc][nt], kbh[kc][nt+2]);
                            mma_bf16(s, qah[mt][kc], kbl[kc][nt], kbl[kc][nt+2]);
                        }
                        int cbase = ntp*16 + nt*8 + (lane & 3)*2;
                        float k2c0 = k2s[cbase], k2c1 = k2s[cbase + 1];
                        #pragma unroll
                        for (int rh = 0; rh < 2; rh++) {
                            float w0 = __expf(s[rh*2+0] + q2r[mt][rh] + k2c0);
                            float w1 = __expf(s[rh*2+1] + q2r[mt][rh] + k2c1);
                            float p0 = __expf(w0);
                            float p1 = __expf(w1);
                            dpart[mt][rh] += p0 + p1;
                            __nv_bfloat162 hp = __float22bfloat162_rn(make_float2(p0, p1));
                            int prow = wid*32 + mt*16 + rh*8 + (lane >> 2);
                            *(uint32_t*)&Ph[prow*72 + cbase] = *(uint32_t*)&hp;
                        }
                    }
            }
        }
        __syncwarp();

        // ---- phase 2: out += Ph @ Vh
        {
            int ar = lane & 15, ag = (lane >> 4) * 8;
            #pragma unroll
            for (int kc = 0; kc < 4; kc++) {
                uint32_t pah[2][4], vbh[2][4];
                #pragma unroll
                for (int mt = 0; mt < 2; mt++)
                    ldsm_x4(pah[mt], smem_u32(&Ph[(wid*32 + mt*16 + ar)*72 + kc*16 + ag]));
                #pragma unroll
                for (int ntp = 0; ntp < 2; ntp++)
                    ldsm_x4t(vbh[ntp], smem_u32(&Vh[(kc*16 + ar)*40 + ntp*16 + ag]));
                #pragma unroll
                for (int mt = 0; mt < 2; mt++)
                    #pragma unroll
                    for (int ntp = 0; ntp < 2; ntp++)
                        #pragma unroll
                        for (int nt = 0; nt < 2; nt++)
                            mma_bf16(oacc[mt][ntp*2 + nt], pah[mt],
                                     vbh[ntp][2*nt], vbh[ntp][2*nt+1]);
            }
        }
        __syncthreads();
    }

    // ---- epilogue: normalize + store as bf16 hi/lo
    #pragma unroll
    for (int mt = 0; mt < 2; mt++)
        #pragma unroll
        for (int rh = 0; rh < 2; rh++) {
            float den = dpart[mt][rh];
            den += __shfl_xor_sync(0xffffffffu, den, 1);
            den += __shfl_xor_sync(0xffffffffu, den, 2);
            float inv = 1.f / den;
            int row = q0 + wid*32 + mt*16 + rh*8 + (lane >> 2);
            size_t obase = (size_t)(b*SEQ + row)*D_MODEL + h*DEPTH + (lane & 3)*2;
            #pragma unroll
            for (int nt4 = 0; nt4 < 4; nt4++) {
                float ox = oacc[mt][nt4][rh*2+0] * inv;
                float oy = oacc[mt][nt4][rh*2+1] * inv;
                __nv_bfloat16 h0 = __float2bfloat16(ox), h1 = __float2bfloat16(oy);
                uint32_t hw = pkbf(h0, h1);
                uint32_t lw = pkbf(__float2bfloat16(ox - __bfloat162float(h0)),
                                   __float2bfloat16(oy - __bfloat162float(h1)));
                *(uint32_t*)(Oh + obase + nt4*8) = hw;
                *(uint32_t*)(Ol + obase + nt4*8) = lw;
            }
        }
}

// ---------------- fused residual + LayerNorm (warp per row) -----------------
// optional bf16 hi/lo split of the output (for feeding the next GEMM).
__global__ __launch_bounds__(256) void residual_ln(
    const float* __restrict__ X, const float* __restrict__ Y,
    const float* __restrict__ g, const float* __restrict__ b,
    float* __restrict__ outf,
    __nv_bfloat16* __restrict__ outh, __nv_bfloat16* __restrict__ outl,
    int do_split)
{
    int lane = threadIdx.x & 31, w = threadIdx.x >> 5;
    int row  = blockIdx.x * 8 + w;
    size_t base = (size_t)row * D_MODEL;
    int c0 = lane * 4, c1 = 128 + lane * 4;

    float4 x0 = *(const float4*)(X + base + c0);
    float4 x1 = *(const float4*)(X + base + c1);
    float4 y0 = *(const float4*)(Y + base + c0);
    float4 y1 = *(const float4*)(Y + base + c1);
    float4 v0 = make_float4(x0.x+y0.x, x0.y+y0.y, x0.z+y0.z, x0.w+y0.w);
    float4 v1 = make_float4(x1.x+y1.x, x1.y+y1.y, x1.z+y1.z, x1.w+y1.w);

    float s = v0.x+v0.y+v0.z+v0.w + v1.x+v1.y+v1.z+v1.w;
    #pragma unroll
    for (int o = 16; o > 0; o >>= 1) s += __shfl_xor_sync(0xffffffffu, s, o);
    float mean = s * (1.f / D_MODEL);

    float4 d0 = make_float4(v0.x-mean, v0.y-mean, v0.z-mean, v0.w-mean);
    float4 d1 = make_float4(v1.x-mean, v1.y-mean, v1.z-mean, v1.w-mean);
    float s2 = d0.x*d0.x+d0.y*d0.y+d0.z*d0.z+d0.w*d0.w
             + d1.x*d1.x+d1.y*d1.y+d1.z*d1.z+d1.w*d1.w;
    #pragma unroll
    for (int o = 16; o > 0; o >>= 1) s2 += __shfl_xor_sync(0xffffffffu, s2, o);
    float rstd = rsqrtf(s2 * (1.f / D_MODEL) + EPS);

    float4 g0 = *(const float4*)(g + c0), g1 = *(const float4*)(g + c1);
    float4 b0 = *(const float4*)(b + c0), b1 = *(const float4*)(b + c1);
    float4 o0, o1;
    o0.x = d0.x*rstd*g0.x + b0.x; o0.y = d0.y*rstd*g0.y + b0.y;
    o0.z = d0.z*rstd*g0.z + b0.z; o0.w = d0.w*rstd*g0.w + b0.w;
    o1.x = d1.x*rstd*g1.x + b1.x; o1.y = d1.y*rstd*g1.y + b1.y;
    o1.z = d1.z*rstd*g1.z + b1.z; o1.w = d1.w*rstd*g1.w + b1.w;
    *(float4*)(outf + base + c0) = o0;
    *(float4*)(outf + base + c1) = o1;

    if (do_split) {
        __nv_bfloat16 h0 = __float2bfloat16(o0.x), h1 = __float2bfloat16(o0.y);
        __nv_bfloat16 h2 = __float2bfloat16(o0.z), h3 = __float2bfloat16(o0.w);
        __nv_bfloat16 h4 = __float2bfloat16(o1.x), h5 = __float2bfloat16(o1.y);
        __nv_bfloat16 h6 = __float2bfloat16(o1.z), h7 = __float2bfloat16(o1.w);
        *(uint2*)(outh + base + c0) = make_uint2(pkbf(h0,h1), pkbf(h2,h3));
        *(uint2*)(outh + base + c1) = make_uint2(pkbf(h4,h5), pkbf(h6,h7));
        *(uint2*)(outl + base + c0) = make_uint2(
            pkbf(__float2bfloat16(o0.x-__bfloat162float(h0)),
                 __float2bfloat16(o0.y-__bfloat162float(h1))),
            pkbf(__float2bfloat16(o0.z-__bfloat162float(h2)),
                 __float2bfloat16(o0.w-__bfloat162float(h3))));
        *(uint2*)(outl + base + c1) = make_uint2(
            pkbf(__float2bfloat16(o1.x-__bfloat162float(h4)),
                 __float2bfloat16(o1.y-__bfloat162float(h5))),
            pkbf(__float2bfloat16(o1.z-__bfloat162float(h6)),
                 __float2bfloat16(o1.w-__bfloat162float(h7))));
    }
}

// ---------------- launch -----------------------------------------------------
extern "C" void kernel_launch(void* const* d_in, const int* in_sizes, int n_in,
                              void* d_out, int out_size)
{
    const float* x      = (const float*)d_in[0];
    const float* wq_w   = (const float*)d_in[1];
    const float* wq_b   = (const float*)d_in[2];
    const float* wk_w   = (const float*)d_in[3];
    const float* wk_b   = (const float*)d_in[4];
    const float* wv_w   = (const float*)d_in[5];
    const float* wv_b   = (const float*)d_in[6];
    const float* wo_w   = (const float*)d_in[7];
    const float* wo_b   = (const float*)d_in[8];
    const float* ffn1_w = (const float*)d_in[9];
    const float* ffn1_b = (const float*)d_in[10];
    const float* ffn2_w = (const float*)d_in[11];
    const float* ffn2_b = (const float*)d_in[12];
    const float* ln1_g  = (const float*)d_in[13];
    const float* ln1_b  = (const float*)d_in[14];
    const float* ln2_g  = (const float*)d_in[15];
    const float* ln2_b  = (const float*)d_in[16];

    float *q, *k, *v, *tmp, *out1;
    cudaGetSymbolAddress((void**)&q,    g_q);
    cudaGetSymbolAddress((void**)&k,    g_k);
    cudaGetSymbolAddress((void**)&v,    g_v);
    cudaGetSymbolAddress((void**)&tmp,  g_tmp);
    cudaGetSymbolAddress((void**)&out1, g_out1);

    __nv_bfloat16 *xh, *xl, *atth, *attl, *o1h, *o1l, *ffhh, *ffhl;
    cudaGetSymbolAddress((void**)&xh,   g_xh);   cudaGetSymbolAddress((void**)&xl,   g_xl);
    cudaGetSymbolAddress((void**)&atth, g_atth); cudaGetSymbolAddress((void**)&attl, g_attl);
    cudaGetSymbolAddress((void**)&o1h,  g_o1h);  cudaGetSymbolAddress((void**)&o1l,  g_o1l);
    cudaGetSymbolAddress((void**)&ffhh, g_ffhh); cudaGetSymbolAddress((void**)&ffhl, g_ffhl);

    __nv_bfloat16 *wqh, *wql, *wkh, *wkl, *wvh, *wvl, *woh, *wol, *f1h, *f1l, *f2h, *f2l;
    cudaGetSymbolAddress((void**)&wqh, g_wqh); cudaGetSymbolAddress((void**)&wql, g_wql);
    cudaGetSymbolAddress((void**)&wkh, g_wkh); cudaGetSymbolAddress((void**)&wkl, g_wkl);
    cudaGetSymbolAddress((void**)&wvh, g_wvh); cudaGetSymbolAddress((void**)&wvl, g_wvl);
    cudaGetSymbolAddress((void**)&woh, g_woh); cudaGetSymbolAddress((void**)&wol, g_wol);
    cudaGetSymbolAddress((void**)&f1h, g_f1h); cudaGetSymbolAddress((void**)&f1l, g_f1l);
    cudaGetSymbolAddress((void**)&f2h, g_f2h); cudaGetSymbolAddress((void**)&f2l, g_f2l);

    cudaFuncSetAttribute(attn_mma, cudaFuncAttributeMaxDynamicSharedMemorySize, ASM_TOT);
    cudaFuncSetAttribute(gemm_bf3, cudaFuncAttributeMaxDynamicSharedMemorySize, G_TOT);

    // one combined split launch: 6 weights + x
    SplitJobs J;
    const float* srcs[7] = {wq_w, wk_w, wv_w, wo_w, ffn1_w, ffn2_w, x};
    __nv_bfloat16* hs[7] = {wqh, wkh, wvh, woh, f1h, f2h, xh};
    __nv_bfloat16* ls[7] = {wql, wkl, wvl, wol, f1l, f2l, xl};
    long long sizes4[7] = {65536/4, 65536/4, 65536/4, 65536/4,
                           262144/4, 262144/4, (long long)TOK*D_MODEL/4};
    long long acc = 0;
    for (int i = 0; i < 7; i++) { J.src[i] = srcs[i]; J.h[i] = hs[i]; J.l[i] = ls[i];
                                  J.start[i] = acc; acc += sizes4[i]; }
    J.start[7] = acc;
    split_all<<<(unsigned)((acc + 255) / 256), 256>>>(J);

    // fused Q/K/V projections (z selects weight set), fp32 out
    gemm_bf3<<<dim3(2, 64, 3), 256, G_TOT>>>(
        xh, xl, wqh, wql, wkh, wkl, wvh, wvl, wq_b, wk_b, wv_b,
        q, k, v, (__nv_bfloat16*)0, (__nv_bfloat16*)0, D_MODEL, D_MODEL, 0, 0);

    // tensor-core RBF attention -> bf16 hi/lo
    attn_mma<<<dim3(SEQ / 128, BATCH * HEADS), 128, ASM_TOT>>>(q, k, v, atth, attl);

    // output projection (fp32) + residual LN1 (emits fp32 + bf16 pair)
    gemm_bf3<<<dim3(2, 64, 1), 256, G_TOT>>>(
        atth, attl, woh, wol, woh, wol, woh, wol, wo_b, wo_b, wo_b,
        tmp, tmp, tmp, (__nv_bfloat16*)0, (__nv_bfloat16*)0, D_MODEL, D_MODEL, 0, 0);
    residual_ln<<<TOK / 8, 256>>>(x, tmp, ln1_g, ln1_b, out1, o1h, o1l, 1);

    // FFN1 (relu, bf16-pair out) -> FFN2 (fp32) -> residual LN2
    gemm_bf3<<<dim3(8, 64, 1), 256, G_TOT>>>(
        o1h, o1l, f1h, f1l, f1h, f1l, f1h, f1l, ffn1_b, ffn1_b, ffn1_b,
        tmp, tmp, tmp, ffhh, ffhl, D_MODEL, DFF, 1, 1);
    gemm_bf3<<<dim3(2, 64, 1), 256, G_TOT>>>(
        ffhh, ffhl, f2h, f2l, f2h, f2l, f2h, f2l, ffn2_b, ffn2_b, ffn2_b,
        tmp, tmp, tmp, (__nv_bfloat16*)0, (__nv_bfloat16*)0, DFF, D_MODEL, 0, 0);
    residual_ln<<<TOK / 8, 256>>>(out1, tmp, ln2_g, ln2_b, (float*)d_out,
                                  (__nv_bfloat16*)0, (__nv_bfloat16*)0, 0);
}

// round 11
// speedup vs baseline: 3.0705x; 1.0993x over previous
#include <cuda_runtime.h>
#include <cuda_bf16.h>
#include <cstdint>
#include <math.h>

#define D_MODEL 256
#define BATCH   4
#define SEQ     2048
#define HEADS   8
#define DEPTH   32
#define DFF     1024
#define TOK     (BATCH*SEQ)   // 8192
#define EPS     1e-6f

// ---------------- mma.sync / cp.async helpers ------------------------------
__device__ __forceinline__ uint32_t smem_u32(const void* p) {
    uint32_t a;
    asm("{ .reg .u64 t; cvta.to.shared.u64 t, %1; cvt.u32.u64 %0, t; }"
        : "=r"(a) : "l"(p));
    return a;
}
__device__ __forceinline__ void ldsm_x4(uint32_t* r, uint32_t addr) {
    asm volatile("ldmatrix.sync.aligned.m8n8.x4.shared.b16 {%0,%1,%2,%3}, [%4];"
        : "=r"(r[0]), "=r"(r[1]), "=r"(r[2]), "=r"(r[3]) : "r"(addr));
}
__device__ __forceinline__ void ldsm_x4t(uint32_t* r, uint32_t addr) {
    asm volatile("ldmatrix.sync.aligned.m8n8.x4.trans.shared.b16 {%0,%1,%2,%3}, [%4];"
        : "=r"(r[0]), "=r"(r[1]), "=r"(r[2]), "=r"(r[3]) : "r"(addr));
}
__device__ __forceinline__ void mma_bf16(float* d, const uint32_t* a,
                                         uint32_t b0, uint32_t b1) {
    asm volatile("mma.sync.aligned.m16n8k16.row.col.f32.bf16.bf16.f32 "
        "{%0,%1,%2,%3}, {%4,%5,%6,%7}, {%8,%9}, {%0,%1,%2,%3};"
        : "+f"(d[0]), "+f"(d[1]), "+f"(d[2]), "+f"(d[3])
        : "r"(a[0]), "r"(a[1]), "r"(a[2]), "r"(a[3]), "r"(b0), "r"(b1));
}
__device__ __forceinline__ uint32_t pkbf(__nv_bfloat16 a, __nv_bfloat16 b) {
    return (uint32_t)__bfloat16_as_ushort(a) | ((uint32_t)__bfloat16_as_ushort(b) << 16);
}
__device__ __forceinline__ void cpa16(uint32_t dst, const void* src) {
    asm volatile("cp.async.cg.shared.global [%0], [%1], 16;" :: "r"(dst), "l"(src));
}
__device__ __forceinline__ void cpa4(uint32_t dst, const void* src) {
    asm volatile("cp.async.ca.shared.global [%0], [%1], 4;" :: "r"(dst), "l"(src));
}
#define CP_COMMIT() asm volatile("cp.async.commit_group;" ::: "memory")

// ---------------- scratch ---------------------------------------------------
__device__ float g_tmp [TOK*D_MODEL];
__device__ float g_out1[TOK*D_MODEL];
__device__ float g_qn[TOK*HEADS], g_kn[TOK*HEADS], g_vn[TOK*HEADS];
__device__ __nv_bfloat16 g_qbh[TOK*D_MODEL], g_qbl[TOK*D_MODEL];
__device__ __nv_bfloat16 g_kbh[TOK*D_MODEL], g_kbl[TOK*D_MODEL];
__device__ __nv_bfloat16 g_vbh[TOK*D_MODEL], g_vbl[TOK*D_MODEL];
__device__ __nv_bfloat16 g_xh  [TOK*D_MODEL], g_xl  [TOK*D_MODEL];
__device__ __nv_bfloat16 g_atth[TOK*D_MODEL], g_attl[TOK*D_MODEL];
__device__ __nv_bfloat16 g_o1h [TOK*D_MODEL], g_o1l [TOK*D_MODEL];
__device__ __nv_bfloat16 g_ffhh[TOK*DFF],     g_ffhl[TOK*DFF];
__device__ __nv_bfloat16 g_wqh[D_MODEL*D_MODEL], g_wql[D_MODEL*D_MODEL];
__device__ __nv_bfloat16 g_wkh[D_MODEL*D_MODEL], g_wkl[D_MODEL*D_MODEL];
__device__ __nv_bfloat16 g_wvh[D_MODEL*D_MODEL], g_wvl[D_MODEL*D_MODEL];
__device__ __nv_bfloat16 g_woh[D_MODEL*D_MODEL], g_wol[D_MODEL*D_MODEL];
__device__ __nv_bfloat16 g_f1h[D_MODEL*DFF],     g_f1l[D_MODEL*DFF];
__device__ __nv_bfloat16 g_f2h[DFF*D_MODEL],     g_f2l[DFF*D_MODEL];

// ---------------- combined hi/lo split (weights + x), one launch ------------
struct SplitJobs {
    const float*   src[7];
    __nv_bfloat16* h[7];
    __nv_bfloat16* l[7];
    long long      start[8];
};
__global__ __launch_bounds__(256) void split_all(SplitJobs J)
{
    long long c = (long long)blockIdx.x * 256 + threadIdx.x;
    if (c >= J.start[7]) return;
    int s = 0;
    #pragma unroll
    for (int i = 1; i < 7; i++) if (c >= J.start[i]) s = i;
    long long i4 = c - J.start[s];
    float4 f = ((const float4*)J.src[s])[i4];
    __nv_bfloat16 h0 = __float2bfloat16(f.x), h1 = __float2bfloat16(f.y);
    __nv_bfloat16 h2 = __float2bfloat16(f.z), h3 = __float2bfloat16(f.w);
    __nv_bfloat16 l0 = __float2bfloat16(f.x - __bfloat162float(h0));
    __nv_bfloat16 l1 = __float2bfloat16(f.y - __bfloat162float(h1));
    __nv_bfloat16 l2 = __float2bfloat16(f.z - __bfloat162float(h2));
    __nv_bfloat16 l3 = __float2bfloat16(f.w - __bfloat162float(h3));
    ((uint2*)J.h[s])[i4] = make_uint2(pkbf(h0, h1), pkbf(h2, h3));
    ((uint2*)J.l[s])[i4] = make_uint2(pkbf(l0, l1), pkbf(l2, l3));
}

// ---------------- bf16x3 GEMM, 64x128 tiles, 3-stage cp.async --------------
// mode 0: fp32 out (+bias,+relu). mode 1: bf16 hi/lo out.
// mode 2: bf16 hi/lo out + per-head(-0.5*||row||^2) norms (BN=128 -> warp=head).
struct GemmPtrs {
    const __nv_bfloat16 *bh[3], *bl[3];
    const float* bias[3];
    float* cf[3];
    __nv_bfloat16 *ch[3], *cl[3];
    float* nrm[3];
};
#define GS_AH 0
#define GS_AL 5120
#define GS_BH 10240
#define GS_BL 18944
#define GSTG  27648
#define G_TOT (3*GSTG)

__global__ __launch_bounds__(256) void gemm_bf3(
    const __nv_bfloat16* __restrict__ Ah, const __nv_bfloat16* __restrict__ Al,
    GemmPtrs P, int K, int Ntot, int relu, int mode)
{
    extern __shared__ __align__(16) char sm[];
    uint32_t smb = smem_u32(sm);

    int tid  = threadIdx.x;
    int lane = tid & 31;
    int wid  = tid >> 5;
    int wm   = wid & 1;       // 0..1 -> 32-row chunk
    int wn   = wid >> 1;      // 0..3 -> 32-col chunk

    int z = blockIdx.z;
    const __nv_bfloat16* Bh = P.bh[z];
    const __nv_bfloat16* Bl = P.bl[z];
    const float* bias = P.bias[z];

    int row0 = blockIdx.y * 64;
    int col0 = blockIdx.x * 128;

    float acc[2][4][4];
    #pragma unroll
    for (int a = 0; a < 2; a++)
        #pragma unroll
        for (int b = 0; b < 4; b++)
            #pragma unroll
            for (int c = 0; c < 4; c++) acc[a][b][c] = 0.f;

    int T = K >> 5;

    #define LOAD_STAGE(s, k0) do {                                             \
        uint32_t _b = smb + (s) * GSTG;                                        \
        {                                                                      \
            int r = tid >> 2, c8 = (tid & 3) << 3;                             \
            size_t ao = (size_t)(row0 + r) * K + (k0) + c8;                    \
            cpa16(_b + GS_AH + r * 80 + c8 * 2, Ah + ao);                      \
            cpa16(_b + GS_AL + r * 80 + c8 * 2, Al + ao);                      \
        }                                                                      \
        _Pragma("unroll")                                                      \
        for (int it = 0; it < 2; it++) {                                       \
            int rr = (tid >> 4) + it * 16;                                     \
            int c8 = (tid & 15) << 3;                                          \
            size_t bo = (size_t)((k0) + rr) * Ntot + col0 + c8;                \
            cpa16(_b + GS_BH + rr * 272 + c8 * 2, Bh + bo);                    \
            cpa16(_b + GS_BL + rr * 272 + c8 * 2, Bl + bo);                    \
        }                                                                      \
        CP_COMMIT();                                                           \
    } while (0)

    LOAD_STAGE(0, 0);
    LOAD_STAGE(1, 32);

    int sidx = 0;
    for (int t = 0; t < T; t++) {
        if (t + 2 < T) {
            int s2 = (t + 2) % 3;
            LOAD_STAGE(s2, (t + 2) * 32);
            asm volatile("cp.async.wait_group 2;" ::: "memory");
        } else if (t + 1 < T) {
            asm volatile("cp.async.wait_group 1;" ::: "memory");
        } else {
            asm volatile("cp.async.wait_group 0;" ::: "memory");
        }
        __syncthreads();

        uint32_t sb = smb + sidx * GSTG;
        #pragma unroll
        for (int kk = 0; kk < 2; kk++) {
            uint32_t ah[2][4], al[2][4], bh[2][4], bl[2][4];
            int ar = lane & 15;
            int ac = kk * 16 + (lane >> 4) * 8;
            #pragma unroll
            for (int mt = 0; mt < 2; mt++) {
                uint32_t ao = sb + (wm * 32 + mt * 16 + ar) * 80 + ac * 2;
                ldsm_x4(ah[mt], ao + GS_AH);
                ldsm_x4(al[mt], ao + GS_AL);
            }
            int br = kk * 16 + (lane & 15);
            int bc = wn * 32 + (lane >> 4) * 8;
            #pragma unroll
            for (int nt = 0; nt < 2; nt++) {
                uint32_t bo = sb + br * 272 + (bc + nt * 16) * 2;
                ldsm_x4t(bh[nt], bo + GS_BH);
                ldsm_x4t(bl[nt], bo + GS_BL);
            }
            #pragma unroll
            for (int mt = 0; mt < 2; mt++)
                #pragma unroll
                for (int nt = 0; nt < 2; nt++) {
                    mma_bf16(acc[mt][2*nt],   ah[mt], bh[nt][0], bh[nt][1]);
                    mma_bf16(acc[mt][2*nt+1], ah[mt], bh[nt][2], bh[nt][3]);
                    mma_bf16(acc[mt][2*nt],   al[mt], bh[nt][0], bh[nt][1]);
                    mma_bf16(acc[mt][2*nt+1], al[mt], bh[nt][2], bh[nt][3]);
                    mma_bf16(acc[mt][2*nt],   ah[mt], bl[nt][0], bl[nt][1]);
                    mma_bf16(acc[mt][2*nt+1], ah[mt], bl[nt][2], bl[nt][3]);
                }
        }
        __syncthreads();
        sidx = (sidx + 1) % 3;
    }

    float* Cf = P.cf[z];
    __nv_bfloat16* Ch = P.ch[z];
    __nv_bfloat16* Cl = P.cl[z];
    int rb = row0 + wm * 32 + (lane >> 2);
    int cb = col0 + wn * 32 + (lane & 3) * 2;
    float s2n[2][2] = {{0.f, 0.f}, {0.f, 0.f}};   // [mt][rowhalf]
    #pragma unroll
    for (int mt = 0; mt < 2; mt++) {
        #pragma unroll
        for (int nt8 = 0; nt8 < 4; nt8++) {
            int gc = cb + nt8 * 8;
            float2 bb = *(const float2*)&bias[gc];
            float2 o0, o1;
            o0.x = acc[mt][nt8][0] + bb.x;
            o0.y = acc[mt][nt8][1] + bb.y;
            o1.x = acc[mt][nt8][2] + bb.x;
            o1.y = acc[mt][nt8][3] + bb.y;
            if (relu) {
                o0.x = fmaxf(o0.x, 0.f); o0.y = fmaxf(o0.y, 0.f);
                o1.x = fmaxf(o1.x, 0.f); o1.y = fmaxf(o1.y, 0.f);
            }
            int gr = rb + mt * 16;
            if (mode == 0) {
                *(float2*)&Cf[(size_t)gr * Ntot + gc] = o0;
                *(float2*)&Cf[(size_t)(gr + 8) * Ntot + gc] = o1;
            } else {
                __nv_bfloat16 h0 = __float2bfloat16(o0.x), h1 = __float2bfloat16(o0.y);
                __nv_bfloat16 h2 = __float2bfloat16(o1.x), h3 = __float2bfloat16(o1.y);
                uint32_t lw0 = pkbf(__float2bfloat16(o0.x - __bfloat162float(h0)),
                                    __float2bfloat16(o0.y - __bfloat162float(h1)));
                uint32_t lw1 = pkbf(__float2bfloat16(o1.x - __bfloat162float(h2)),
                                    __float2bfloat16(o1.y - __bfloat162float(h3)));
                *(uint32_t*)&Ch[(size_t)gr * Ntot + gc] = pkbf(h0, h1);
                *(uint32_t*)&Cl[(size_t)gr * Ntot + gc] = lw0;
                *(uint32_t*)&Ch[(size_t)(gr + 8) * Ntot + gc] = pkbf(h2, h3);
                *(uint32_t*)&Cl[(size_t)(gr + 8) * Ntot + gc] = lw1;
                if (mode == 2) {
                    s2n[mt][0] += o0.x * o0.x + o0.y * o0.y;
                    s2n[mt][1] += o1.x * o1.x + o1.y * o1.y;
                }
            }
        }
    }
    if (mode == 2) {
        float* Nrm = P.nrm[z];
        int head = blockIdx.x * 4 + wn;
        #pragma unroll
        for (int mt = 0; mt < 2; mt++)
            #pragma unroll
            for (int rh = 0; rh < 2; rh++) {
                float s = s2n[mt][rh];
                s += __shfl_xor_sync(0xffffffffu, s, 1);
                s += __shfl_xor_sync(0xffffffffu, s, 2);
                if ((lane & 3) == 0) {
                    int gr = rb + mt * 16 + rh * 8;
                    Nrm[(size_t)gr * HEADS + head] = -0.5f * s;
                }
            }
    }
}

// ---------------- tensor-core RBF flash attention ---------------------------
// Consumes pre-split bf16 Q/K/V + precomputed fp32 norms. cp.async double-
// buffered K/V stages. Scores bf16x3; PV single-term PhVh.
#define AT_QH 0
#define AT_QL 10240
#define AT_Q2 20480
#define AT_ST 20992
#define AT_KH 0
#define AT_KL 5120
#define AT_VH 10240
#define AT_K2 15360
#define AT_STG 15616
#define AT_PH 52224
#define AT_TOT 70656

__global__ __launch_bounds__(128) void attn_mma(
    const __nv_bfloat16* __restrict__ Qbh, const __nv_bfloat16* __restrict__ Qbl,
    const __nv_bfloat16* __restrict__ Kbh, const __nv_bfloat16* __restrict__ Kbl,
    const __nv_bfloat16* __restrict__ Vbh,
    const float* __restrict__ Qn, const float* __restrict__ Kn,
    __nv_bfloat16* __restrict__ Oh, __nv_bfloat16* __restrict__ Ol)
{
    extern __shared__ __align__(16) char sm[];
    uint32_t smb = smem_u32(sm);
    float* q2s = (float*)(sm + AT_Q2);
    __nv_bfloat16* Ph = (__nv_bfloat16*)(sm + AT_PH);

    int tid = threadIdx.x, lane = tid & 31, wid = tid >> 5;
    int bh = blockIdx.y, b = bh >> 3, h = bh & 7;
    int q0 = blockIdx.x * 128;

    #define LOADKV(kt, s) do {                                                 \
        uint32_t _b = smb + AT_ST + (s) * AT_STG;                              \
        _Pragma("unroll")                                                      \
        for (int it = 0; it < 2; it++) {                                       \
            int idx = tid + it * 128;                                          \
            int r = idx >> 2, c = idx & 3;                                     \
            size_t go = (size_t)(b*SEQ + (kt)*64 + r)*D_MODEL + h*DEPTH + c*8; \
            cpa16(_b + AT_KH + r * 80 + c * 16, Kbh + go);                     \
            cpa16(_b + AT_KL + r * 80 + c * 16, Kbl + go);                     \
            cpa16(_b + AT_VH + r * 80 + c * 16, Vbh + go);                     \
        }                                                                      \
        if (tid < 64)                                                          \
            cpa4(_b + AT_K2 + tid * 4,                                         \
                 Kn + (size_t)(b*SEQ + (kt)*64 + tid) * HEADS + h);            \
        CP_COMMIT();                                                           \
    } while (0)

    // prefetch KV tile 0, then Q
    LOADKV(0, 0);
    #pragma unroll
    for (int it = 0; it < 4; it++) {
        int idx = tid + it * 128;
        int r = idx >> 2, c = idx & 3;
        size_t go = (size_t)(b*SEQ + q0 + r)*D_MODEL + h*DEPTH + c*8;
        cpa16(smb + AT_QH + r * 80 + c * 16, Qbh + go);
        cpa16(smb + AT_QL + r * 80 + c * 16, Qbl + go);
    }
    CP_COMMIT();
    q2s[tid] = Qn[(size_t)(b*SEQ + q0 + tid) * HEADS + h];
    asm volatile("cp.async.wait_group 0;" ::: "memory");
    __syncthreads();

    // Q fragments (once)
    uint32_t qah[2][2][4], qal[2][2][4];
    {
        int ar = lane & 15, ag = (lane >> 4) * 8;
        #pragma unroll
        for (int mt = 0; mt < 2; mt++)
            #pragma unroll
            for (int kc = 0; kc < 2; kc++) {
                uint32_t off = smb + (wid*32 + mt*16 + ar) * 80 + (kc*16 + ag) * 2;
                ldsm_x4(qah[mt][kc], off + AT_QH);
                ldsm_x4(qal[mt][kc], off + AT_QL);
            }
    }
    float q2r[2][2];
    #pragma unroll
    for (int mt = 0; mt < 2; mt++)
        #pragma unroll
        for (int rh = 0; rh < 2; rh++)
            q2r[mt][rh] = q2s[wid*32 + mt*16 + rh*8 + (lane >> 2)];

    float oacc[2][4][4];
    #pragma unroll
    for (int a = 0; a < 2; a++)
        #pragma unroll
        for (int c = 0; c < 4; c++)
            #pragma unroll
            for (int d = 0; d < 4; d++) oacc[a][c][d] = 0.f;
    float dpart[2][2] = {{0.f, 0.f}, {0.f, 0.f}};

    for (int kt = 0; kt < SEQ / 64; kt++) {
        if (kt + 1 < SEQ / 64) {
            LOADKV(kt + 1, (kt + 1) & 1);
            asm volatile("cp.async.wait_group 1;" ::: "memory");
        } else {
            asm volatile("cp.async.wait_group 0;" ::: "memory");
        }
        __syncthreads();

        uint32_t kf = smb + AT_ST + (kt & 1) * AT_STG;
        float* k2s = (float*)(sm + AT_ST + (kt & 1) * AT_STG + AT_K2);

        // ---- phase 1: scores -> p
        {
            int ar = lane & 15, ag = (lane >> 4) * 8;
            #pragma unroll
            for (int ntp = 0; ntp < 4; ntp++) {
                uint32_t kbh[2][4], kbl[2][4];
                #pragma unroll
                for (int kc = 0; kc < 2; kc++) {
                    uint32_t off = kf + (ntp*16 + ar) * 80 + (kc*16 + ag) * 2;
                    ldsm_x4(kbh[kc], off + AT_KH);
                    ldsm_x4(kbl[kc], off + AT_KL);
                }
                #pragma unroll
                for (int mt = 0; mt < 2; mt++)
                    #pragma unroll
                    for (int nt = 0; nt < 2; nt++) {
                        float s[4] = {0.f, 0.f, 0.f, 0.f};
                        #pragma unroll
                        for (int kc = 0; kc < 2; kc++) {
                            mma_bf16(s, qah[mt][kc], kbh[kc][nt], kbh[kc][nt+2]);
                            mma_bf16(s, qal[mt][kc], kbh[kc][nt], kbh[kc][nt+2]);
                            mma_bf16(s, qah[mt][kc], kbl[kc][nt], kbl[kc][nt+2]);
                        }
                        int cbase = ntp*16 + nt*8 + (lane & 3)*2;
                        float k2c0 = k2s[cbase], k2c1 = k2s[cbase + 1];
                        #pragma unroll
                        for (int rh = 0; rh < 2; rh++) {
                            float w0 = __expf(s[rh*2+0] + q2r[mt][rh] + k2c0);
                            float w1 = __expf(s[rh*2+1] + q2r[mt][rh] + k2c1);
                            float p0 = __expf(w0);
                            float p1 = __expf(w1);
                            dpart[mt][rh] += p0 + p1;
                            __nv_bfloat162 hp = __float22bfloat162_rn(make_float2(p0, p1));
                            int prow = wid*32 + mt*16 + rh*8 + (lane >> 2);
                            *(uint32_t*)&Ph[prow*72 + cbase] = *(uint32_t*)&hp;
                        }
                    }
            }
        }
        __syncwarp();

        // ---- phase 2: out += Ph @ Vh
        {
            int ar = lane & 15, ag = (lane >> 4) * 8;
            #pragma unroll
            for (int kc = 0; kc < 4; kc++) {
                uint32_t pah[2][4], vbh[2][4];
                #pragma unroll
                for (int mt = 0; mt < 2; mt++)
                    ldsm_x4(pah[mt],
                        smb + AT_PH + ((wid*32 + mt*16 + ar)*72 + kc*16 + ag) * 2);
                #pragma unroll
                for (int ntp = 0; ntp < 2; ntp++)
                    ldsm_x4t(vbh[ntp],
                        kf + AT_VH + (kc*16 + ar) * 80 + (ntp*16 + ag) * 2);
                #pragma unroll
                for (int mt = 0; mt < 2; mt++)
                    #pragma unroll
                    for (int ntp = 0; ntp < 2; ntp++)
                        #pragma unroll
                        for (int nt = 0; nt < 2; nt++)
                            mma_bf16(oacc[mt][ntp*2 + nt], pah[mt],
                                     vbh[ntp][2*nt], vbh[ntp][2*nt+1]);
            }
        }
        __syncthreads();
    }

    // ---- epilogue: normalize + store bf16 hi/lo
    #pragma unroll
    for (int mt = 0; mt < 2; mt++)
        #pragma unroll
        for (int rh = 0; rh < 2; rh++) {
            float den = dpart[mt][rh];
            den += __shfl_xor_sync(0xffffffffu, den, 1);
            den += __shfl_xor_sync(0xffffffffu, den, 2);
            float inv = 1.f / den;
            int row = q0 + wid*32 + mt*16 + rh*8 + (lane >> 2);
            size_t obase = (size_t)(b*SEQ + row)*D_MODEL + h*DEPTH + (lane & 3)*2;
            #pragma unroll
            for (int nt4 = 0; nt4 < 4; nt4++) {
                float ox = oacc[mt][nt4][rh*2+0] * inv;
                float oy = oacc[mt][nt4][rh*2+1] * inv;
                __nv_bfloat16 h0 = __float2bfloat16(ox), h1 = __float2bfloat16(oy);
                uint32_t hw = pkbf(h0, h1);
                uint32_t lw = pkbf(__float2bfloat16(ox - __bfloat162float(h0)),
                                   __float2bfloat16(oy - __bfloat162float(h1)));
                *(uint32_t*)(Oh + obase + nt4*8) = hw;
                *(uint32_t*)(Ol + obase + nt4*8) = lw;
            }
        }
}

// ---------------- fused residual + LayerNorm (warp per row) -----------------
__global__ __launch_bounds__(256) void residual_ln(
    const float* __restrict__ X, const float* __restrict__ Y,
    const float* __restrict__ g, const float* __restrict__ b,
    float* __restrict__ outf,
    __nv_bfloat16* __restrict__ outh, __nv_bfloat16* __restrict__ outl,
    int do_split)
{
    int lane = threadIdx.x & 31, w = threadIdx.x >> 5;
    int row  = blockIdx.x * 8 + w;
    size_t base = (size_t)row * D_MODEL;
    int c0 = lane * 4, c1 = 128 + lane * 4;

    float4 x0 = *(const float4*)(X + base + c0);
    float4 x1 = *(const float4*)(X + base + c1);
    float4 y0 = *(const float4*)(Y + base + c0);
    float4 y1 = *(const float4*)(Y + base + c1);
    float4 v0 = make_float4(x0.x+y0.x, x0.y+y0.y, x0.z+y0.z, x0.w+y0.w);
    float4 v1 = make_float4(x1.x+y1.x, x1.y+y1.y, x1.z+y1.z, x1.w+y1.w);

    float s = v0.x+v0.y+v0.z+v0.w + v1.x+v1.y+v1.z+v1.w;
    #pragma unroll
    for (int o = 16; o > 0; o >>= 1) s += __shfl_xor_sync(0xffffffffu, s, o);
    float mean = s * (1.f / D_MODEL);

    float4 d0 = make_float4(v0.x-mean, v0.y-mean, v0.z-mean, v0.w-mean);
    float4 d1 = make_float4(v1.x-mean, v1.y-mean, v1.z-mean, v1.w-mean);
    float s2 = d0.x*d0.x+d0.y*d0.y+d0.z*d0.z+d0.w*d0.w
             + d1.x*d1.x+d1.y*d1.y+d1.z*d1.z+d1.w*d1.w;
    #pragma unroll
    for (int o = 16; o > 0; o >>= 1) s2 += __shfl_xor_sync(0xffffffffu, s2, o);
    float rstd = rsqrtf(s2 * (1.f / D_MODEL) + EPS);

    float4 g0 = *(const float4*)(g + c0), g1 = *(const float4*)(g + c1);
    float4 b0 = *(const float4*)(b + c0), b1 = *(const float4*)(b + c1);
    float4 o0, o1;
    o0.x = d0.x*rstd*g0.x + b0.x; o0.y = d0.y*rstd*g0.y + b0.y;
    o0.z = d0.z*rstd*g0.z + b0.z; o0.w = d0.w*rstd*g0.w + b0.w;
    o1.x = d1.x*rstd*g1.x + b1.x; o1.y = d1.y*rstd*g1.y + b1.y;
    o1.z = d1.z*rstd*g1.z + b1.z; o1.w = d1.w*rstd*g1.w + b1.w;
    *(float4*)(outf + base + c0) = o0;
    *(float4*)(outf + base + c1) = o1;

    if (do_split) {
        __nv_bfloat16 h0 = __float2bfloat16(o0.x), h1 = __float2bfloat16(o0.y);
        __nv_bfloat16 h2 = __float2bfloat16(o0.z), h3 = __float2bfloat16(o0.w);
        __nv_bfloat16 h4 = __float2bfloat16(o1.x), h5 = __float2bfloat16(o1.y);
        __nv_bfloat16 h6 = __float2bfloat16(o1.z), h7 = __float2bfloat16(o1.w);
        *(uint2*)(outh + base + c0) = make_uint2(pkbf(h0,h1), pkbf(h2,h3));
        *(uint2*)(outh + base + c1) = make_uint2(pkbf(h4,h5), pkbf(h6,h7));
        *(uint2*)(outl + base + c0) = make_uint2(
            pkbf(__float2bfloat16(o0.x-__bfloat162float(h0)),
                 __float2bfloat16(o0.y-__bfloat162float(h1))),
            pkbf(__float2bfloat16(o0.z-__bfloat162float(h2)),
                 __float2bfloat16(o0.w-__bfloat162float(h3))));
        *(uint2*)(outl + base + c1) = make_uint2(
            pkbf(__float2bfloat16(o1.x-__bfloat162float(h4)),
                 __float2bfloat16(o1.y-__bfloat162float(h5))),
            pkbf(__float2bfloat16(o1.z-__bfloat162float(h6)),
                 __float2bfloat16(o1.w-__bfloat162float(h7))));
    }
}

// ---------------- launch -----------------------------------------------------
extern "C" void kernel_launch(void* const* d_in, const int* in_sizes, int n_in,
                              void* d_out, int out_size)
{
    const float* x      = (const float*)d_in[0];
    const float* wq_w   = (const float*)d_in[1];
    const float* wq_b   = (const float*)d_in[2];
    const float* wk_w   = (const float*)d_in[3];
    const float* wk_b   = (const float*)d_in[4];
    const float* wv_w   = (const float*)d_in[5];
    const float* wv_b   = (const float*)d_in[6];
    const float* wo_w   = (const float*)d_in[7];
    const float* wo_b   = (const float*)d_in[8];
    const float* ffn1_w = (const float*)d_in[9];
    const float* ffn1_b = (const float*)d_in[10];
    const float* ffn2_w = (const float*)d_in[11];
    const float* ffn2_b = (const float*)d_in[12];
    const float* ln1_g  = (const float*)d_in[13];
    const float* ln1_b  = (const float*)d_in[14];
    const float* ln2_g  = (const float*)d_in[15];
    const float* ln2_b  = (const float*)d_in[16];

    float *tmp, *out1, *qn, *kn, *vn;
    cudaGetSymbolAddress((void**)&tmp,  g_tmp);
    cudaGetSymbolAddress((void**)&out1, g_out1);
    cudaGetSymbolAddress((void**)&qn,   g_qn);
    cudaGetSymbolAddress((void**)&kn,   g_kn);
    cudaGetSymbolAddress((void**)&vn,   g_vn);

    __nv_bfloat16 *qbh, *qbl, *kbh, *kbl, *vbh, *vbl;
    cudaGetSymbolAddress((void**)&qbh, g_qbh); cudaGetSymbolAddress((void**)&qbl, g_qbl);
    cudaGetSymbolAddress((void**)&kbh, g_kbh); cudaGetSymbolAddress((void**)&kbl, g_kbl);
    cudaGetSymbolAddress((void**)&vbh, g_vbh); cudaGetSymbolAddress((void**)&vbl, g_vbl);

    __nv_bfloat16 *xh, *xl, *atth, *attl, *o1h, *o1l, *ffhh, *ffhl;
    cudaGetSymbolAddress((void**)&xh,   g_xh);   cudaGetSymbolAddress((void**)&xl,   g_xl);
    cudaGetSymbolAddress((void**)&atth, g_atth); cudaGetSymbolAddress((void**)&attl, g_attl);
    cudaGetSymbolAddress((void**)&o1h,  g_o1h);  cudaGetSymbolAddress((void**)&o1l,  g_o1l);
    cudaGetSymbolAddress((void**)&ffhh, g_ffhh); cudaGetSymbolAddress((void**)&ffhl, g_ffhl);

    __nv_bfloat16 *wqh, *wql, *wkh, *wkl, *wvh, *wvl, *woh, *wol, *f1h, *f1l, *f2h, *f2l;
    cudaGetSymbolAddress((void**)&wqh, g_wqh); cudaGetSymbolAddress((void**)&wql, g_wql);
    cudaGetSymbolAddress((void**)&wkh, g_wkh); cudaGetSymbolAddress((void**)&wkl, g_wkl);
    cudaGetSymbolAddress((void**)&wvh, g_wvh); cudaGetSymbolAddress((void**)&wvl, g_wvl);
    cudaGetSymbolAddress((void**)&woh, g_woh); cudaGetSymbolAddress((void**)&wol, g_wol);
    cudaGetSymbolAddress((void**)&f1h, g_f1h); cudaGetSymbolAddress((void**)&f1l, g_f1l);
    cudaGetSymbolAddress((void**)&f2h, g_f2h); cudaGetSymbolAddress((void**)&f2l, g_f2l);

    cudaFuncSetAttribute(attn_mma, cudaFuncAttributeMaxDynamicSharedMemorySize, AT_TOT);
    cudaFuncSetAttribute(gemm_bf3, cudaFuncAttributeMaxDynamicSharedMemorySize, G_TOT);

    // one combined split launch: 6 weights + x
    SplitJobs J;
    const float* srcs[7] = {wq_w, wk_w, wv_w, wo_w, ffn1_w, ffn2_w, x};
    __nv_bfloat16* hs[7] = {wqh, wkh, wvh, woh, f1h, f2h, xh};
    __nv_bfloat16* ls[7] = {wql, wkl, wvl, wol, f1l, f2l, xl};
    long long sizes4[7] = {65536/4, 65536/4, 65536/4, 65536/4,
                           262144/4, 262144/4, (long long)TOK*D_MODEL/4};
    long long acc = 0;
    for (int i = 0; i < 7; i++) { J.src[i] = srcs[i]; J.h[i] = hs[i]; J.l[i] = ls[i];
                                  J.start[i] = acc; acc += sizes4[i]; }
    J.start[7] = acc;
    split_all<<<(unsigned)((acc + 255) / 256), 256>>>(J);

    // QKV projections: bf16 hi/lo out + head norms (mode 2)
    {
        GemmPtrs P = {};
        P.bh[0] = wqh; P.bl[0] = wql; P.bias[0] = wq_b;
        P.bh[1] = wkh; P.bl[1] = wkl; P.bias[1] = wk_b;
        P.bh[2] = wvh; P.bl[2] = wvl; P.bias[2] = wv_b;
        P.ch[0] = qbh; P.cl[0] = qbl; P.nrm[0] = qn;
        P.ch[1] = kbh; P.cl[1] = kbl; P.nrm[1] = kn;
        P.ch[2] = vbh; P.cl[2] = vbl; P.nrm[2] = vn;
        gemm_bf3<<<dim3(2, 128, 3), 256, G_TOT>>>(xh, xl, P, D_MODEL, D_MODEL, 0, 2);
    }

    // tensor-core RBF attention
    attn_mma<<<dim3(SEQ / 128, BATCH * HEADS), 128, AT_TOT>>>(
        qbh, qbl, kbh, kbl, vbh, qn, kn, atth, attl);

    // output projection (fp32) + residual LN1
    {
        GemmPtrs P = {};
        P.bh[0] = woh; P.bl[0] = wol; P.bias[0] = wo_b; P.cf[0] = tmp;
        gemm_bf3<<<dim3(2, 128, 1), 256, G_TOT>>>(atth, attl, P, D_MODEL, D_MODEL, 0, 0);
    }
    residual_ln<<<TOK / 8, 256>>>(x, tmp, ln1_g, ln1_b, out1, o1h, o1l, 1);

    // FFN1 (relu, bf16 out) -> FFN2 (fp32) -> residual LN2
    {
        GemmPtrs P = {};
        P.bh[0] = f1h; P.bl[0] = f1l; P.bias[0] = ffn1_b;
        P.ch[0] = ffhh; P.cl[0] = ffhl;
        gemm_bf3<<<dim3(8, 128, 1), 256, G_TOT>>>(o1h, o1l, P, D_MODEL, DFF, 1, 1);
    }
    {
        GemmPtrs P = {};
        P.bh[0] = f2h; P.bl[0] = f2l; P.bias[0] = ffn2_b; P.cf[0] = tmp;
        gemm_bf3<<<dim3(2, 128, 1), 256, G_TOT>>>(ffhh, ffhl, P, DFF, D_MODEL, 0, 0);
    }
    residual_ln<<<TOK / 8, 256>>>(out1, tmp, ln2_g, ln2_b, (float*)d_out,
                                  (__nv_bfloat16*)0, (__nv_bfloat16*)0, 0);
}

// round 12
// speedup vs baseline: 3.1042x; 1.0110x over previous
#include <cuda_runtime.h>
#include <cuda_bf16.h>
#include <cstdint>
#include <math.h>

#define D_MODEL 256
#define BATCH   4
#define SEQ     2048
#define HEADS   8
#define DEPTH   32
#define DFF     1024
#define TOK     (BATCH*SEQ)   // 8192
#define EPS     1e-6f

// ---------------- mma.sync / cp.async helpers ------------------------------
__device__ __forceinline__ uint32_t smem_u32(const void* p) {
    uint32_t a;
    asm("{ .reg .u64 t; cvta.to.shared.u64 t, %1; cvt.u32.u64 %0, t; }"
        : "=r"(a) : "l"(p));
    return a;
}
__device__ __forceinline__ void ldsm_x4(uint32_t* r, uint32_t addr) {
    asm volatile("ldmatrix.sync.aligned.m8n8.x4.shared.b16 {%0,%1,%2,%3}, [%4];"
        : "=r"(r[0]), "=r"(r[1]), "=r"(r[2]), "=r"(r[3]) : "r"(addr));
}
__device__ __forceinline__ void ldsm_x4t(uint32_t* r, uint32_t addr) {
    asm volatile("ldmatrix.sync.aligned.m8n8.x4.trans.shared.b16 {%0,%1,%2,%3}, [%4];"
        : "=r"(r[0]), "=r"(r[1]), "=r"(r[2]), "=r"(r[3]) : "r"(addr));
}
__device__ __forceinline__ void mma_bf16(float* d, const uint32_t* a,
                                         uint32_t b0, uint32_t b1) {
    asm volatile("mma.sync.aligned.m16n8k16.row.col.f32.bf16.bf16.f32 "
        "{%0,%1,%2,%3}, {%4,%5,%6,%7}, {%8,%9}, {%0,%1,%2,%3};"
        : "+f"(d[0]), "+f"(d[1]), "+f"(d[2]), "+f"(d[3])
        : "r"(a[0]), "r"(a[1]), "r"(a[2]), "r"(a[3]), "r"(b0), "r"(b1));
}
__device__ __forceinline__ uint32_t pkbf(__nv_bfloat16 a, __nv_bfloat16 b) {
    return (uint32_t)__bfloat16_as_ushort(a) | ((uint32_t)__bfloat16_as_ushort(b) << 16);
}
__device__ __forceinline__ void cpa16(uint32_t dst, const void* src) {
    asm volatile("cp.async.cg.shared.global [%0], [%1], 16;" :: "r"(dst), "l"(src));
}
__device__ __forceinline__ void cpa4(uint32_t dst, const void* src) {
    asm volatile("cp.async.ca.shared.global [%0], [%1], 4;" :: "r"(dst), "l"(src));
}
#define CP_COMMIT() asm volatile("cp.async.commit_group;" ::: "memory")

// ---------------- scratch ---------------------------------------------------
__device__ float g_tmp [TOK*D_MODEL];
__device__ float g_out1[TOK*D_MODEL];
__device__ float g_qn[TOK*HEADS], g_kn[TOK*HEADS], g_vn[TOK*HEADS];
__device__ __nv_bfloat16 g_qbh[TOK*D_MODEL], g_qbl[TOK*D_MODEL];
__device__ __nv_bfloat16 g_kbh[TOK*D_MODEL], g_kbl[TOK*D_MODEL];
__device__ __nv_bfloat16 g_vbh[TOK*D_MODEL], g_vbl[TOK*D_MODEL];
__device__ __nv_bfloat16 g_xh  [TOK*D_MODEL], g_xl  [TOK*D_MODEL];
__device__ __nv_bfloat16 g_atth[TOK*D_MODEL], g_attl[TOK*D_MODEL];
__device__ __nv_bfloat16 g_o1h [TOK*D_MODEL], g_o1l [TOK*D_MODEL];
__device__ __nv_bfloat16 g_ffhh[TOK*DFF],     g_ffhl[TOK*DFF];
__device__ __nv_bfloat16 g_wqh[D_MODEL*D_MODEL], g_wql[D_MODEL*D_MODEL];
__device__ __nv_bfloat16 g_wkh[D_MODEL*D_MODEL], g_wkl[D_MODEL*D_MODEL];
__device__ __nv_bfloat16 g_wvh[D_MODEL*D_MODEL], g_wvl[D_MODEL*D_MODEL];
__device__ __nv_bfloat16 g_woh[D_MODEL*D_MODEL], g_wol[D_MODEL*D_MODEL];
__device__ __nv_bfloat16 g_f1h[D_MODEL*DFF],     g_f1l[D_MODEL*DFF];
__device__ __nv_bfloat16 g_f2h[DFF*D_MODEL],     g_f2l[DFF*D_MODEL];

// ---------------- combined hi/lo split (weights + x), one launch ------------
struct SplitJobs {
    const float*   src[7];
    __nv_bfloat16* h[7];
    __nv_bfloat16* l[7];
    long long      start[8];
};
__global__ __launch_bounds__(256) void split_all(SplitJobs J)
{
    long long c = (long long)blockIdx.x * 256 + threadIdx.x;
    if (c >= J.start[7]) return;
    int s = 0;
    #pragma unroll
    for (int i = 1; i < 7; i++) if (c >= J.start[i]) s = i;
    long long i4 = c - J.start[s];
    float4 f = ((const float4*)J.src[s])[i4];
    __nv_bfloat16 h0 = __float2bfloat16(f.x), h1 = __float2bfloat16(f.y);
    __nv_bfloat16 h2 = __float2bfloat16(f.z), h3 = __float2bfloat16(f.w);
    __nv_bfloat16 l0 = __float2bfloat16(f.x - __bfloat162float(h0));
    __nv_bfloat16 l1 = __float2bfloat16(f.y - __bfloat162float(h1));
    __nv_bfloat16 l2 = __float2bfloat16(f.z - __bfloat162float(h2));
    __nv_bfloat16 l3 = __float2bfloat16(f.w - __bfloat162float(h3));
    ((uint2*)J.h[s])[i4] = make_uint2(pkbf(h0, h1), pkbf(h2, h3));
    ((uint2*)J.l[s])[i4] = make_uint2(pkbf(l0, l1), pkbf(l2, l3));
}

// ---------------- bf16x3 GEMM, 64x128 tiles, 2-stage cp.async --------------
// mode 0: fp32 out (+bias,+relu). mode 1: bf16 hi/lo out.
// mode 2: bf16 hi/lo out + per-head(-0.5*||row||^2) norms (BN=128 -> warp=head).
struct GemmPtrs {
    const __nv_bfloat16 *bh[3], *bl[3];
    const float* bias[3];
    float* cf[3];
    __nv_bfloat16 *ch[3], *cl[3];
    float* nrm[3];
};
#define GS_AH 0
#define GS_AL 5120
#define GS_BH 10240
#define GS_BL 18944
#define GSTG  27648
#define G_TOT (2*GSTG)

__global__ __launch_bounds__(256) void gemm_bf3(
    const __nv_bfloat16* __restrict__ Ah, const __nv_bfloat16* __restrict__ Al,
    GemmPtrs P, int K, int Ntot, int relu, int mode)
{
    extern __shared__ __align__(16) char sm[];
    uint32_t smb = smem_u32(sm);

    int tid  = threadIdx.x;
    int lane = tid & 31;
    int wid  = tid >> 5;
    int wm   = wid & 1;
    int wn   = wid >> 1;

    int z = blockIdx.z;
    const __nv_bfloat16* Bh = P.bh[z];
    const __nv_bfloat16* Bl = P.bl[z];
    const float* bias = P.bias[z];

    int row0 = blockIdx.y * 64;
    int col0 = blockIdx.x * 128;

    float acc[2][4][4];
    #pragma unroll
    for (int a = 0; a < 2; a++)
        #pragma unroll
        for (int b = 0; b < 4; b++)
            #pragma unroll
            for (int c = 0; c < 4; c++) acc[a][b][c] = 0.f;

    int T = K >> 5;

    #define LOAD_STAGE(s, k0) do {                                             \
        uint32_t _b = smb + (s) * GSTG;                                        \
        {                                                                      \
            int r = tid >> 2, c8 = (tid & 3) << 3;                             \
            size_t ao = (size_t)(row0 + r) * K + (k0) + c8;                    \
            cpa16(_b + GS_AH + r * 80 + c8 * 2, Ah + ao);                      \
            cpa16(_b + GS_AL + r * 80 + c8 * 2, Al + ao);                      \
        }                                                                      \
        _Pragma("unroll")                                                      \
        for (int it = 0; it < 2; it++) {                                       \
            int rr = (tid >> 4) + it * 16;                                     \
            int c8 = (tid & 15) << 3;                                          \
            size_t bo = (size_t)((k0) + rr) * Ntot + col0 + c8;                \
            cpa16(_b + GS_BH + rr * 272 + c8 * 2, Bh + bo);                    \
            cpa16(_b + GS_BL + rr * 272 + c8 * 2, Bl + bo);                    \
        }                                                                      \
        CP_COMMIT();                                                           \
    } while (0)

    LOAD_STAGE(0, 0);

    for (int t = 0; t < T; t++) {
        if (t + 1 < T) {
            LOAD_STAGE((t + 1) & 1, (t + 1) * 32);
            asm volatile("cp.async.wait_group 1;" ::: "memory");
        } else {
            asm volatile("cp.async.wait_group 0;" ::: "memory");
        }
        __syncthreads();

        uint32_t sb = smb + (t & 1) * GSTG;
        #pragma unroll
        for (int kk = 0; kk < 2; kk++) {
            uint32_t ah[2][4], al[2][4], bh[2][4], bl[2][4];
            int ar = lane & 15;
            int ac = kk * 16 + (lane >> 4) * 8;
            #pragma unroll
            for (int mt = 0; mt < 2; mt++) {
                uint32_t ao = sb + (wm * 32 + mt * 16 + ar) * 80 + ac * 2;
                ldsm_x4(ah[mt], ao + GS_AH);
                ldsm_x4(al[mt], ao + GS_AL);
            }
            int br = kk * 16 + (lane & 15);
            int bc = wn * 32 + (lane >> 4) * 8;
            #pragma unroll
            for (int nt = 0; nt < 2; nt++) {
                uint32_t bo = sb + br * 272 + (bc + nt * 16) * 2;
                ldsm_x4t(bh[nt], bo + GS_BH);
                ldsm_x4t(bl[nt], bo + GS_BL);
            }
            #pragma unroll
            for (int mt = 0; mt < 2; mt++)
                #pragma unroll
                for (int nt = 0; nt < 2; nt++) {
                    mma_bf16(acc[mt][2*nt],   ah[mt], bh[nt][0], bh[nt][1]);
                    mma_bf16(acc[mt][2*nt+1], ah[mt], bh[nt][2], bh[nt][3]);
                    mma_bf16(acc[mt][2*nt],   al[mt], bh[nt][0], bh[nt][1]);
                    mma_bf16(acc[mt][2*nt+1], al[mt], bh[nt][2], bh[nt][3]);
                    mma_bf16(acc[mt][2*nt],   ah[mt], bl[nt][0], bl[nt][1]);
                    mma_bf16(acc[mt][2*nt+1], ah[mt], bl[nt][2], bl[nt][3]);
                }
        }
        __syncthreads();
    }

    float* Cf = P.cf[z];
    __nv_bfloat16* Ch = P.ch[z];
    __nv_bfloat16* Cl = P.cl[z];
    int rb = row0 + wm * 32 + (lane >> 2);
    int cb = col0 + wn * 32 + (lane & 3) * 2;
    float s2n[2][2] = {{0.f, 0.f}, {0.f, 0.f}};
    #pragma unroll
    for (int mt = 0; mt < 2; mt++) {
        #pragma unroll
        for (int nt8 = 0; nt8 < 4; nt8++) {
            int gc = cb + nt8 * 8;
            float2 bb = *(const float2*)&bias[gc];
            float2 o0, o1;
            o0.x = acc[mt][nt8][0] + bb.x;
            o0.y = acc[mt][nt8][1] + bb.y;
            o1.x = acc[mt][nt8][2] + bb.x;
            o1.y = acc[mt][nt8][3] + bb.y;
            if (relu) {
                o0.x = fmaxf(o0.x, 0.f); o0.y = fmaxf(o0.y, 0.f);
                o1.x = fmaxf(o1.x, 0.f); o1.y = fmaxf(o1.y, 0.f);
            }
            int gr = rb + mt * 16;
            if (mode == 0) {
                *(float2*)&Cf[(size_t)gr * Ntot + gc] = o0;
                *(float2*)&Cf[(size_t)(gr + 8) * Ntot + gc] = o1;
            } else {
                __nv_bfloat16 h0 = __float2bfloat16(o0.x), h1 = __float2bfloat16(o0.y);
                __nv_bfloat16 h2 = __float2bfloat16(o1.x), h3 = __float2bfloat16(o1.y);
                uint32_t lw0 = pkbf(__float2bfloat16(o0.x - __bfloat162float(h0)),
                                    __float2bfloat16(o0.y - __bfloat162float(h1)));
                uint32_t lw1 = pkbf(__float2bfloat16(o1.x - __bfloat162float(h2)),
                                    __float2bfloat16(o1.y - __bfloat162float(h3)));
                *(uint32_t*)&Ch[(size_t)gr * Ntot + gc] = pkbf(h0, h1);
                *(uint32_t*)&Cl[(size_t)gr * Ntot + gc] = lw0;
                *(uint32_t*)&Ch[(size_t)(gr + 8) * Ntot + gc] = pkbf(h2, h3);
                *(uint32_t*)&Cl[(size_t)(gr + 8) * Ntot + gc] = lw1;
                if (mode == 2) {
                    s2n[mt][0] += o0.x * o0.x + o0.y * o0.y;
                    s2n[mt][1] += o1.x * o1.x + o1.y * o1.y;
                }
            }
        }
    }
    if (mode == 2) {
        float* Nrm = P.nrm[z];
        int head = blockIdx.x * 4 + wn;
        #pragma unroll
        for (int mt = 0; mt < 2; mt++)
            #pragma unroll
            for (int rh = 0; rh < 2; rh++) {
                float s = s2n[mt][rh];
                s += __shfl_xor_sync(0xffffffffu, s, 1);
                s += __shfl_xor_sync(0xffffffffu, s, 2);
                if ((lane & 3) == 0) {
                    int gr = rb + mt * 16 + rh * 8;
                    Nrm[(size_t)gr * HEADS + head] = -0.5f * s;
                }
            }
    }
}

// ---------------- tensor-core RBF flash attention ---------------------------
#define AT_QH 0
#define AT_QL 10240
#define AT_Q2 20480
#define AT_ST 20992
#define AT_KH 0
#define AT_KL 5120
#define AT_VH 10240
#define AT_K2 15360
#define AT_STG 15616
#define AT_PH 52224
#define AT_TOT 70656

__global__ __launch_bounds__(128) void attn_mma(
    const __nv_bfloat16* __restrict__ Qbh, const __nv_bfloat16* __restrict__ Qbl,
    const __nv_bfloat16* __restrict__ Kbh, const __nv_bfloat16* __restrict__ Kbl,
    const __nv_bfloat16* __restrict__ Vbh,
    const float* __restrict__ Qn, const float* __restrict__ Kn,
    __nv_bfloat16* __restrict__ Oh, __nv_bfloat16* __restrict__ Ol)
{
    extern __shared__ __align__(16) char sm[];
    uint32_t smb = smem_u32(sm);
    float* q2s = (float*)(sm + AT_Q2);
    __nv_bfloat16* Ph = (__nv_bfloat16*)(sm + AT_PH);

    int tid = threadIdx.x, lane = tid & 31, wid = tid >> 5;
    int bh = blockIdx.y, b = bh >> 3, h = bh & 7;
    int q0 = blockIdx.x * 128;

    #define LOADKV(kt, s) do {                                                 \
        uint32_t _b = smb + AT_ST + (s) * AT_STG;                              \
        _Pragma("unroll")                                                      \
        for (int it = 0; it < 2; it++) {                                       \
            int idx = tid + it * 128;                                          \
            int r = idx >> 2, c = idx & 3;                                     \
            size_t go = (size_t)(b*SEQ + (kt)*64 + r)*D_MODEL + h*DEPTH + c*8; \
            cpa16(_b + AT_KH + r * 80 + c * 16, Kbh + go);                     \
            cpa16(_b + AT_KL + r * 80 + c * 16, Kbl + go);                     \
            cpa16(_b + AT_VH + r * 80 + c * 16, Vbh + go);                     \
        }                                                                      \
        if (tid < 64)                                                          \
            cpa4(_b + AT_K2 + tid * 4,                                         \
                 Kn + (size_t)(b*SEQ + (kt)*64 + tid) * HEADS + h);            \
        CP_COMMIT();                                                           \
    } while (0)

    LOADKV(0, 0);
    #pragma unroll
    for (int it = 0; it < 4; it++) {
        int idx = tid + it * 128;
        int r = idx >> 2, c = idx & 3;
        size_t go = (size_t)(b*SEQ + q0 + r)*D_MODEL + h*DEPTH + c*8;
        cpa16(smb + AT_QH + r * 80 + c * 16, Qbh + go);
        cpa16(smb + AT_QL + r * 80 + c * 16, Qbl + go);
    }
    CP_COMMIT();
    q2s[tid] = Qn[(size_t)(b*SEQ + q0 + tid) * HEADS + h];
    asm volatile("cp.async.wait_group 0;" ::: "memory");
    __syncthreads();

    uint32_t qah[2][2][4], qal[2][2][4];
    {
        int ar = lane & 15, ag = (lane >> 4) * 8;
        #pragma unroll
        for (int mt = 0; mt < 2; mt++)
            #pragma unroll
            for (int kc = 0; kc < 2; kc++) {
                uint32_t off = smb + (wid*32 + mt*16 + ar) * 80 + (kc*16 + ag) * 2;
                ldsm_x4(qah[mt][kc], off + AT_QH);
                ldsm_x4(qal[mt][kc], off + AT_QL);
            }
    }
    float q2r[2][2];
    #pragma unroll
    for (int mt = 0; mt < 2; mt++)
        #pragma unroll
        for (int rh = 0; rh < 2; rh++)
            q2r[mt][rh] = q2s[wid*32 + mt*16 + rh*8 + (lane >> 2)];

    float oacc[2][4][4];
    #pragma unroll
    for (int a = 0; a < 2; a++)
        #pragma unroll
        for (int c = 0; c < 4; c++)
            #pragma unroll
            for (int d = 0; d < 4; d++) oacc[a][c][d] = 0.f;
    float dpart[2][2] = {{0.f, 0.f}, {0.f, 0.f}};

    for (int kt = 0; kt < SEQ / 64; kt++) {
        if (kt + 1 < SEQ / 64) {
            LOADKV(kt + 1, (kt + 1) & 1);
            asm volatile("cp.async.wait_group 1;" ::: "memory");
        } else {
            asm volatile("cp.async.wait_group 0;" ::: "memory");
        }
        __syncthreads();

        uint32_t kf = smb + AT_ST + (kt & 1) * AT_STG;
        float* k2s = (float*)(sm + AT_ST + (kt & 1) * AT_STG + AT_K2);

        {
            int ar = lane & 15, ag = (lane >> 4) * 8;
            #pragma unroll
            for (int ntp = 0; ntp < 4; ntp++) {
                uint32_t kbh[2][4], kbl[2][4];
                #pragma unroll
                for (int kc = 0; kc < 2; kc++) {
                    uint32_t off = kf + (ntp*16 + ar) * 80 + (kc*16 + ag) * 2;
                    ldsm_x4(kbh[kc], off + AT_KH);
                    ldsm_x4(kbl[kc], off + AT_KL);
                }
                #pragma unroll
                for (int mt = 0; mt < 2; mt++)
                    #pragma unroll
                    for (int nt = 0; nt < 2; nt++) {
                        float s[4] = {0.f, 0.f, 0.f, 0.f};
                        #pragma unroll
                        for (int kc = 0; kc < 2; kc++) {
                            mma_bf16(s, qah[mt][kc], kbh[kc][nt], kbh[kc][nt+2]);
                            mma_bf16(s, qal[mt][kc], kbh[kc][nt], kbh[kc][nt+2]);
                            mma_bf16(s, qah[mt][kc], kbl[kc][nt], kbl[kc][nt+2]);
                        }
                        int cbase = ntp*16 + nt*8 + (lane & 3)*2;
                        float k2c0 = k2s[cbase], k2c1 = k2s[cbase + 1];
                        #pragma unroll
                        for (int rh = 0; rh < 2; rh++) {
                            float w0 = __expf(s[rh*2+0] + q2r[mt][rh] + k2c0);
                            float w1 = __expf(s[rh*2+1] + q2r[mt][rh] + k2c1);
                            float p0 = __expf(w0);
                            float p1 = __expf(w1);
                            dpart[mt][rh] += p0 + p1;
                            __nv_bfloat162 hp = __float22bfloat162_rn(make_float2(p0, p1));
                            int prow = wid*32 + mt*16 + rh*8 + (lane >> 2);
                            *(uint32_t*)&Ph[prow*72 + cbase] = *(uint32_t*)&hp;
                        }
                    }
            }
        }
        __syncwarp();

        {
            int ar = lane & 15, ag = (lane >> 4) * 8;
            #pragma unroll
            for (int kc = 0; kc < 4; kc++) {
                uint32_t pah[2][4], vbh[2][4];
                #pragma unroll
                for (int mt = 0; mt < 2; mt++)
                    ldsm_x4(pah[mt],
                        smb + AT_PH + ((wid*32 + mt*16 + ar)*72 + kc*16 + ag) * 2);
                #pragma unroll
                for (int ntp = 0; ntp < 2; ntp++)
                    ldsm_x4t(vbh[ntp],
                        kf + AT_VH + (kc*16 + ar) * 80 + (ntp*16 + ag) * 2);
                #pragma unroll
                for (int mt = 0; mt < 2; mt++)
                    #pragma unroll
                    for (int ntp = 0; ntp < 2; ntp++)
                        #pragma unroll
                        for (int nt = 0; nt < 2; nt++)
                            mma_bf16(oacc[mt][ntp*2 + nt], pah[mt],
                                     vbh[ntp][2*nt], vbh[ntp][2*nt+1]);
            }
        }
        __syncthreads();
    }

    #pragma unroll
    for (int mt = 0; mt < 2; mt++)
        #pragma unroll
        for (int rh = 0; rh < 2; rh++) {
            float den = dpart[mt][rh];
            den += __shfl_xor_sync(0xffffffffu, den, 1);
            den += __shfl_xor_sync(0xffffffffu, den, 2);
            float inv = 1.f / den;
            int row = q0 + wid*32 + mt*16 + rh*8 + (lane >> 2);
            size_t obase = (size_t)(b*SEQ + row)*D_MODEL + h*DEPTH + (lane & 3)*2;
            #pragma unroll
            for (int nt4 = 0; nt4 < 4; nt4++) {
                float ox = oacc[mt][nt4][rh*2+0] * inv;
                float oy = oacc[mt][nt4][rh*2+1] * inv;
                __nv_bfloat16 h0 = __float2bfloat16(ox), h1 = __float2bfloat16(oy);
                uint32_t hw = pkbf(h0, h1);
                uint32_t lw = pkbf(__float2bfloat16(ox - __bfloat162float(h0)),
                                   __float2bfloat16(oy - __bfloat162float(h1)));
                *(uint32_t*)(Oh + obase + nt4*8) = hw;
                *(uint32_t*)(Ol + obase + nt4*8) = lw;
            }
        }
}

// ---------------- fused residual + LayerNorm (warp per row) -----------------
__global__ __launch_bounds__(256) void residual_ln(
    const float* __restrict__ X, const float* __restrict__ Y,
    const float* __restrict__ g, const float* __restrict__ b,
    float* __restrict__ outf,
    __nv_bfloat16* __restrict__ outh, __nv_bfloat16* __restrict__ outl,
    int do_split)
{
    int lane = threadIdx.x & 31, w = threadIdx.x >> 5;
    int row  = blockIdx.x * 8 + w;
    size_t base = (size_t)row * D_MODEL;
    int c0 = lane * 4, c1 = 128 + lane * 4;

    float4 x0 = *(const float4*)(X + base + c0);
    float4 x1 = *(const float4*)(X + base + c1);
    float4 y0 = *(const float4*)(Y + base + c0);
    float4 y1 = *(const float4*)(Y + base + c1);
    float4 v0 = make_float4(x0.x+y0.x, x0.y+y0.y, x0.z+y0.z, x0.w+y0.w);
    float4 v1 = make_float4(x1.x+y1.x, x1.y+y1.y, x1.z+y1.z, x1.w+y1.w);

    float s = v0.x+v0.y+v0.z+v0.w + v1.x+v1.y+v1.z+v1.w;
    #pragma unroll
    for (int o = 16; o > 0; o >>= 1) s += __shfl_xor_sync(0xffffffffu, s, o);
    float mean = s * (1.f / D_MODEL);

    float4 d0 = make_float4(v0.x-mean, v0.y-mean, v0.z-mean, v0.w-mean);
    float4 d1 = make_float4(v1.x-mean, v1.y-mean, v1.z-mean, v1.w-mean);
    float s2 = d0.x*d0.x+d0.y*d0.y+d0.z*d0.z+d0.w*d0.w
             + d1.x*d1.x+d1.y*d1.y+d1.z*d1.z+d1.w*d1.w;
    #pragma unroll
    for (int o = 16; o > 0; o >>= 1) s2 += __shfl_xor_sync(0xffffffffu, s2, o);
    float rstd = rsqrtf(s2 * (1.f / D_MODEL) + EPS);

    float4 g0 = *(const float4*)(g + c0), g1 = *(const float4*)(g + c1);
    float4 b0 = *(const float4*)(b + c0), b1 = *(const float4*)(b + c1);
    float4 o0, o1;
    o0.x = d0.x*rstd*g0.x + b0.x; o0.y = d0.y*rstd*g0.y + b0.y;
    o0.z = d0.z*rstd*g0.z + b0.z; o0.w = d0.w*rstd*g0.w + b0.w;
    o1.x = d1.x*rstd*g1.x + b1.x; o1.y = d1.y*rstd*g1.y + b1.y;
    o1.z = d1.z*rstd*g1.z + b1.z; o1.w = d1.w*rstd*g1.w + b1.w;
    *(float4*)(outf + base + c0) = o0;
    *(float4*)(outf + base + c1) = o1;

    if (do_split) {
        __nv_bfloat16 h0 = __float2bfloat16(o0.x), h1 = __float2bfloat16(o0.y);
        __nv_bfloat16 h2 = __float2bfloat16(o0.z), h3 = __float2bfloat16(o0.w);
        __nv_bfloat16 h4 = __float2bfloat16(o1.x), h5 = __float2bfloat16(o1.y);
        __nv_bfloat16 h6 = __float2bfloat16(o1.z), h7 = __float2bfloat16(o1.w);
        *(uint2*)(outh + base + c0) = make_uint2(pkbf(h0,h1), pkbf(h2,h3));
        *(uint2*)(outh + base + c1) = make_uint2(pkbf(h4,h5), pkbf(h6,h7));
        *(uint2*)(outl + base + c0) = make_uint2(
            pkbf(__float2bfloat16(o0.x-__bfloat162float(h0)),
                 __float2bfloat16(o0.y-__bfloat162float(h1))),
            pkbf(__float2bfloat16(o0.z-__bfloat162float(h2)),
                 __float2bfloat16(o0.w-__bfloat162float(h3))));
        *(uint2*)(outl + base + c1) = make_uint2(
            pkbf(__float2bfloat16(o1.x-__bfloat162float(h4)),
                 __float2bfloat16(o1.y-__bfloat162float(h5))),
            pkbf(__float2bfloat16(o1.z-__bfloat162float(h6)),
                 __float2bfloat16(o1.w-__bfloat162float(h7))));
    }
}

// ---------------- launch -----------------------------------------------------
extern "C" void kernel_launch(void* const* d_in, const int* in_sizes, int n_in,
                              void* d_out, int out_size)
{
    const float* x      = (const float*)d_in[0];
    const float* wq_w   = (const float*)d_in[1];
    const float* wq_b   = (const float*)d_in[2];
    const float* wk_w   = (const float*)d_in[3];
    const float* wk_b   = (const float*)d_in[4];
    const float* wv_w   = (const float*)d_in[5];
    const float* wv_b   = (const float*)d_in[6];
    const float* wo_w   = (const float*)d_in[7];
    const float* wo_b   = (const float*)d_in[8];
    const float* ffn1_w = (const float*)d_in[9];
    const float* ffn1_b = (const float*)d_in[10];
    const float* ffn2_w = (const float*)d_in[11];
    const float* ffn2_b = (const float*)d_in[12];
    const float* ln1_g  = (const float*)d_in[13];
    const float* ln1_b  = (const float*)d_in[14];
    const float* ln2_g  = (const float*)d_in[15];
    const float* ln2_b  = (const float*)d_in[16];

    float *tmp, *out1, *qn, *kn, *vn;
    cudaGetSymbolAddress((void**)&tmp,  g_tmp);
    cudaGetSymbolAddress((void**)&out1, g_out1);
    cudaGetSymbolAddress((void**)&qn,   g_qn);
    cudaGetSymbolAddress((void**)&kn,   g_kn);
    cudaGetSymbolAddress((void**)&vn,   g_vn);

    __nv_bfloat16 *qbh, *qbl, *kbh, *kbl, *vbh, *vbl;
    cudaGetSymbolAddress((void**)&qbh, g_qbh); cudaGetSymbolAddress((void**)&qbl, g_qbl);
    cudaGetSymbolAddress((void**)&kbh, g_kbh); cudaGetSymbolAddress((void**)&kbl, g_kbl);
    cudaGetSymbolAddress((void**)&vbh, g_vbh); cudaGetSymbolAddress((void**)&vbl, g_vbl);

    __nv_bfloat16 *xh, *xl, *atth, *attl, *o1h, *o1l, *ffhh, *ffhl;
    cudaGetSymbolAddress((void**)&xh,   g_xh);   cudaGetSymbolAddress((void**)&xl,   g_xl);
    cudaGetSymbolAddress((void**)&atth, g_atth); cudaGetSymbolAddress((void**)&attl, g_attl);
    cudaGetSymbolAddress((void**)&o1h,  g_o1h);  cudaGetSymbolAddress((void**)&o1l,  g_o1l);
    cudaGetSymbolAddress((void**)&ffhh, g_ffhh); cudaGetSymbolAddress((void**)&ffhl, g_ffhl);

    __nv_bfloat16 *wqh, *wql, *wkh, *wkl, *wvh, *wvl, *woh, *wol, *f1h, *f1l, *f2h, *f2l;
    cudaGetSymbolAddress((void**)&wqh, g_wqh); cudaGetSymbolAddress((void**)&wql, g_wql);
    cudaGetSymbolAddress((void**)&wkh, g_wkh); cudaGetSymbolAddress((void**)&wkl, g_wkl);
    cudaGetSymbolAddress((void**)&wvh, g_wvh); cudaGetSymbolAddress((void**)&wvl, g_wvl);
    cudaGetSymbolAddress((void**)&woh, g_woh); cudaGetSymbolAddress((void**)&wol, g_wol);
    cudaGetSymbolAddress((void**)&f1h, g_f1h); cudaGetSymbolAddress((void**)&f1l, g_f1l);
    cudaGetSymbolAddress((void**)&f2h, g_f2h); cudaGetSymbolAddress((void**)&f2l, g_f2l);

    cudaFuncSetAttribute(attn_mma, cudaFuncAttributeMaxDynamicSharedMemorySize, AT_TOT);
    cudaFuncSetAttribute(gemm_bf3, cudaFuncAttributeMaxDynamicSharedMemorySize, G_TOT);

    // one combined split launch: 6 weights + x
    SplitJobs J;
    const float* srcs[7] = {wq_w, wk_w, wv_w, wo_w, ffn1_w, ffn2_w, x};
    __nv_bfloat16* hs[7] = {wqh, wkh, wvh, woh, f1h, f2h, xh};
    __nv_bfloat16* ls[7] = {wql, wkl, wvl, wol, f1l, f2l, xl};
    long long sizes4[7] = {65536/4, 65536/4, 65536/4, 65536/4,
                           262144/4, 262144/4, (long long)TOK*D_MODEL/4};
    long long acc = 0;
    for (int i = 0; i < 7; i++) { J.src[i] = srcs[i]; J.h[i] = hs[i]; J.l[i] = ls[i];
                                  J.start[i] = acc; acc += sizes4[i]; }
    J.start[7] = acc;
    split_all<<<(unsigned)((acc + 255) / 256), 256>>>(J);

    // QKV projections: bf16 hi/lo out + head norms (mode 2)
    {
        GemmPtrs P = {};
        P.bh[0] = wqh; P.bl[0] = wql; P.bias[0] = wq_b;
        P.bh[1] = wkh; P.bl[1] = wkl; P.bias[1] = wk_b;
        P.bh[2] = wvh; P.bl[2] = wvl; P.bias[2] = wv_b;
        P.ch[0] = qbh; P.cl[0] = qbl; P.nrm[0] = qn;
        P.ch[1] = kbh; P.cl[1] = kbl; P.nrm[1] = kn;
        P.ch[2] = vbh; P.cl[2] = vbl; P.nrm[2] = vn;
        gemm_bf3<<<dim3(2, 128, 3), 256, G_TOT>>>(xh, xl, P, D_MODEL, D_MODEL, 0, 2);
    }

    // tensor-core RBF attention
    attn_mma<<<dim3(SEQ / 128, BATCH * HEADS), 128, AT_TOT>>>(
        qbh, qbl, kbh, kbl, vbh, qn, kn, atth, attl);

    // output projection (fp32) + residual LN1
    {
        GemmPtrs P = {};
        P.bh[0] = woh; P.bl[0] = wol; P.bias[0] = wo_b; P.cf[0] = tmp;
        gemm_bf3<<<dim3(2, 128, 1), 256, G_TOT>>>(atth, attl, P, D_MODEL, D_MODEL, 0, 0);
    }
    residual_ln<<<TOK / 8, 256>>>(x, tmp, ln1_g, ln1_b, out1, o1h, o1l, 1);

    // FFN1 (relu, bf16 out) -> FFN2 (fp32) -> residual LN2
    {
        GemmPtrs P = {};
        P.bh[0] = f1h; P.bl[0] = f1l; P.bias[0] = ffn1_b;
        P.ch[0] = ffhh; P.cl[0] = ffhl;
        gemm_bf3<<<dim3(8, 128, 1), 256, G_TOT>>>(o1h, o1l, P, D_MODEL, DFF, 1, 1);
    }
    {
        GemmPtrs P = {};
        P.bh[0] = f2h; P.bl[0] = f2l; P.bias[0] = ffn2_b; P.cf[0] = tmp;
        gemm_bf3<<<dim3(2, 128, 1), 256, G_TOT>>>(ffhh, ffhl, P, DFF, D_MODEL, 0, 0);
    }
    residual_ln<<<TOK / 8, 256>>>(out1, tmp, ln2_g, ln2_b, (float*)d_out,
                                  (__nv_bfloat16*)0, (__nv_bfloat16*)0, 0);
}

// round 13
// speedup vs baseline: 3.3549x; 1.0807x over previous
#include <cuda_runtime.h>
#include <cuda_bf16.h>
#include <cstdint>
#include <math.h>

#define D_MODEL 256
#define BATCH   4
#define SEQ     2048
#define HEADS   8
#define DEPTH   32
#define DFF     1024
#define TOK     (BATCH*SEQ)   // 8192
#define EPS     1e-6f

typedef unsigned long long ull;

// ---------------- mma.sync / cp.async / f32x2 helpers -----------------------
__device__ __forceinline__ uint32_t smem_u32(const void* p) {
    uint32_t a;
    asm("{ .reg .u64 t; cvta.to.shared.u64 t, %1; cvt.u32.u64 %0, t; }"
        : "=r"(a) : "l"(p));
    return a;
}
__device__ __forceinline__ void ldsm_x4(uint32_t* r, uint32_t addr) {
    asm volatile("ldmatrix.sync.aligned.m8n8.x4.shared.b16 {%0,%1,%2,%3}, [%4];"
        : "=r"(r[0]), "=r"(r[1]), "=r"(r[2]), "=r"(r[3]) : "r"(addr));
}
__device__ __forceinline__ void ldsm_x4t(uint32_t* r, uint32_t addr) {
    asm volatile("ldmatrix.sync.aligned.m8n8.x4.trans.shared.b16 {%0,%1,%2,%3}, [%4];"
        : "=r"(r[0]), "=r"(r[1]), "=r"(r[2]), "=r"(r[3]) : "r"(addr));
}
__device__ __forceinline__ void mma_bf16(float* d, const uint32_t* a,
                                         uint32_t b0, uint32_t b1) {
    asm volatile("mma.sync.aligned.m16n8k16.row.col.f32.bf16.bf16.f32 "
        "{%0,%1,%2,%3}, {%4,%5,%6,%7}, {%8,%9}, {%0,%1,%2,%3};"
        : "+f"(d[0]), "+f"(d[1]), "+f"(d[2]), "+f"(d[3])
        : "r"(a[0]), "r"(a[1]), "r"(a[2]), "r"(a[3]), "r"(b0), "r"(b1));
}
__device__ __forceinline__ uint32_t pkbf(__nv_bfloat16 a, __nv_bfloat16 b) {
    return (uint32_t)__bfloat16_as_ushort(a) | ((uint32_t)__bfloat16_as_ushort(b) << 16);
}
__device__ __forceinline__ void cpa16(uint32_t dst, const void* src) {
    asm volatile("cp.async.cg.shared.global [%0], [%1], 16;" :: "r"(dst), "l"(src));
}
__device__ __forceinline__ void cpa4(uint32_t dst, const void* src) {
    asm volatile("cp.async.ca.shared.global [%0], [%1], 4;" :: "r"(dst), "l"(src));
}
#define CP_COMMIT() asm volatile("cp.async.commit_group;" ::: "memory")

__device__ __forceinline__ ull fma2(ull a, ull b, ull c) {
    ull d; asm("fma.rn.f32x2 %0, %1, %2, %3;" : "=l"(d) : "l"(a), "l"(b), "l"(c));
    return d;
}
__device__ __forceinline__ ull add2(ull a, ull b) {
    ull d; asm("add.rn.f32x2 %0, %1, %2;" : "=l"(d) : "l"(a), "l"(b));
    return d;
}
__device__ __forceinline__ ull pack2(float lo, float hi) {
    ull d; asm("mov.b64 %0, {%1, %2};" : "=l"(d) : "f"(lo), "f"(hi));
    return d;
}
__device__ __forceinline__ float2 unpack2(ull v) {
    float lo, hi; asm("mov.b64 {%0, %1}, %2;" : "=f"(lo), "=f"(hi) : "l"(v));
    return make_float2(lo, hi);
}

// ---------------- scratch ---------------------------------------------------
__device__ float g_tmp [TOK*D_MODEL];
__device__ float g_out1[TOK*D_MODEL];
__device__ float g_qn[TOK*HEADS], g_kn[TOK*HEADS], g_vn[TOK*HEADS];
__device__ __nv_bfloat16 g_qbh[TOK*D_MODEL], g_qbl[TOK*D_MODEL];
__device__ __nv_bfloat16 g_kbh[TOK*D_MODEL], g_kbl[TOK*D_MODEL];
__device__ __nv_bfloat16 g_vbh[TOK*D_MODEL], g_vbl[TOK*D_MODEL];
__device__ __nv_bfloat16 g_xh  [TOK*D_MODEL], g_xl  [TOK*D_MODEL];
__device__ __nv_bfloat16 g_atth[TOK*D_MODEL], g_attl[TOK*D_MODEL];
__device__ __nv_bfloat16 g_o1h [TOK*D_MODEL], g_o1l [TOK*D_MODEL];
__device__ __nv_bfloat16 g_ffhh[TOK*DFF],     g_ffhl[TOK*DFF];
__device__ __nv_bfloat16 g_wqh[D_MODEL*D_MODEL], g_wql[D_MODEL*D_MODEL];
__device__ __nv_bfloat16 g_wkh[D_MODEL*D_MODEL], g_wkl[D_MODEL*D_MODEL];
__device__ __nv_bfloat16 g_wvh[D_MODEL*D_MODEL], g_wvl[D_MODEL*D_MODEL];
__device__ __nv_bfloat16 g_woh[D_MODEL*D_MODEL], g_wol[D_MODEL*D_MODEL];
__device__ __nv_bfloat16 g_f1h[D_MODEL*DFF],     g_f1l[D_MODEL*DFF];
__device__ __nv_bfloat16 g_f2h[DFF*D_MODEL],     g_f2l[DFF*D_MODEL];

// ---------------- combined hi/lo split (weights + x), one launch ------------
struct SplitJobs {
    const float*   src[7];
    __nv_bfloat16* h[7];
    __nv_bfloat16* l[7];
    long long      start[8];
};
__global__ __launch_bounds__(256) void split_all(SplitJobs J)
{
    long long c = (long long)blockIdx.x * 256 + threadIdx.x;
    if (c >= J.start[7]) return;
    int s = 0;
    #pragma unroll
    for (int i = 1; i < 7; i++) if (c >= J.start[i]) s = i;
    long long i4 = c - J.start[s];
    float4 f = ((const float4*)J.src[s])[i4];
    __nv_bfloat16 h0 = __float2bfloat16(f.x), h1 = __float2bfloat16(f.y);
    __nv_bfloat16 h2 = __float2bfloat16(f.z), h3 = __float2bfloat16(f.w);
    __nv_bfloat16 l0 = __float2bfloat16(f.x - __bfloat162float(h0));
    __nv_bfloat16 l1 = __float2bfloat16(f.y - __bfloat162float(h1));
    __nv_bfloat16 l2 = __float2bfloat16(f.z - __bfloat162float(h2));
    __nv_bfloat16 l3 = __float2bfloat16(f.w - __bfloat162float(h3));
    ((uint2*)J.h[s])[i4] = make_uint2(pkbf(h0, h1), pkbf(h2, h3));
    ((uint2*)J.l[s])[i4] = make_uint2(pkbf(l0, l1), pkbf(l2, l3));
}

// ---------------- bf16x3 GEMM, 64x128 tiles, 2-stage cp.async --------------
struct GemmPtrs {
    const __nv_bfloat16 *bh[3], *bl[3];
    const float* bias[3];
    float* cf[3];
    __nv_bfloat16 *ch[3], *cl[3];
    float* nrm[3];
};
#define GS_AH 0
#define GS_AL 5120
#define GS_BH 10240
#define GS_BL 18944
#define GSTG  27648
#define G_TOT (2*GSTG)

__global__ __launch_bounds__(256) void gemm_bf3(
    const __nv_bfloat16* __restrict__ Ah, const __nv_bfloat16* __restrict__ Al,
    GemmPtrs P, int K, int Ntot, int relu, int mode)
{
    extern __shared__ __align__(16) char sm[];
    uint32_t smb = smem_u32(sm);

    int tid  = threadIdx.x;
    int lane = tid & 31;
    int wid  = tid >> 5;
    int wm   = wid & 1;
    int wn   = wid >> 1;

    int z = blockIdx.z;
    const __nv_bfloat16* Bh = P.bh[z];
    const __nv_bfloat16* Bl = P.bl[z];
    const float* bias = P.bias[z];

    int row0 = blockIdx.y * 64;
    int col0 = blockIdx.x * 128;

    float acc[2][4][4];
    #pragma unroll
    for (int a = 0; a < 2; a++)
        #pragma unroll
        for (int b = 0; b < 4; b++)
            #pragma unroll
            for (int c = 0; c < 4; c++) acc[a][b][c] = 0.f;

    int T = K >> 5;

    #define LOAD_STAGE(s, k0) do {                                             \
        uint32_t _b = smb + (s) * GSTG;                                        \
        {                                                                      \
            int r = tid >> 2, c8 = (tid & 3) << 3;                             \
            size_t ao = (size_t)(row0 + r) * K + (k0) + c8;                    \
            cpa16(_b + GS_AH + r * 80 + c8 * 2, Ah + ao);                      \
            cpa16(_b + GS_AL + r * 80 + c8 * 2, Al + ao);                      \
        }                                                                      \
        _Pragma("unroll")                                                      \
        for (int it = 0; it < 2; it++) {                                       \
            int rr = (tid >> 4) + it * 16;                                     \
            int c8 = (tid & 15) << 3;                                          \
            size_t bo = (size_t)((k0) + rr) * Ntot + col0 + c8;                \
            cpa16(_b + GS_BH + rr * 272 + c8 * 2, Bh + bo);                    \
            cpa16(_b + GS_BL + rr * 272 + c8 * 2, Bl + bo);                    \
        }                                                                      \
        CP_COMMIT();                                                           \
    } while (0)

    LOAD_STAGE(0, 0);

    for (int t = 0; t < T; t++) {
        if (t + 1 < T) {
            LOAD_STAGE((t + 1) & 1, (t + 1) * 32);
            asm volatile("cp.async.wait_group 1;" ::: "memory");
        } else {
            asm volatile("cp.async.wait_group 0;" ::: "memory");
        }
        __syncthreads();

        uint32_t sb = smb + (t & 1) * GSTG;
        #pragma unroll
        for (int kk = 0; kk < 2; kk++) {
            uint32_t ah[2][4], al[2][4], bh[2][4], bl[2][4];
            int ar = lane & 15;
            int ac = kk * 16 + (lane >> 4) * 8;
            #pragma unroll
            for (int mt = 0; mt < 2; mt++) {
                uint32_t ao = sb + (wm * 32 + mt * 16 + ar) * 80 + ac * 2;
                ldsm_x4(ah[mt], ao + GS_AH);
                ldsm_x4(al[mt], ao + GS_AL);
            }
            int br = kk * 16 + (lane & 15);
            int bc = wn * 32 + (lane >> 4) * 8;
            #pragma unroll
            for (int nt = 0; nt < 2; nt++) {
                uint32_t bo = sb + br * 272 + (bc + nt * 16) * 2;
                ldsm_x4t(bh[nt], bo + GS_BH);
                ldsm_x4t(bl[nt], bo + GS_BL);
            }
            #pragma unroll
            for (int mt = 0; mt < 2; mt++)
                #pragma unroll
                for (int nt = 0; nt < 2; nt++) {
                    mma_bf16(acc[mt][2*nt],   ah[mt], bh[nt][0], bh[nt][1]);
                    mma_bf16(acc[mt][2*nt+1], ah[mt], bh[nt][2], bh[nt][3]);
                    mma_bf16(acc[mt][2*nt],   al[mt], bh[nt][0], bh[nt][1]);
                    mma_bf16(acc[mt][2*nt+1], al[mt], bh[nt][2], bh[nt][3]);
                    mma_bf16(acc[mt][2*nt],   ah[mt], bl[nt][0], bl[nt][1]);
                    mma_bf16(acc[mt][2*nt+1], ah[mt], bl[nt][2], bl[nt][3]);
                }
        }
        __syncthreads();
    }

    float* Cf = P.cf[z];
    __nv_bfloat16* Ch = P.ch[z];
    __nv_bfloat16* Cl = P.cl[z];
    int rb = row0 + wm * 32 + (lane >> 2);
    int cb = col0 + wn * 32 + (lane & 3) * 2;
    float s2n[2][2] = {{0.f, 0.f}, {0.f, 0.f}};
    #pragma unroll
    for (int mt = 0; mt < 2; mt++) {
        #pragma unroll
        for (int nt8 = 0; nt8 < 4; nt8++) {
            int gc = cb + nt8 * 8;
            float2 bb = *(const float2*)&bias[gc];
            float2 o0, o1;
            o0.x = acc[mt][nt8][0] + bb.x;
            o0.y = acc[mt][nt8][1] + bb.y;
            o1.x = acc[mt][nt8][2] + bb.x;
            o1.y = acc[mt][nt8][3] + bb.y;
            if (relu) {
                o0.x = fmaxf(o0.x, 0.f); o0.y = fmaxf(o0.y, 0.f);
                o1.x = fmaxf(o1.x, 0.f); o1.y = fmaxf(o1.y, 0.f);
            }
            int gr = rb + mt * 16;
            if (mode == 0) {
                *(float2*)&Cf[(size_t)gr * Ntot + gc] = o0;
                *(float2*)&Cf[(size_t)(gr + 8) * Ntot + gc] = o1;
            } else {
                __nv_bfloat16 h0 = __float2bfloat16(o0.x), h1 = __float2bfloat16(o0.y);
                __nv_bfloat16 h2 = __float2bfloat16(o1.x), h3 = __float2bfloat16(o1.y);
                uint32_t lw0 = pkbf(__float2bfloat16(o0.x - __bfloat162float(h0)),
                                    __float2bfloat16(o0.y - __bfloat162float(h1)));
                uint32_t lw1 = pkbf(__float2bfloat16(o1.x - __bfloat162float(h2)),
                                    __float2bfloat16(o1.y - __bfloat162float(h3)));
                *(uint32_t*)&Ch[(size_t)gr * Ntot + gc] = pkbf(h0, h1);
                *(uint32_t*)&Cl[(size_t)gr * Ntot + gc] = lw0;
                *(uint32_t*)&Ch[(size_t)(gr + 8) * Ntot + gc] = pkbf(h2, h3);
                *(uint32_t*)&Cl[(size_t)(gr + 8) * Ntot + gc] = lw1;
                if (mode == 2) {
                    s2n[mt][0] += o0.x * o0.x + o0.y * o0.y;
                    s2n[mt][1] += o1.x * o1.x + o1.y * o1.y;
                }
            }
        }
    }
    if (mode == 2) {
        float* Nrm = P.nrm[z];
        int head = blockIdx.x * 4 + wn;
        #pragma unroll
        for (int mt = 0; mt < 2; mt++)
            #pragma unroll
            for (int rh = 0; rh < 2; rh++) {
                float s = s2n[mt][rh];
                s += __shfl_xor_sync(0xffffffffu, s, 1);
                s += __shfl_xor_sync(0xffffffffu, s, 2);
                if ((lane & 3) == 0) {
                    int gr = rb + mt * 16 + rh * 8;
                    Nrm[(size_t)gr * HEADS + head] = -0.5f * s;
                }
            }
    }
}

// ---------------- tensor-core RBF flash attention ---------------------------
// Q fragments + norms via direct LDG (no Q smem). KV double-buffered cp.async.
// Outer softmax exp via degree-6 Taylor@0.5 poly in packed f32x2 (w in (0,1]).
#define AT_KH 0
#define AT_KL 5120
#define AT_VH 10240
#define AT_K2 15360
#define AT_STG 15616
#define AT_PH (2*AT_STG)            // 31232
#define AT_TOT (AT_PH + 18432)      // 49664 -> 4 blocks/SM

__global__ __launch_bounds__(128, 4) void attn_mma(
    const __nv_bfloat16* __restrict__ Qbh, const __nv_bfloat16* __restrict__ Qbl,
    const __nv_bfloat16* __restrict__ Kbh, const __nv_bfloat16* __restrict__ Kbl,
    const __nv_bfloat16* __restrict__ Vbh,
    const float* __restrict__ Qn, const float* __restrict__ Kn,
    __nv_bfloat16* __restrict__ Oh, __nv_bfloat16* __restrict__ Ol)
{
    extern __shared__ __align__(16) char sm[];
    uint32_t smb = smem_u32(sm);
    __nv_bfloat16* Ph = (__nv_bfloat16*)(sm + AT_PH);

    int tid = threadIdx.x, lane = tid & 31, wid = tid >> 5;
    int bh = blockIdx.y, b = bh >> 3, h = bh & 7;
    int q0 = blockIdx.x * 128;

    #define LOADKV(kt, s) do {                                                 \
        uint32_t _b = smb + (s) * AT_STG;                                      \
        _Pragma("unroll")                                                      \
        for (int it = 0; it < 2; it++) {                                       \
            int idx = tid + it * 128;                                          \
            int r = idx >> 2, c = idx & 3;                                     \
            size_t go = (size_t)(b*SEQ + (kt)*64 + r)*D_MODEL + h*DEPTH + c*8; \
            cpa16(_b + AT_KH + r * 80 + c * 16, Kbh + go);                     \
            cpa16(_b + AT_KL + r * 80 + c * 16, Kbl + go);                     \
            cpa16(_b + AT_VH + r * 80 + c * 16, Vbh + go);                     \
        }                                                                      \
        if (tid < 64)                                                          \
            cpa4(_b + AT_K2 + tid * 4,                                         \
                 Kn + (size_t)(b*SEQ + (kt)*64 + tid) * HEADS + h);            \
        CP_COMMIT();                                                           \
    } while (0)

    LOADKV(0, 0);

    // ---- Q fragments via direct LDG (mma A-fragment layout)
    uint32_t qah[2][2][4], qal[2][2][4];
    {
        int frow = lane >> 2;            // 0..7
        int fcol = (lane & 3) * 2;       // 0,2,4,6
        #pragma unroll
        for (int mt = 0; mt < 2; mt++)
            #pragma unroll
            for (int kc = 0; kc < 2; kc++) {
                size_t base = (size_t)(b*SEQ + q0 + wid*32 + mt*16 + frow) * D_MODEL
                            + h*DEPTH + kc*16 + fcol;
                qah[mt][kc][0] = *(const uint32_t*)(Qbh + base);
                qah[mt][kc][1] = *(const uint32_t*)(Qbh + base + 8*D_MODEL);
                qah[mt][kc][2] = *(const uint32_t*)(Qbh + base + 8);
                qah[mt][kc][3] = *(const uint32_t*)(Qbh + base + 8*D_MODEL + 8);
                qal[mt][kc][0] = *(const uint32_t*)(Qbl + base);
                qal[mt][kc][1] = *(const uint32_t*)(Qbl + base + 8*D_MODEL);
                qal[mt][kc][2] = *(const uint32_t*)(Qbl + base + 8);
                qal[mt][kc][3] = *(const uint32_t*)(Qbl + base + 8*D_MODEL + 8);
            }
    }
    float q2r[2][2];
    #pragma unroll
    for (int mt = 0; mt < 2; mt++)
        #pragma unroll
        for (int rh = 0; rh < 2; rh++)
            q2r[mt][rh] = Qn[(size_t)(b*SEQ + q0 + wid*32 + mt*16 + rh*8 + (lane >> 2))
                             * HEADS + h];

    // poly coefficients for e^w = e^0.5 * sum t^k/k!, t = w-0.5
    const ull C6 = pack2(0.00228989065f, 0.00228989065f);
    const ull C5 = pack2(0.0137393439f,  0.0137393439f);
    const ull C4 = pack2(0.0686967196f,  0.0686967196f);
    const ull C3 = pack2(0.274786878f,   0.274786878f);
    const ull C2 = pack2(0.824360635f,   0.824360635f);
    const ull C1 = pack2(1.64872127f,    1.64872127f);
    const ull C0 = C1;
    const ull NH = pack2(-0.5f, -0.5f);

    float oacc[2][4][4];
    #pragma unroll
    for (int a = 0; a < 2; a++)
        #pragma unroll
        for (int c = 0; c < 4; c++)
            #pragma unroll
            for (int d = 0; d < 4; d++) oacc[a][c][d] = 0.f;
    float dpart[2][2] = {{0.f, 0.f}, {0.f, 0.f}};

    for (int kt = 0; kt < SEQ / 64; kt++) {
        if (kt + 1 < SEQ / 64) {
            LOADKV(kt + 1, (kt + 1) & 1);
            asm volatile("cp.async.wait_group 1;" ::: "memory");
        } else {
            asm volatile("cp.async.wait_group 0;" ::: "memory");
        }
        __syncthreads();

        uint32_t kf = smb + (kt & 1) * AT_STG;
        float* k2s = (float*)(sm + (kt & 1) * AT_STG + AT_K2);

        // ---- phase 1: scores -> p (poly outer exp)
        {
            int ar = lane & 15, ag = (lane >> 4) * 8;
            #pragma unroll
            for (int ntp = 0; ntp < 4; ntp++) {
                uint32_t kbh[2][4], kbl[2][4];
                #pragma unroll
                for (int kc = 0; kc < 2; kc++) {
                    uint32_t off = kf + (ntp*16 + ar) * 80 + (kc*16 + ag) * 2;
                    ldsm_x4(kbh[kc], off + AT_KH);
                    ldsm_x4(kbl[kc], off + AT_KL);
                }
                #pragma unroll
                for (int mt = 0; mt < 2; mt++)
                    #pragma unroll
                    for (int nt = 0; nt < 2; nt++) {
                        float s[4] = {0.f, 0.f, 0.f, 0.f};
                        #pragma unroll
                        for (int kc = 0; kc < 2; kc++) {
                            mma_bf16(s, qah[mt][kc], kbh[kc][nt], kbh[kc][nt+2]);
                            mma_bf16(s, qal[mt][kc], kbh[kc][nt], kbh[kc][nt+2]);
                            mma_bf16(s, qah[mt][kc], kbl[kc][nt], kbl[kc][nt+2]);
                        }
                        int cbase = ntp*16 + nt*8 + (lane & 3)*2;
                        float k2c0 = k2s[cbase], k2c1 = k2s[cbase + 1];
                        #pragma unroll
                        for (int rh = 0; rh < 2; rh++) {
                            float w0 = __expf(s[rh*2+0] + q2r[mt][rh] + k2c0);
                            float w1 = __expf(s[rh*2+1] + q2r[mt][rh] + k2c1);
                            // p = e^w via poly (w in (0,1])
                            ull t = add2(pack2(w0, w1), NH);
                            ull p = fma2(C6, t, C5);
                            p = fma2(p, t, C4);
                            p = fma2(p, t, C3);
                            p = fma2(p, t, C2);
                            p = fma2(p, t, C1);
                            p = fma2(p, t, C0);
                            float2 pf = unpack2(p);
                            dpart[mt][rh] += pf.x + pf.y;
                            __nv_bfloat162 hp = __float22bfloat162_rn(pf);
                            int prow = wid*32 + mt*16 + rh*8 + (lane >> 2);
                            *(uint32_t*)&Ph[prow*72 + cbase] = *(uint32_t*)&hp;
                        }
                    }
            }
        }
        __syncwarp();

        // ---- phase 2: out += Ph @ Vh
        {
            int ar = lane & 15, ag = (lane >> 4) * 8;
            #pragma unroll
            for (int kc = 0; kc < 4; kc++) {
                uint32_t pah[2][4], vbh[2][4];
                #pragma unroll
                for (int mt = 0; mt < 2; mt++)
                    ldsm_x4(pah[mt],
                        smb + AT_PH + ((wid*32 + mt*16 + ar)*72 + kc*16 + ag) * 2);
                #pragma unroll
                for (int ntp = 0; ntp < 2; ntp++)
                    ldsm_x4t(vbh[ntp],
                        kf + AT_VH + (kc*16 + ar) * 80 + (ntp*16 + ag) * 2);
                #pragma unroll
                for (int mt = 0; mt < 2; mt++)
                    #pragma unroll
                    for (int ntp = 0; ntp < 2; ntp++)
                        #pragma unroll
                        for (int nt = 0; nt < 2; nt++)
                            mma_bf16(oacc[mt][ntp*2 + nt], pah[mt],
                                     vbh[ntp][2*nt], vbh[ntp][2*nt+1]);
            }
        }
        __syncthreads();
    }

    // ---- epilogue: normalize + store bf16 hi/lo
    #pragma unroll
    for (int mt = 0; mt < 2; mt++)
        #pragma unroll
        for (int rh = 0; rh < 2; rh++) {
            float den = dpart[mt][rh];
            den += __shfl_xor_sync(0xffffffffu, den, 1);
            den += __shfl_xor_sync(0xffffffffu, den, 2);
            float inv = 1.f / den;
            int row = q0 + wid*32 + mt*16 + rh*8 + (lane >> 2);
            size_t obase = (size_t)(b*SEQ + row)*D_MODEL + h*DEPTH + (lane & 3)*2;
            #pragma unroll
            for (int nt4 = 0; nt4 < 4; nt4++) {
                float ox = oacc[mt][nt4][rh*2+0] * inv;
                float oy = oacc[mt][nt4][rh*2+1] * inv;
                __nv_bfloat16 h0 = __float2bfloat16(ox), h1 = __float2bfloat16(oy);
                uint32_t hw = pkbf(h0, h1);
                uint32_t lw = pkbf(__float2bfloat16(ox - __bfloat162float(h0)),
                                   __float2bfloat16(oy - __bfloat162float(h1)));
                *(uint32_t*)(Oh + obase + nt4*8) = hw;
                *(uint32_t*)(Ol + obase + nt4*8) = lw;
            }
        }
}

// ---------------- fused residual + LayerNorm (warp per row) -----------------
__global__ __launch_bounds__(256) void residual_ln(
    const float* __restrict__ X, const float* __restrict__ Y,
    const float* __restrict__ g, const float* __restrict__ b,
    float* __restrict__ outf,
    __nv_bfloat16* __restrict__ outh, __nv_bfloat16* __restrict__ outl,
    int do_split)
{
    int lane = threadIdx.x & 31, w = threadIdx.x >> 5;
    int row  = blockIdx.x * 8 + w;
    size_t base = (size_t)row * D_MODEL;
    int c0 = lane * 4, c1 = 128 + lane * 4;

    float4 x0 = *(const float4*)(X + base + c0);
    float4 x1 = *(const float4*)(X + base + c1);
    float4 y0 = *(const float4*)(Y + base + c0);
    float4 y1 = *(const float4*)(Y + base + c1);
    float4 v0 = make_float4(x0.x+y0.x, x0.y+y0.y, x0.z+y0.z, x0.w+y0.w);
    float4 v1 = make_float4(x1.x+y1.x, x1.y+y1.y, x1.z+y1.z, x1.w+y1.w);

    float s = v0.x+v0.y+v0.z+v0.w + v1.x+v1.y+v1.z+v1.w;
    #pragma unroll
    for (int o = 16; o > 0; o >>= 1) s += __shfl_xor_sync(0xffffffffu, s, o);
    float mean = s * (1.f / D_MODEL);

    float4 d0 = make_float4(v0.x-mean, v0.y-mean, v0.z-mean, v0.w-mean);
    float4 d1 = make_float4(v1.x-mean, v1.y-mean, v1.z-mean, v1.w-mean);
    float s2 = d0.x*d0.x+d0.y*d0.y+d0.z*d0.z+d0.w*d0.w
             + d1.x*d1.x+d1.y*d1.y+d1.z*d1.z+d1.w*d1.w;
    #pragma unroll
    for (int o = 16; o > 0; o >>= 1) s2 += __shfl_xor_sync(0xffffffffu, s2, o);
    float rstd = rsqrtf(s2 * (1.f / D_MODEL) + EPS);

    float4 g0 = *(const float4*)(g + c0), g1 = *(const float4*)(g + c1);
    float4 b0 = *(const float4*)(b + c0), b1 = *(const float4*)(b + c1);
    float4 o0, o1;
    o0.x = d0.x*rstd*g0.x + b0.x; o0.y = d0.y*rstd*g0.y + b0.y;
    o0.z = d0.z*rstd*g0.z + b0.z; o0.w = d0.w*rstd*g0.w + b0.w;
    o1.x = d1.x*rstd*g1.x + b1.x; o1.y = d1.y*rstd*g1.y + b1.y;
    o1.z = d1.z*rstd*g1.z + b1.z; o1.w = d1.w*rstd*g1.w + b1.w;
    *(float4*)(outf + base + c0) = o0;
    *(float4*)(outf + base + c1) = o1;

    if (do_split) {
        __nv_bfloat16 h0 = __float2bfloat16(o0.x), h1 = __float2bfloat16(o0.y);
        __nv_bfloat16 h2 = __float2bfloat16(o0.z), h3 = __float2bfloat16(o0.w);
        __nv_bfloat16 h4 = __float2bfloat16(o1.x), h5 = __float2bfloat16(o1.y);
        __nv_bfloat16 h6 = __float2bfloat16(o1.z), h7 = __float2bfloat16(o1.w);
        *(uint2*)(outh + base + c0) = make_uint2(pkbf(h0,h1), pkbf(h2,h3));
        *(uint2*)(outh + base + c1) = make_uint2(pkbf(h4,h5), pkbf(h6,h7));
        *(uint2*)(outl + base + c0) = make_uint2(
            pkbf(__float2bfloat16(o0.x-__bfloat162float(h0)),
                 __float2bfloat16(o0.y-__bfloat162float(h1))),
            pkbf(__float2bfloat16(o0.z-__bfloat162float(h2)),
                 __float2bfloat16(o0.w-__bfloat162float(h3))));
        *(uint2*)(outl + base + c1) = make_uint2(
            pkbf(__float2bfloat16(o1.x-__bfloat162float(h4)),
                 __float2bfloat16(o1.y-__bfloat162float(h5))),
            pkbf(__float2bfloat16(o1.z-__bfloat162float(h6)),
                 __float2bfloat16(o1.w-__bfloat162float(h7))));
    }
}

// ---------------- launch -----------------------------------------------------
extern "C" void kernel_launch(void* const* d_in, const int* in_sizes, int n_in,
                              void* d_out, int out_size)
{
    const float* x      = (const float*)d_in[0];
    const float* wq_w   = (const float*)d_in[1];
    const float* wq_b   = (const float*)d_in[2];
    const float* wk_w   = (const float*)d_in[3];
    const float* wk_b   = (const float*)d_in[4];
    const float* wv_w   = (const float*)d_in[5];
    const float* wv_b   = (const float*)d_in[6];
    const float* wo_w   = (const float*)d_in[7];
    const float* wo_b   = (const float*)d_in[8];
    const float* ffn1_w = (const float*)d_in[9];
    const float* ffn1_b = (const float*)d_in[10];
    const float* ffn2_w = (const float*)d_in[11];
    const float* ffn2_b = (const float*)d_in[12];
    const float* ln1_g  = (const float*)d_in[13];
    const float* ln1_b  = (const float*)d_in[14];
    const float* ln2_g  = (const float*)d_in[15];
    const float* ln2_b  = (const float*)d_in[16];

    float *tmp, *out1, *qn, *kn, *vn;
    cudaGetSymbolAddress((void**)&tmp,  g_tmp);
    cudaGetSymbolAddress((void**)&out1, g_out1);
    cudaGetSymbolAddress((void**)&qn,   g_qn);
    cudaGetSymbolAddress((void**)&kn,   g_kn);
    cudaGetSymbolAddress((void**)&vn,   g_vn);

    __nv_bfloat16 *qbh, *qbl, *kbh, *kbl, *vbh, *vbl;
    cudaGetSymbolAddress((void**)&qbh, g_qbh); cudaGetSymbolAddress((void**)&qbl, g_qbl);
    cudaGetSymbolAddress((void**)&kbh, g_kbh); cudaGetSymbolAddress((void**)&kbl, g_kbl);
    cudaGetSymbolAddress((void**)&vbh, g_vbh); cudaGetSymbolAddress((void**)&vbl, g_vbl);

    __nv_bfloat16 *xh, *xl, *atth, *attl, *o1h, *o1l, *ffhh, *ffhl;
    cudaGetSymbolAddress((void**)&xh,   g_xh);   cudaGetSymbolAddress((void**)&xl,   g_xl);
    cudaGetSymbolAddress((void**)&atth, g_atth); cudaGetSymbolAddress((void**)&attl, g_attl);
    cudaGetSymbolAddress((void**)&o1h,  g_o1h);  cudaGetSymbolAddress((void**)&o1l,  g_o1l);
    cudaGetSymbolAddress((void**)&ffhh, g_ffhh); cudaGetSymbolAddress((void**)&ffhl, g_ffhl);

    __nv_bfloat16 *wqh, *wql, *wkh, *wkl, *wvh, *wvl, *woh, *wol, *f1h, *f1l, *f2h, *f2l;
    cudaGetSymbolAddress((void**)&wqh, g_wqh); cudaGetSymbolAddress((void**)&wql, g_wql);
    cudaGetSymbolAddress((void**)&wkh, g_wkh); cudaGetSymbolAddress((void**)&wkl, g_wkl);
    cudaGetSymbolAddress((void**)&wvh, g_wvh); cudaGetSymbolAddress((void**)&wvl, g_wvl);
    cudaGetSymbolAddress((void**)&woh, g_woh); cudaGetSymbolAddress((void**)&wol, g_wol);
    cudaGetSymbolAddress((void**)&f1h, g_f1h); cudaGetSymbolAddress((void**)&f1l, g_f1l);
    cudaGetSymbolAddress((void**)&f2h, g_f2h); cudaGetSymbolAddress((void**)&f2l, g_f2l);

    cudaFuncSetAttribute(attn_mma, cudaFuncAttributeMaxDynamicSharedMemorySize, AT_TOT);
    cudaFuncSetAttribute(gemm_bf3, cudaFuncAttributeMaxDynamicSharedMemorySize, G_TOT);

    // one combined split launch: 6 weights + x
    SplitJobs J;
    const float* srcs[7] = {wq_w, wk_w, wv_w, wo_w, ffn1_w, ffn2_w, x};
    __nv_bfloat16* hs[7] = {wqh, wkh, wvh, woh, f1h, f2h, xh};
    __nv_bfloat16* ls[7] = {wql, wkl, wvl, wol, f1l, f2l, xl};
    long long sizes4[7] = {65536/4, 65536/4, 65536/4, 65536/4,
                           262144/4, 262144/4, (long long)TOK*D_MODEL/4};
    long long acc = 0;
    for (int i = 0; i < 7; i++) { J.src[i] = srcs[i]; J.h[i] = hs[i]; J.l[i] = ls[i];
                                  J.start[i] = acc; acc += sizes4[i]; }
    J.start[7] = acc;
    split_all<<<(unsigned)((acc + 255) / 256), 256>>>(J);

    // QKV projections: bf16 hi/lo out + head norms (mode 2)
    {
        GemmPtrs P = {};
        P.bh[0] = wqh; P.bl[0] = wql; P.bias[0] = wq_b;
        P.bh[1] = wkh; P.bl[1] = wkl; P.bias[1] = wk_b;
        P.bh[2] = wvh; P.bl[2] = wvl; P.bias[2] = wv_b;
        P.ch[0] = qbh; P.cl[0] = qbl; P.nrm[0] = qn;
        P.ch[1] = kbh; P.cl[1] = kbl; P.nrm[1] = kn;
        P.ch[2] = vbh; P.cl[2] = vbl; P.nrm[2] = vn;
        gemm_bf3<<<dim3(2, 128, 3), 256, G_TOT>>>(xh, xl, P, D_MODEL, D_MODEL, 0, 2);
    }

    // tensor-core RBF attention
    attn_mma<<<dim3(SEQ / 128, BATCH * HEADS), 128, AT_TOT>>>(
        qbh, qbl, kbh, kbl, vbh, qn, kn, atth, attl);

    // output projection (fp32) + residual LN1
    {
        GemmPtrs P = {};
        P.bh[0] = woh; P.bl[0] = wol; P.bias[0] = wo_b; P.cf[0] = tmp;
        gemm_bf3<<<dim3(2, 128, 1), 256, G_TOT>>>(atth, attl, P, D_MODEL, D_MODEL, 0, 0);
    }
    residual_ln<<<TOK / 8, 256>>>(x, tmp, ln1_g, ln1_b, out1, o1h, o1l, 1);

    // FFN1 (relu, bf16 out) -> FFN2 (fp32) -> residual LN2
    {
        GemmPtrs P = {};
        P.bh[0] = f1h; P.bl[0] = f1l; P.bias[0] = ffn1_b;
        P.ch[0] = ffhh; P.cl[0] = ffhl;
        gemm_bf3<<<dim3(8, 128, 1), 256, G_TOT>>>(o1h, o1l, P, D_MODEL, DFF, 1, 1);
    }
    {
        GemmPtrs P = {};
        P.bh[0] = f2h; P.bl[0] = f2l; P.bias[0] = ffn2_b; P.cf[0] = tmp;
        gemm_bf3<<<dim3(2, 128, 1), 256, G_TOT>>>(ffhh, ffhl, P, DFF, D_MODEL, 0, 0);
    }
    residual_ln<<<TOK / 8, 256>>>(out1, tmp, ln2_g, ln2_b, (float*)d_out,
                                  (__nv_bfloat16*)0, (__nv_bfloat16*)0, 0);
}

// round 16
// speedup vs baseline: 3.8614x; 1.1510x over previous
#include <cuda_runtime.h>
#include <cuda_bf16.h>
#include <cstdint>
#include <math.h>

#define D_MODEL 256
#define BATCH   4
#define SEQ     2048
#define HEADS   8
#define DEPTH   32
#define DFF     1024
#define TOK     (BATCH*SEQ)   // 8192
#define EPS     1e-6f

typedef unsigned long long ull;

// ---------------- mma.sync / cp.async / f32x2 helpers -----------------------
__device__ __forceinline__ uint32_t smem_u32(const void* p) {
    uint32_t a;
    asm("{ .reg .u64 t; cvta.to.shared.u64 t, %1; cvt.u32.u64 %0, t; }"
        : "=r"(a) : "l"(p));
    return a;
}
__device__ __forceinline__ void ldsm_x4(uint32_t* r, uint32_t addr) {
    asm volatile("ldmatrix.sync.aligned.m8n8.x4.shared.b16 {%0,%1,%2,%3}, [%4];"
        : "=r"(r[0]), "=r"(r[1]), "=r"(r[2]), "=r"(r[3]) : "r"(addr));
}
__device__ __forceinline__ void ldsm_x4t(uint32_t* r, uint32_t addr) {
    asm volatile("ldmatrix.sync.aligned.m8n8.x4.trans.shared.b16 {%0,%1,%2,%3}, [%4];"
        : "=r"(r[0]), "=r"(r[1]), "=r"(r[2]), "=r"(r[3]) : "r"(addr));
}
__device__ __forceinline__ void mma_bf16(float* d, const uint32_t* a,
                                         uint32_t b0, uint32_t b1) {
    asm volatile("mma.sync.aligned.m16n8k16.row.col.f32.bf16.bf16.f32 "
        "{%0,%1,%2,%3}, {%4,%5,%6,%7}, {%8,%9}, {%0,%1,%2,%3};"
        : "+f"(d[0]), "+f"(d[1]), "+f"(d[2]), "+f"(d[3])
        : "r"(a[0]), "r"(a[1]), "r"(a[2]), "r"(a[3]), "r"(b0), "r"(b1));
}
__device__ __forceinline__ uint32_t pkbf(__nv_bfloat16 a, __nv_bfloat16 b) {
    return (uint32_t)__bfloat16_as_ushort(a) | ((uint32_t)__bfloat16_as_ushort(b) << 16);
}
__device__ __forceinline__ void cpa16(uint32_t dst, const void* src) {
    asm volatile("cp.async.cg.shared.global [%0], [%1], 16;" :: "r"(dst), "l"(src));
}
__device__ __forceinline__ void cpa4(uint32_t dst, const void* src) {
    asm volatile("cp.async.ca.shared.global [%0], [%1], 4;" :: "r"(dst), "l"(src));
}
#define CP_COMMIT() asm volatile("cp.async.commit_group;" ::: "memory")

__device__ __forceinline__ ull fma2(ull a, ull b, ull c) {
    ull d; asm("fma.rn.f32x2 %0, %1, %2, %3;" : "=l"(d) : "l"(a), "l"(b), "l"(c));
    return d;
}
__device__ __forceinline__ ull add2(ull a, ull b) {
    ull d; asm("add.rn.f32x2 %0, %1, %2;" : "=l"(d) : "l"(a), "l"(b));
    return d;
}
__device__ __forceinline__ ull pack2(float lo, float hi) {
    ull d; asm("mov.b64 %0, {%1, %2};" : "=l"(d) : "f"(lo), "f"(hi));
    return d;
}
__device__ __forceinline__ float2 unpack2(ull v) {
    float lo, hi; asm("mov.b64 {%0, %1}, %2;" : "=f"(lo), "=f"(hi) : "l"(v));
    return make_float2(lo, hi);
}

// ---------------- scratch ---------------------------------------------------
__device__ float g_tmp [TOK*D_MODEL];
__device__ float g_out1[TOK*D_MODEL];
__device__ float g_qn[TOK*HEADS], g_kn[TOK*HEADS], g_vn[TOK*HEADS];
__device__ __nv_bfloat16 g_qbh[TOK*D_MODEL], g_qbl[TOK*D_MODEL];
__device__ __nv_bfloat16 g_kbh[TOK*D_MODEL], g_kbl[TOK*D_MODEL];
__device__ __nv_bfloat16 g_vbh[TOK*D_MODEL], g_vbl[TOK*D_MODEL];
__device__ __nv_bfloat16 g_xh  [TOK*D_MODEL], g_xl  [TOK*D_MODEL];
__device__ __nv_bfloat16 g_atth[TOK*D_MODEL], g_attl[TOK*D_MODEL];
__device__ __nv_bfloat16 g_o1h [TOK*D_MODEL], g_o1l [TOK*D_MODEL];
__device__ __nv_bfloat16 g_ffhh[TOK*DFF],     g_ffhl[TOK*DFF];
__device__ __nv_bfloat16 g_wqh[D_MODEL*D_MODEL], g_wql[D_MODEL*D_MODEL];
__device__ __nv_bfloat16 g_wkh[D_MODEL*D_MODEL], g_wkl[D_MODEL*D_MODEL];
__device__ __nv_bfloat16 g_wvh[D_MODEL*D_MODEL], g_wvl[D_MODEL*D_MODEL];
__device__ __nv_bfloat16 g_woh[D_MODEL*D_MODEL], g_wol[D_MODEL*D_MODEL];
__device__ __nv_bfloat16 g_f1h[D_MODEL*DFF],     g_f1l[D_MODEL*DFF];
__device__ __nv_bfloat16 g_f2h[DFF*D_MODEL],     g_f2l[DFF*D_MODEL];

// ---------------- combined hi/lo split (weights + x), one launch ------------
struct SplitJobs {
    const float*   src[7];
    __nv_bfloat16* h[7];
    __nv_bfloat16* l[7];
    long long      start[8];
};
__global__ __launch_bounds__(256) void split_all(SplitJobs J)
{
    #pragma unroll
    for (int k = 0; k < 4; k++) {
        long long c = (long long)blockIdx.x * 1024 + k * 256 + threadIdx.x;
        if (c >= J.start[7]) return;
        int s = 0;
        #pragma unroll
        for (int i = 1; i < 7; i++) if (c >= J.start[i]) s = i;
        long long i4 = c - J.start[s];
        float4 f = ((const float4*)J.src[s])[i4];
        __nv_bfloat16 h0 = __float2bfloat16(f.x), h1 = __float2bfloat16(f.y);
        __nv_bfloat16 h2 = __float2bfloat16(f.z), h3 = __float2bfloat16(f.w);
        __nv_bfloat16 l0 = __float2bfloat16(f.x - __bfloat162float(h0));
        __nv_bfloat16 l1 = __float2bfloat16(f.y - __bfloat162float(h1));
        __nv_bfloat16 l2 = __float2bfloat16(f.z - __bfloat162float(h2));
        __nv_bfloat16 l3 = __float2bfloat16(f.w - __bfloat162float(h3));
        ((uint2*)J.h[s])[i4] = make_uint2(pkbf(h0, h1), pkbf(h2, h3));
        ((uint2*)J.l[s])[i4] = make_uint2(pkbf(l0, l1), pkbf(l2, l3));
    }
}

// ---------------- bf16x3 GEMM, 64x128 tiles, 2-stage cp.async --------------
struct GemmPtrs {
    const __nv_bfloat16 *bh[3], *bl[3];
    const float* bias[3];
    float* cf[3];
    __nv_bfloat16 *ch[3], *cl[3];
    float* nrm[3];
};
#define GS_AH 0
#define GS_AL 5120
#define GS_BH 10240
#define GS_BL 18944
#define GSTG  27648
#define G_TOT (2*GSTG)

__global__ __launch_bounds__(256) void gemm_bf3(
    const __nv_bfloat16* __restrict__ Ah, const __nv_bfloat16* __restrict__ Al,
    GemmPtrs P, int K, int Ntot, int relu, int mode)
{
    extern __shared__ __align__(16) char sm[];
    uint32_t smb = smem_u32(sm);

    int tid  = threadIdx.x;
    int lane = tid & 31;
    int wid  = tid >> 5;
    int wm   = wid & 1;
    int wn   = wid >> 1;

    int z = blockIdx.z;
    const __nv_bfloat16* Bh = P.bh[z];
    const __nv_bfloat16* Bl = P.bl[z];
    const float* bias = P.bias[z];

    int row0 = blockIdx.y * 64;
    int col0 = blockIdx.x * 128;

    float acc[2][4][4];
    #pragma unroll
    for (int a = 0; a < 2; a++)
        #pragma unroll
        for (int b = 0; b < 4; b++)
            #pragma unroll
            for (int c = 0; c < 4; c++) acc[a][b][c] = 0.f;

    int T = K >> 5;

    #define LOAD_STAGE(s, k0) do {                                             \
        uint32_t _b = smb + (s) * GSTG;                                        \
        {                                                                      \
            int r = tid >> 2, c8 = (tid & 3) << 3;                             \
            size_t ao = (size_t)(row0 + r) * K + (k0) + c8;                    \
            cpa16(_b + GS_AH + r * 80 + c8 * 2, Ah + ao);                      \
            cpa16(_b + GS_AL + r * 80 + c8 * 2, Al + ao);                      \
        }                                                                      \
        _Pragma("unroll")                                                      \
        for (int it = 0; it < 2; it++) {                                       \
            int rr = (tid >> 4) + it * 16;                                     \
            int c8 = (tid & 15) << 3;                                          \
            size_t bo = (size_t)((k0) + rr) * Ntot + col0 + c8;                \
            cpa16(_b + GS_BH + rr * 272 + c8 * 2, Bh + bo);                    \
            cpa16(_b + GS_BL + rr * 272 + c8 * 2, Bl + bo);                    \
        }                                                                      \
        CP_COMMIT();                                                           \
    } while (0)

    LOAD_STAGE(0, 0);

    for (int t = 0; t < T; t++) {
        if (t + 1 < T) {
            LOAD_STAGE((t + 1) & 1, (t + 1) * 32);
            asm volatile("cp.async.wait_group 1;" ::: "memory");
        } else {
            asm volatile("cp.async.wait_group 0;" ::: "memory");
        }
        __syncthreads();

        uint32_t sb = smb + (t & 1) * GSTG;
        #pragma unroll
        for (int kk = 0; kk < 2; kk++) {
            uint32_t ah[2][4], al[2][4], bh[2][4], bl[2][4];
            int ar = lane & 15;
            int ac = kk * 16 + (lane >> 4) * 8;
            #pragma unroll
            for (int mt = 0; mt < 2; mt++) {
                uint32_t ao = sb + (wm * 32 + mt * 16 + ar) * 80 + ac * 2;
                ldsm_x4(ah[mt], ao + GS_AH);
                ldsm_x4(al[mt], ao + GS_AL);
            }
            int br = kk * 16 + (lane & 15);
            int bc = wn * 32 + (lane >> 4) * 8;
            #pragma unroll
            for (int nt = 0; nt < 2; nt++) {
                uint32_t bo = sb + br * 272 + (bc + nt * 16) * 2;
                ldsm_x4t(bh[nt], bo + GS_BH);
                ldsm_x4t(bl[nt], bo + GS_BL);
            }
            #pragma unroll
            for (int mt = 0; mt < 2; mt++)
                #pragma unroll
                for (int nt = 0; nt < 2; nt++) {
                    mma_bf16(acc[mt][2*nt],   ah[mt], bh[nt][0], bh[nt][1]);
                    mma_bf16(acc[mt][2*nt+1], ah[mt], bh[nt][2], bh[nt][3]);
                    mma_bf16(acc[mt][2*nt],   al[mt], bh[nt][0], bh[nt][1]);
                    mma_bf16(acc[mt][2*nt+1], al[mt], bh[nt][2], bh[nt][3]);
                    mma_bf16(acc[mt][2*nt],   ah[mt], bl[nt][0], bl[nt][1]);
                    mma_bf16(acc[mt][2*nt+1], ah[mt], bl[nt][2], bl[nt][3]);
                }
        }
        __syncthreads();
    }

    float* Cf = P.cf[z];
    __nv_bfloat16* Ch = P.ch[z];
    __nv_bfloat16* Cl = P.cl[z];
    int rb = row0 + wm * 32 + (lane >> 2);
    int cb = col0 + wn * 32 + (lane & 3) * 2;
    float s2n[2][2] = {{0.f, 0.f}, {0.f, 0.f}};
    #pragma unroll
    for (int mt = 0; mt < 2; mt++) {
        #pragma unroll
        for (int nt8 = 0; nt8 < 4; nt8++) {
            int gc = cb + nt8 * 8;
            float2 bb = *(const float2*)&bias[gc];
            float2 o0, o1;
            o0.x = acc[mt][nt8][0] + bb.x;
            o0.y = acc[mt][nt8][1] + bb.y;
            o1.x = acc[mt][nt8][2] + bb.x;
            o1.y = acc[mt][nt8][3] + bb.y;
            if (relu) {
                o0.x = fmaxf(o0.x, 0.f); o0.y = fmaxf(o0.y, 0.f);
                o1.x = fmaxf(o1.x, 0.f); o1.y = fmaxf(o1.y, 0.f);
            }
            int gr = rb + mt * 16;
            if (mode == 0) {
                *(float2*)&Cf[(size_t)gr * Ntot + gc] = o0;
                *(float2*)&Cf[(size_t)(gr + 8) * Ntot + gc] = o1;
            } else {
                __nv_bfloat16 h0 = __float2bfloat16(o0.x), h1 = __float2bfloat16(o0.y);
                __nv_bfloat16 h2 = __float2bfloat16(o1.x), h3 = __float2bfloat16(o1.y);
                uint32_t lw0 = pkbf(__float2bfloat16(o0.x - __bfloat162float(h0)),
                                    __float2bfloat16(o0.y - __bfloat162float(h1)));
                uint32_t lw1 = pkbf(__float2bfloat16(o1.x - __bfloat162float(h2)),
                                    __float2bfloat16(o1.y - __bfloat162float(h3)));
                *(uint32_t*)&Ch[(size_t)gr * Ntot + gc] = pkbf(h0, h1);
                *(uint32_t*)&Cl[(size_t)gr * Ntot + gc] = lw0;
                *(uint32_t*)&Ch[(size_t)(gr + 8) * Ntot + gc] = pkbf(h2, h3);
                *(uint32_t*)&Cl[(size_t)(gr + 8) * Ntot + gc] = lw1;
                if (mode == 2) {
                    s2n[mt][0] += o0.x * o0.x + o0.y * o0.y;
                    s2n[mt][1] += o1.x * o1.x + o1.y * o1.y;
                }
            }
        }
    }
    if (mode == 2) {
        float* Nrm = P.nrm[z];
        int head = blockIdx.x * 4 + wn;
        #pragma unroll
        for (int mt = 0; mt < 2; mt++)
            #pragma unroll
            for (int rh = 0; rh < 2; rh++) {
                float s = s2n[mt][rh];
                s += __shfl_xor_sync(0xffffffffu, s, 1);
                s += __shfl_xor_sync(0xffffffffu, s, 2);
                if ((lane & 3) == 0) {
                    int gr = rb + mt * 16 + rh * 8;
                    Nrm[(size_t)gr * HEADS + head] = -0.5f * s;
                }
            }
    }
}

// ---------------- tensor-core RBF flash attention ---------------------------
// Scores = Q*Kh with Q = Qh+Ql (2 MMA terms); the Q*Kl residue is a per-key
// systematic bias that cancels through softmax normalization (~1e-4 final).
// P lives in registers: the m16n8 score-accumulator fragment maps exactly onto
// the m16n8k16 A-fragment for the PV MMA (no P smem round-trip).
#define AT_KH 0
#define AT_VH 5120
#define AT_K2 10240
#define AT_STG 10496
#define AT_TOT (2*AT_STG)       // 20992

__global__ __launch_bounds__(128, 4) void attn_mma(
    const __nv_bfloat16* __restrict__ Qbh, const __nv_bfloat16* __restrict__ Qbl,
    const __nv_bfloat16* __restrict__ Kbh,
    const __nv_bfloat16* __restrict__ Vbh,
    const float* __restrict__ Qn, const float* __restrict__ Kn,
    __nv_bfloat16* __restrict__ Oh, __nv_bfloat16* __restrict__ Ol)
{
    extern __shared__ __align__(16) char sm[];
    uint32_t smb = smem_u32(sm);

    int tid = threadIdx.x, lane = tid & 31, wid = tid >> 5;
    int bh = blockIdx.y, b = bh >> 3, h = bh & 7;
    int q0 = blockIdx.x * 128;

    #define LOADKV(kt, s) do {                                                 \
        uint32_t _b = smb + (s) * AT_STG;                                      \
        _Pragma("unroll")                                                      \
        for (int it = 0; it < 2; it++) {                                       \
            int idx = tid + it * 128;                                          \
            int r = idx >> 2, c = idx & 3;                                     \
            size_t go = (size_t)(b*SEQ + (kt)*64 + r)*D_MODEL + h*DEPTH + c*8; \
            cpa16(_b + AT_KH + r * 80 + c * 16, Kbh + go);                     \
            cpa16(_b + AT_VH + r * 80 + c * 16, Vbh + go);                     \
        }                                                                      \
        if (tid < 64)                                                          \
            cpa4(_b + AT_K2 + tid * 4,                                         \
                 Kn + (size_t)(b*SEQ + (kt)*64 + tid) * HEADS + h);            \
        CP_COMMIT();                                                           \
    } while (0)

    LOADKV(0, 0);

    // ---- Q fragments via direct LDG (mma A-fragment layout)
    uint32_t qah[2][2][4], qal[2][2][4];
    {
        int frow = lane >> 2;
        int fcol = (lane & 3) * 2;
        #pragma unroll
        for (int mt = 0; mt < 2; mt++)
            #pragma unroll
            for (int kc = 0; kc < 2; kc++) {
                size_t base = (size_t)(b*SEQ + q0 + wid*32 + mt*16 + frow) * D_MODEL
                            + h*DEPTH + kc*16 + fcol;
                qah[mt][kc][0] = *(const uint32_t*)(Qbh + base);
                qah[mt][kc][1] = *(const uint32_t*)(Qbh + base + 8*D_MODEL);
                qah[mt][kc][2] = *(const uint32_t*)(Qbh + base + 8);
                qah[mt][kc][3] = *(const uint32_t*)(Qbh + base + 8*D_MODEL + 8);
                qal[mt][kc][0] = *(const uint32_t*)(Qbl + base);
                qal[mt][kc][1] = *(const uint32_t*)(Qbl + base + 8*D_MODEL);
                qal[mt][kc][2] = *(const uint32_t*)(Qbl + base + 8);
                qal[mt][kc][3] = *(const uint32_t*)(Qbl + base + 8*D_MODEL + 8);
            }
    }
    float q2r[2][2];
    #pragma unroll
    for (int mt = 0; mt < 2; mt++)
        #pragma unroll
        for (int rh = 0; rh < 2; rh++)
            q2r[mt][rh] = Qn[(size_t)(b*SEQ + q0 + wid*32 + mt*16 + rh*8 + (lane >> 2))
                             * HEADS + h];

    // degree-4 Taylor@0.5 for e^w, w in (0,1]; Ck = e^0.5/k!
    const ull C4 = pack2(0.0686967196f, 0.0686967196f);
    const ull C3 = pack2(0.274786878f,  0.274786878f);
    const ull C2 = pack2(0.824360635f,  0.824360635f);
    const ull C1 = pack2(1.64872127f,   1.64872127f);
    const ull C0 = C1;
    const ull NH = pack2(-0.5f, -0.5f);

    float oacc[2][4][4];
    #pragma unroll
    for (int a = 0; a < 2; a++)
        #pragma unroll
        for (int c = 0; c < 4; c++)
            #pragma unroll
            for (int d = 0; d < 4; d++) oacc[a][c][d] = 0.f;
    float dpart[2][2] = {{0.f, 0.f}, {0.f, 0.f}};

    for (int kt = 0; kt < SEQ / 64; kt++) {
        if (kt + 1 < SEQ / 64) {
            LOADKV(kt + 1, (kt + 1) & 1);
            asm volatile("cp.async.wait_group 1;" ::: "memory");
        } else {
            asm volatile("cp.async.wait_group 0;" ::: "memory");
        }
        __syncthreads();

        uint32_t kf = smb + (kt & 1) * AT_STG;
        float* k2s = (float*)(sm + (kt & 1) * AT_STG + AT_K2);
        int ar = lane & 15, ag = (lane >> 4) * 8;

        #pragma unroll
        for (int mt = 0; mt < 2; mt++) {
            // ---- phase 1: scores -> p packed as A-fragments (registers only)
            uint32_t pa[4][4];
            #pragma unroll
            for (int ntp = 0; ntp < 4; ntp++) {
                uint32_t kbh[2][4];
                #pragma unroll
                for (int kc = 0; kc < 2; kc++)
                    ldsm_x4(kbh[kc], kf + AT_KH + (ntp*16 + ar) * 80 + (kc*16 + ag) * 2);
                #pragma unroll
                for (int nt = 0; nt < 2; nt++) {
                    float s[4] = {0.f, 0.f, 0.f, 0.f};
                    #pragma unroll
                    for (int kc = 0; kc < 2; kc++) {
                        mma_bf16(s, qah[mt][kc], kbh[kc][nt], kbh[kc][nt+2]);
                        mma_bf16(s, qal[mt][kc], kbh[kc][nt], kbh[kc][nt+2]);
                    }
                    int cbase = ntp*16 + nt*8 + (lane & 3)*2;
                    float k2c0 = k2s[cbase], k2c1 = k2s[cbase + 1];
                    #pragma unroll
                    for (int rh = 0; rh < 2; rh++) {
                        float w0 = __expf(s[rh*2+0] + q2r[mt][rh] + k2c0);
                        float w1 = __expf(s[rh*2+1] + q2r[mt][rh] + k2c1);
                        ull t = add2(pack2(w0, w1), NH);
                        ull p = fma2(C4, t, C3);
                        p = fma2(p, t, C2);
                        p = fma2(p, t, C1);
                        p = fma2(p, t, C0);
                        float2 pf = unpack2(p);
                        dpart[mt][rh] += pf.x + pf.y;
                        __nv_bfloat162 hp = __float22bfloat162_rn(pf);
                        pa[ntp][nt*2 + rh] = *(uint32_t*)&hp;
                    }
                }
            }
            // ---- phase 2: out += P @ Vh (P straight from registers)
            #pragma unroll
            for (int kc = 0; kc < 4; kc++) {
                uint32_t vbh[2][4];
                #pragma unroll
                for (int ntp = 0; ntp < 2; ntp++)
                    ldsm_x4t(vbh[ntp], kf + AT_VH + (kc*16 + ar) * 80 + (ntp*16 + ag) * 2);
                #pragma unroll
                for (int ntp = 0; ntp < 2; ntp++)
                    #pragma unroll
                    for (int nt = 0; nt < 2; nt++)
                        mma_bf16(oacc[mt][ntp*2 + nt], pa[kc],
                                 vbh[ntp][2*nt], vbh[ntp][2*nt+1]);
            }
        }
        __syncthreads();
    }

    // ---- epilogue: normalize + store bf16 hi/lo
    #pragma unroll
    for (int mt = 0; mt < 2; mt++)
        #pragma unroll
        for (int rh = 0; rh < 2; rh++) {
            float den = dpart[mt][rh];
            den += __shfl_xor_sync(0xffffffffu, den, 1);
            den += __shfl_xor_sync(0xffffffffu, den, 2);
            float inv = 1.f / den;
            int row = q0 + wid*32 + mt*16 + rh*8 + (lane >> 2);
            size_t obase = (size_t)(b*SEQ + row)*D_MODEL + h*DEPTH + (lane & 3)*2;
            #pragma unroll
            for (int nt4 = 0; nt4 < 4; nt4++) {
                float ox = oacc[mt][nt4][rh*2+0] * inv;
                float oy = oacc[mt][nt4][rh*2+1] * inv;
                __nv_bfloat16 h0 = __float2bfloat16(ox), h1 = __float2bfloat16(oy);
                uint32_t hw = pkbf(h0, h1);
                uint32_t lw = pkbf(__float2bfloat16(ox - __bfloat162float(h0)),
                                   __float2bfloat16(oy - __bfloat162float(h1)));
                *(uint32_t*)(Oh + obase + nt4*8) = hw;
                *(uint32_t*)(Ol + obase + nt4*8) = lw;
            }
        }
}

// ---------------- fused residual + LayerNorm (warp per row) -----------------
__global__ __launch_bounds__(256) void residual_ln(
    const float* __restrict__ X, const float* __restrict__ Y,
    const float* __restrict__ g, const float* __restrict__ b,
    float* __restrict__ outf,
    __nv_bfloat16* __restrict__ outh, __nv_bfloat16* __restrict__ outl,
    int do_split)
{
    int lane = threadIdx.x & 31, w = threadIdx.x >> 5;
    int row  = blockIdx.x * 8 + w;
    size_t base = (size_t)row * D_MODEL;
    int c0 = lane * 4, c1 = 128 + lane * 4;

    float4 x0 = *(const float4*)(X + base + c0);
    float4 x1 = *(const float4*)(X + base + c1);
    float4 y0 = *(const float4*)(Y + base + c0);
    float4 y1 = *(const float4*)(Y + base + c1);
    float4 v0 = make_float4(x0.x+y0.x, x0.y+y0.y, x0.z+y0.z, x0.w+y0.w);
    float4 v1 = make_float4(x1.x+y1.x, x1.y+y1.y, x1.z+y1.z, x1.w+y1.w);

    float s = v0.x+v0.y+v0.z+v0.w + v1.x+v1.y+v1.z+v1.w;
    #pragma unroll
    for (int o = 16; o > 0; o >>= 1) s += __shfl_xor_sync(0xffffffffu, s, o);
    float mean = s * (1.f / D_MODEL);

    float4 d0 = make_float4(v0.x-mean, v0.y-mean, v0.z-mean, v0.w-mean);
    float4 d1 = make_float4(v1.x-mean, v1.y-mean, v1.z-mean, v1.w-mean);
    float s2 = d0.x*d0.x+d0.y*d0.y+d0.z*d0.z+d0.w*d0.w
             + d1.x*d1.x+d1.y*d1.y+d1.z*d1.z+d1.w*d1.w;
    #pragma unroll
    for (int o = 16; o > 0; o >>= 1) s2 += __shfl_xor_sync(0xffffffffu, s2, o);
    float rstd = rsqrtf(s2 * (1.f / D_MODEL) + EPS);

    float4 g0 = *(const float4*)(g + c0), g1 = *(const float4*)(g + c1);
    float4 b0 = *(const float4*)(b + c0), b1 = *(const float4*)(b + c1);
    float4 o0, o1;
    o0.x = d0.x*rstd*g0.x + b0.x; o0.y = d0.y*rstd*g0.y + b0.y;
    o0.z = d0.z*rstd*g0.z + b0.z; o0.w = d0.w*rstd*g0.w + b0.w;
    o1.x = d1.x*rstd*g1.x + b1.x; o1.y = d1.y*rstd*g1.y + b1.y;
    o1.z = d1.z*rstd*g1.z + b1.z; o1.w = d1.w*rstd*g1.w + b1.w;
    *(float4*)(outf + base + c0) = o0;
    *(float4*)(outf + base + c1) = o1;

    if (do_split) {
        __nv_bfloat16 h0 = __float2bfloat16(o0.x), h1 = __float2bfloat16(o0.y);
        __nv_bfloat16 h2 = __float2bfloat16(o0.z), h3 = __float2bfloat16(o0.w);
        __nv_bfloat16 h4 = __float2bfloat16(o1.x), h5 = __float2bfloat16(o1.y);
        __nv_bfloat16 h6 = __float2bfloat16(o1.z), h7 = __float2bfloat16(o1.w);
        *(uint2*)(outh + base + c0) = make_uint2(pkbf(h0,h1), pkbf(h2,h3));
        *(uint2*)(outh + base + c1) = make_uint2(pkbf(h4,h5), pkbf(h6,h7));
        *(uint2*)(outl + base + c0) = make_uint2(
            pkbf(__float2bfloat16(o0.x-__bfloat162float(h0)),
                 __float2bfloat16(o0.y-__bfloat162float(h1))),
            pkbf(__float2bfloat16(o0.z-__bfloat162float(h2)),
                 __float2bfloat16(o0.w-__bfloat162float(h3))));
        *(uint2*)(outl + base + c1) = make_uint2(
            pkbf(__float2bfloat16(o1.x-__bfloat162float(h4)),
                 __float2bfloat16(o1.y-__bfloat162float(h5))),
            pkbf(__float2bfloat16(o1.z-__bfloat162float(h6)),
                 __float2bfloat16(o1.w-__bfloat162float(h7))));
    }
}

// ---------------- launch -----------------------------------------------------
extern "C" void kernel_launch(void* const* d_in, const int* in_sizes, int n_in,
                              void* d_out, int out_size)
{
    const float* x      = (const float*)d_in[0];
    const float* wq_w   = (const float*)d_in[1];
    const float* wq_b   = (const float*)d_in[2];
    const float* wk_w   = (const float*)d_in[3];
    const float* wk_b   = (const float*)d_in[4];
    const float* wv_w   = (const float*)d_in[5];
    const float* wv_b   = (const float*)d_in[6];
    const float* wo_w   = (const float*)d_in[7];
    const float* wo_b   = (const float*)d_in[8];
    const float* ffn1_w = (const float*)d_in[9];
    const float* ffn1_b = (const float*)d_in[10];
    const float* ffn2_w = (const float*)d_in[11];
    const float* ffn2_b = (const float*)d_in[12];
    const float* ln1_g  = (const float*)d_in[13];
    const float* ln1_b  = (const float*)d_in[14];
    const float* ln2_g  = (const float*)d_in[15];
    const float* ln2_b  = (const float*)d_in[16];

    float *tmp, *out1, *qn, *kn, *vn;
    cudaGetSymbolAddress((void**)&tmp,  g_tmp);
    cudaGetSymbolAddress((void**)&out1, g_out1);
    cudaGetSymbolAddress((void**)&qn,   g_qn);
    cudaGetSymbolAddress((void**)&kn,   g_kn);
    cudaGetSymbolAddress((void**)&vn,   g_vn);

    __nv_bfloat16 *qbh, *qbl, *kbh, *kbl, *vbh, *vbl;
    cudaGetSymbolAddress((void**)&qbh, g_qbh); cudaGetSymbolAddress((void**)&qbl, g_qbl);
    cudaGetSymbolAddress((void**)&kbh, g_kbh); cudaGetSymbolAddress((void**)&kbl, g_kbl);
    cudaGetSymbolAddress((void**)&vbh, g_vbh); cudaGetSymbolAddress((void**)&vbl, g_vbl);

    __nv_bfloat16 *xh, *xl, *atth, *attl, *o1h, *o1l, *ffhh, *ffhl;
    cudaGetSymbolAddress((void**)&xh,   g_xh);   cudaGetSymbolAddress((void**)&xl,   g_xl);
    cudaGetSymbolAddress((void**)&atth, g_atth); cudaGetSymbolAddress((void**)&attl, g_attl);
    cudaGetSymbolAddress((void**)&o1h,  g_o1h);  cudaGetSymbolAddress((void**)&o1l,  g_o1l);
    cudaGetSymbolAddress((void**)&ffhh, g_ffhh); cudaGetSymbolAddress((void**)&ffhl, g_ffhl);

    __nv_bfloat16 *wqh, *wql, *wkh, *wkl, *wvh, *wvl, *woh, *wol, *f1h, *f1l, *f2h, *f2l;
    cudaGetSymbolAddress((void**)&wqh, g_wqh); cudaGetSymbolAddress((void**)&wql, g_wql);
    cudaGetSymbolAddress((void**)&wkh, g_wkh); cudaGetSymbolAddress((void**)&wkl, g_wkl);
    cudaGetSymbolAddress((void**)&wvh, g_wvh); cudaGetSymbolAddress((void**)&wvl, g_wvl);
    cudaGetSymbolAddress((void**)&woh, g_woh); cudaGetSymbolAddress((void**)&wol, g_wol);
    cudaGetSymbolAddress((void**)&f1h, g_f1h); cudaGetSymbolAddress((void**)&f1l, g_f1l);
    cudaGetSymbolAddress((void**)&f2h, g_f2h); cudaGetSymbolAddress((void**)&f2l, g_f2l);

    cudaFuncSetAttribute(attn_mma, cudaFuncAttributeMaxDynamicSharedMemorySize, AT_TOT);
    cudaFuncSetAttribute(gemm_bf3, cudaFuncAttributeMaxDynamicSharedMemorySize, G_TOT);

    // one combined split launch: 6 weights + x (4 float4 per thread)
    SplitJobs J;
    const float* srcs[7] = {wq_w, wk_w, wv_w, wo_w, ffn1_w, ffn2_w, x};
    __nv_bfloat16* hs[7] = {wqh, wkh, wvh, woh, f1h, f2h, xh};
    __nv_bfloat16* ls[7] = {wql, wkl, wvl, wol, f1l, f2l, xl};
    long long sizes4[7] = {65536/4, 65536/4, 65536/4, 65536/4,
                           262144/4, 262144/4, (long long)TOK*D_MODEL/4};
    long long acc = 0;
    for (int i = 0; i < 7; i++) { J.src[i] = srcs[i]; J.h[i] = hs[i]; J.l[i] = ls[i];
                                  J.start[i] = acc; acc += sizes4[i]; }
    J.start[7] = acc;
    split_all<<<(unsigned)((acc + 1023) / 1024), 256>>>(J);

    // QKV projections: bf16 hi/lo out + head norms (mode 2)
    {
        GemmPtrs P = {};
        P.bh[0] = wqh; P.bl[0] = wql; P.bias[0] = wq_b;
        P.bh[1] = wkh; P.bl[1] = wkl; P.bias[1] = wk_b;
        P.bh[2] = wvh; P.bl[2] = wvl; P.bias[2] = wv_b;
        P.ch[0] = qbh; P.cl[0] = qbl; P.nrm[0] = qn;
        P.ch[1] = kbh; P.cl[1] = kbl; P.nrm[1] = kn;
        P.ch[2] = vbh; P.cl[2] = vbl; P.nrm[2] = vn;
        gemm_bf3<<<dim3(2, 128, 3), 256, G_TOT>>>(xh, xl, P, D_MODEL, D_MODEL, 0, 2);
    }

    // tensor-core RBF attention
    attn_mma<<<dim3(SEQ / 128, BATCH * HEADS), 128, AT_TOT>>>(
        qbh, qbl, kbh, vbh, qn, kn, atth, attl);

    // output projection (fp32) + residual LN1
    {
        GemmPtrs P = {};
        P.bh[0] = woh; P.bl[0] = wol; P.bias[0] = wo_b; P.cf[0] = tmp;
        gemm_bf3<<<dim3(2, 128, 1), 256, G_TOT>>>(atth, attl, P, D_MODEL, D_MODEL, 0, 0);
    }
    residual_ln<<<TOK / 8, 256>>>(x, tmp, ln1_g, ln1_b, out1, o1h, o1l, 1);

    // FFN1 (relu, bf16 out) -> FFN2 (fp32) -> residual LN2
    {
        GemmPtrs P = {};
        P.bh[0] = f1h; P.bl[0] = f1l; P.bias[0] = ffn1_b;
        P.ch[0] = ffhh; P.cl[0] = ffhl;
        gemm_bf3<<<dim3(8, 128, 1), 256, G_TOT>>>(o1h, o1l, P, D_MODEL, DFF, 1, 1);
    }
    {
        GemmPtrs P = {};
        P.bh[0] = f2h; P.bl[0] = f2l; P.bias[0] = ffn2_b; P.cf[0] = tmp;
        gemm_bf3<<<dim3(2, 128, 1), 256, G_TOT>>>(ffhh, ffhl, P, DFF, D_MODEL, 0, 0);
    }
    residual_ln<<<TOK / 8, 256>>>(out1, tmp, ln2_g, ln2_b, (float*)d_out,
                                  (__nv_bfloat16*)0, (__nv_bfloat16*)0, 0);
}